// round 5
// baseline (speedup 1.0000x reference)
#include <cuda_runtime.h>
#include <cuda_bf16.h>
#include <cstdint>
#include <stdint.h>
#include <math.h>

#define Nn 16
#define Cc 512
#define C4 128
#define QKC 16
#define LLEN 1024
#define EPSf 1e-5f
#define CONVK 2304          // 256 ci * 9 taps

// ---------------- scratch (device globals; no allocation allowed) ----------------
__device__ float g_value[Nn * C4 * LLEN];                 // proj_value
__device__ float g_qk[2 * 2 * Nn * QKC * LLEN];           // [q/k][pyr][b][qc][l]
__device__ float g_attn[2 * Nn * LLEN * LLEN];            // [pyr][b][m][l] probabilities
__device__ float g_cat[Nn * 2 * C4 * LLEN];               // sz2/sz4 pyramid outputs
__device__ float g_y[Nn * Cc * LLEN];                     // conv output pre-BN
__device__ float g_stats[Cc * 2];
__device__ float g_mean[Nn * C4];
__device__ float g_wsum[9 * Cc * C4];
__device__ float g_contrib[Nn * 9 * Cc];
__device__ __nv_bfloat16 g_wh[Cc * CONVK];                // weight hi  [co][k]
__device__ __nv_bfloat16 g_wl[Cc * CONVK];                // weight lo
__device__ __nv_bfloat16 g_imh[(size_t)Nn * LLEN * CONVK]; // im2col hi [b][pix][k]
__device__ __nv_bfloat16 g_iml[(size_t)Nn * LLEN * CONVK]; // im2col lo

__device__ __forceinline__ int qk_idx(int g, int py, int b, int qc, int l) {
    return (((g * 2 + py) * Nn + b) * QKC + qc) * LLEN + l;
}

// ---------------- PTX helpers (legacy tensor path, sm_80+) ----------------
__device__ __forceinline__ uint32_t smem_u32(const void* p) {
    uint32_t a;
    asm("{ .reg .u64 t; cvta.to.shared.u64 t, %1; cvt.u32.u64 %0, t; }" : "=r"(a) : "l"(p));
    return a;
}
__device__ __forceinline__ void ldsm_x4(uint32_t& r0, uint32_t& r1, uint32_t& r2, uint32_t& r3,
                                        uint32_t addr) {
    asm volatile("ldmatrix.sync.aligned.m8n8.x4.shared.b16 {%0,%1,%2,%3}, [%4];"
                 : "=r"(r0), "=r"(r1), "=r"(r2), "=r"(r3) : "r"(addr));
}
__device__ __forceinline__ void ldsm_x2(uint32_t& r0, uint32_t& r1, uint32_t addr) {
    asm volatile("ldmatrix.sync.aligned.m8n8.x2.shared.b16 {%0,%1}, [%2];"
                 : "=r"(r0), "=r"(r1) : "r"(addr));
}
__device__ __forceinline__ void mma_bf16(float* c, const uint32_t* a, const uint32_t* b) {
    asm volatile(
        "mma.sync.aligned.m16n8k16.row.col.f32.bf16.bf16.f32 "
        "{%0,%1,%2,%3}, {%4,%5,%6,%7}, {%8,%9}, {%0,%1,%2,%3};"
        : "+f"(c[0]), "+f"(c[1]), "+f"(c[2]), "+f"(c[3])
        : "r"(a[0]), "r"(a[1]), "r"(a[2]), "r"(a[3]), "r"(b[0]), "r"(b[1]));
}
__device__ __forceinline__ uint32_t swz(uint32_t boff) {
    return boff ^ ((boff >> 3) & 0x70);
}

// ---------------- K1: value projection GEMM ----
__global__ void k_value_proj(const float* __restrict__ x,
                             const float* __restrict__ w,
                             const float* __restrict__ bias) {
    __shared__ float As[32 * 68];
    __shared__ float Bs[32 * 68];
    const int b  = blockIdx.z;
    const int m0 = blockIdx.y * 64;
    const int n0 = blockIdx.x * 64;
    const float* xb = x + b * Cc * LLEN;
    const int t  = threadIdx.x;
    const int ty = t >> 4, tx = t & 15;
    const int am = t >> 2, akq = (t & 3) * 8;
    const int bk = t >> 3, bnq = (t & 7) * 8;
    float acc[4][4] = {};

    for (int kc = 0; kc < Cc / 32; kc++) {
        const int k0 = kc * 32;
        __syncthreads();
        float4 a0 = *(const float4*)&w[(m0 + am) * Cc + k0 + akq];
        float4 a1 = *(const float4*)&w[(m0 + am) * Cc + k0 + akq + 4];
        As[(akq + 0) * 68 + am] = a0.x; As[(akq + 1) * 68 + am] = a0.y;
        As[(akq + 2) * 68 + am] = a0.z; As[(akq + 3) * 68 + am] = a0.w;
        As[(akq + 4) * 68 + am] = a1.x; As[(akq + 5) * 68 + am] = a1.y;
        As[(akq + 6) * 68 + am] = a1.z; As[(akq + 7) * 68 + am] = a1.w;
        float4 b0 = *(const float4*)&xb[(k0 + bk) * LLEN + n0 + bnq];
        float4 b1 = *(const float4*)&xb[(k0 + bk) * LLEN + n0 + bnq + 4];
        *(float4*)&Bs[bk * 68 + bnq]     = b0;
        *(float4*)&Bs[bk * 68 + bnq + 4] = b1;
        __syncthreads();
#pragma unroll
        for (int k = 0; k < 32; k++) {
            float4 av = *(const float4*)&As[k * 68 + ty * 4];
            float4 bv = *(const float4*)&Bs[k * 68 + tx * 4];
            acc[0][0] += av.x * bv.x; acc[0][1] += av.x * bv.y; acc[0][2] += av.x * bv.z; acc[0][3] += av.x * bv.w;
            acc[1][0] += av.y * bv.x; acc[1][1] += av.y * bv.y; acc[1][2] += av.y * bv.z; acc[1][3] += av.y * bv.w;
            acc[2][0] += av.z * bv.x; acc[2][1] += av.z * bv.y; acc[2][2] += av.z * bv.z; acc[2][3] += av.z * bv.w;
            acc[3][0] += av.w * bv.x; acc[3][1] += av.w * bv.y; acc[3][2] += av.w * bv.z; acc[3][3] += av.w * bv.w;
        }
    }
#pragma unroll
    for (int i = 0; i < 4; i++) {
        const int c = m0 + ty * 4 + i;
        const float bs = bias[c];
        float4 o;
        o.x = acc[i][0] + bs; o.y = acc[i][1] + bs; o.z = acc[i][2] + bs; o.w = acc[i][3] + bs;
        *(float4*)&g_value[(b * C4 + c) * LLEN + n0 + tx * 4] = o;
    }
}

// ---------------- K2: pooling + rce + q/k feats + bilinear upsample -------------
__global__ void k_prep(const float* __restrict__ x,
                       const float* __restrict__ rce_w, const float* __restrict__ rce_b,
                       const float* __restrict__ qw, const float* __restrict__ qb,
                       const float* __restrict__ kw, const float* __restrict__ kb) {
    __shared__ float sp4[Cc * 16];
    __shared__ float f4[C4 * 16];
    __shared__ float f2[C4 * 4];
    __shared__ float qf4[QKC * 16], kf4[QKC * 16];
    __shared__ float qf2[QKC * 4],  kf2[QKC * 4];
    const int b = blockIdx.x, t = threadIdx.x;
    const float* xb = x + b * Cc * LLEN;

    for (int idx = t; idx < Cc * 16; idx += 256) {
        int c = idx >> 4, cell = idx & 15, i = cell >> 2, j = cell & 3;
        float s = 0.f;
        for (int y = 0; y < 8; y++)
#pragma unroll
            for (int xx = 0; xx < 8; xx++)
                s += xb[c * LLEN + (i * 8 + y) * 32 + j * 8 + xx];
        sp4[idx] = s * (1.f / 64.f);
    }
    __syncthreads();

    if (t < C4) {
        float a4[16] = {}, a2[4] = {};
        for (int c = 0; c < Cc; c++) {
            const float w4 = rce_w[(2 * C4 + t) * Cc + c];
            const float w2 = rce_w[(1 * C4 + t) * Cc + c];
            const float* p = &sp4[c * 16];
#pragma unroll
            for (int cell = 0; cell < 16; cell++) a4[cell] += w4 * p[cell];
#pragma unroll
            for (int i = 0; i < 2; i++)
#pragma unroll
                for (int j = 0; j < 2; j++)
                    a2[i * 2 + j] += w2 * 0.25f *
                        (p[(2 * i) * 4 + 2 * j] + p[(2 * i) * 4 + 2 * j + 1] +
                         p[(2 * i + 1) * 4 + 2 * j] + p[(2 * i + 1) * 4 + 2 * j + 1]);
        }
        const float b4 = rce_b[2 * C4 + t], b2v = rce_b[1 * C4 + t];
#pragma unroll
        for (int cell = 0; cell < 16; cell++) f4[t * 16 + cell] = a4[cell] + b4;
#pragma unroll
        for (int cc = 0; cc < 4; cc++) f2[t * 4 + cc] = a2[cc] + b2v;
    }
    __syncthreads();

    {
        const int qc = t >> 4, cell = t & 15;
        float aq = 0.f, ak = 0.f;
        for (int o = 0; o < C4; o++) {
            const float fv = f4[o * 16 + cell];
            aq += qw[qc * C4 + o] * fv;
            ak += kw[qc * C4 + o] * fv;
        }
        qf4[t] = aq + qb[qc]; kf4[t] = ak + kb[qc];
    }
    if (t < 64) {
        const int qc = t >> 2, cc = t & 3;
        float aq = 0.f, ak = 0.f;
        for (int o = 0; o < C4; o++) {
            const float fv = f2[o * 4 + cc];
            aq += qw[qc * C4 + o] * fv;
            ak += kw[qc * C4 + o] * fv;
        }
        qf2[t] = aq + qb[qc]; kf2[t] = ak + kb[qc];
    }
    __syncthreads();

    const float st4 = 3.0f / 31.0f, st2 = 1.0f / 31.0f;
    for (int idx = t; idx < QKC * LLEN; idx += 256) {
        const int qc = idx >> 10, p = idx & 1023, r = p >> 5, cc = p & 31;
        float pr = r * st4;  int lr = (int)pr; lr = lr > 2 ? 2 : lr; float fr = pr - lr;
        float pc = cc * st4; int lc = (int)pc; lc = lc > 2 ? 2 : lc; float fc = pc - lc;
        const float w00 = (1.f - fr) * (1.f - fc), w01 = (1.f - fr) * fc;
        const float w10 = fr * (1.f - fc),         w11 = fr * fc;
        const float* q4 = &qf4[qc * 16]; const float* k4 = &kf4[qc * 16];
        g_qk[qk_idx(0, 1, b, qc, p)] =
            w00 * q4[lr * 4 + lc] + w01 * q4[lr * 4 + lc + 1] +
            w10 * q4[(lr + 1) * 4 + lc] + w11 * q4[(lr + 1) * 4 + lc + 1];
        g_qk[qk_idx(1, 1, b, qc, p)] =
            w00 * k4[lr * 4 + lc] + w01 * k4[lr * 4 + lc + 1] +
            w10 * k4[(lr + 1) * 4 + lc] + w11 * k4[(lr + 1) * 4 + lc + 1];
        const float fr2 = r * st2, fc2 = cc * st2;
        const float u00 = (1.f - fr2) * (1.f - fc2), u01 = (1.f - fr2) * fc2;
        const float u10 = fr2 * (1.f - fc2),          u11 = fr2 * fc2;
        const float* q2 = &qf2[qc * 4]; const float* k2 = &kf2[qc * 4];
        g_qk[qk_idx(0, 0, b, qc, p)] = u00 * q2[0] + u01 * q2[1] + u10 * q2[2] + u11 * q2[3];
        g_qk[qk_idx(1, 0, b, qc, p)] = u00 * k2[0] + u01 * k2[1] + u10 * k2[2] + u11 * k2[3];
    }
}

// ---------------- K3: sz=1 pyramid mean ----------------------------
__global__ void k_mean() {
    const int c = blockIdx.x, b = blockIdx.y, t = threadIdx.x;
    const float* v = &g_value[(b * C4 + c) * LLEN];
    float s = 0.f;
    for (int i = t; i < LLEN; i += 256) s += v[i];
    __shared__ float red[256];
    red[t] = s; __syncthreads();
    for (int o = 128; o > 0; o >>= 1) { if (t < o) red[t] += red[t + o]; __syncthreads(); }
    if (t == 0) g_mean[b * C4 + c] = red[0] * (1.f / LLEN);
}

// ---------------- K3b: border-pattern weight sums ----------------
__global__ void k_wsum(const float* __restrict__ fw) {
    const int co = blockIdx.x, ci = threadIdx.x;
    float w[9];
#pragma unroll
    for (int k = 0; k < 9; k++) w[k] = fw[co * 3456 + ci * 9 + k];
#pragma unroll
    for (int rt = 0; rt < 3; rt++) {
        const int kylo = (rt == 0) ? 1 : 0, kyhi = (rt == 2) ? 1 : 2;
#pragma unroll
        for (int ct = 0; ct < 3; ct++) {
            const int kxlo = (ct == 0) ? 1 : 0, kxhi = (ct == 2) ? 1 : 2;
            float s = 0.f;
            for (int ky = kylo; ky <= kyhi; ky++)
                for (int kx = kxlo; kx <= kxhi; kx++)
                    s += w[ky * 3 + kx];
            g_wsum[((rt * 3 + ct) * Cc + co) * C4 + ci] = s;
        }
    }
}

// ---------------- K3c: constant-channel conv contribution ----------------
__global__ void k_const() {
    __shared__ float sm[C4];
    const int b = blockIdx.x, co = threadIdx.x;
    if (co < C4) sm[co] = g_mean[b * C4 + co];
    __syncthreads();
#pragma unroll
    for (int pat = 0; pat < 9; pat++) {
        const float* ws = &g_wsum[(pat * Cc + co) * C4];
        float s = 0.f;
        for (int ci = 0; ci < C4; ci++) s += sm[ci] * ws[ci];
        g_contrib[(b * 9 + pat) * Cc + co] = s;
    }
}

// ---------------- K3d: weight hi/lo bf16 split [co][k] -------------------
__global__ void k_wsplit(const float* __restrict__ fw) {
    const int idx = blockIdx.x * 256 + threadIdx.x;   // 512*2304
    const int co = idx / CONVK, k = idx % CONVK;
    const float v = fw[co * 3456 + 1152 + k];
    const __nv_bfloat16 h = __float2bfloat16(v);
    g_wh[idx] = h;
    g_wl[idx] = __float2bfloat16(v - __bfloat162float(h));
}

// ---------------- K4: energy + softmax -> attn probabilities ----------------
__global__ void __launch_bounds__(256) k_attn() {
    extern __shared__ float ks[];
    const int b = blockIdx.z, pyr = blockIdx.y;
    const int mbase = blockIdx.x * 128;
    const int t = threadIdx.x, w = t >> 5, lane = t & 31;
    const float* gq = &g_qk[qk_idx(0, pyr, b, 0, 0)];
    const float* gk = &g_qk[qk_idx(1, pyr, b, 0, 0)];
    for (int idx = t; idx < QKC * LLEN; idx += 256) {
        const int qc = idx >> 10, l = idx & 1023;
        ks[l * 20 + qc] = gk[qc * LLEN + l];
    }
    __syncthreads();
    float* pb = &g_attn[(size_t)(pyr * Nn + b) * LLEN * LLEN];

    for (int pr = 0; pr < 16; pr++) {
        const int m = mbase + pr * 8 + w;
        float q[16];
#pragma unroll
        for (int j = 0; j < 16; j++) q[j] = gq[j * LLEN + m];
        float e[32];
        float mx = -1e30f;
#pragma unroll
        for (int i = 0; i < 32; i++) {
            const int l = i * 32 + lane;
            const float4* kp = (const float4*)&ks[l * 20];
            const float4 k0 = kp[0], k1 = kp[1], k2 = kp[2], k3 = kp[3];
            float s = q[0]*k0.x + q[1]*k0.y + q[2]*k0.z + q[3]*k0.w
                    + q[4]*k1.x + q[5]*k1.y + q[6]*k1.z + q[7]*k1.w
                    + q[8]*k2.x + q[9]*k2.y + q[10]*k2.z + q[11]*k2.w
                    + q[12]*k3.x + q[13]*k3.y + q[14]*k3.z + q[15]*k3.w;
            e[i] = s;
            mx = fmaxf(mx, s);
        }
#pragma unroll
        for (int o = 16; o > 0; o >>= 1)
            mx = fmaxf(mx, __shfl_xor_sync(0xffffffffu, mx, o));
        float sm = 0.f;
#pragma unroll
        for (int i = 0; i < 32; i++) { e[i] = __expf(e[i] - mx); sm += e[i]; }
#pragma unroll
        for (int o = 16; o > 0; o >>= 1)
            sm += __shfl_xor_sync(0xffffffffu, sm, o);
        const float inv = 1.f / sm;
        float* pa = &pb[(size_t)m * LLEN];
#pragma unroll
        for (int i = 0; i < 32; i++)
            pa[i * 32 + lane] = e[i] * inv;
    }
}

// ---------------- K5: out[c][m] = sum_l V[c][l] * P[m][l] -------------------
__global__ void k_outgemm() {
    __shared__ float As[32 * 68];
    __shared__ float Bs[32 * 68];
    const int z = blockIdx.z; const int b = z >> 1; const int pyr = z & 1;
    const int c0 = blockIdx.y * 64;
    const int m0 = blockIdx.x * 64;
    const float* V = g_value + b * C4 * LLEN;
    const float* P = g_attn + (size_t)(pyr * Nn + b) * LLEN * LLEN;
    const int t = threadIdx.x, ty = t >> 4, tx = t & 15;
    const int r = t >> 2, kq = (t & 3) * 8;
    float acc[4][4] = {};

    for (int kc = 0; kc < LLEN / 32; kc++) {
        const int l0 = kc * 32;
        __syncthreads();
        float4 a0 = *(const float4*)&V[(c0 + r) * LLEN + l0 + kq];
        float4 a1 = *(const float4*)&V[(c0 + r) * LLEN + l0 + kq + 4];
        As[(kq + 0) * 68 + r] = a0.x; As[(kq + 1) * 68 + r] = a0.y;
        As[(kq + 2) * 68 + r] = a0.z; As[(kq + 3) * 68 + r] = a0.w;
        As[(kq + 4) * 68 + r] = a1.x; As[(kq + 5) * 68 + r] = a1.y;
        As[(kq + 6) * 68 + r] = a1.z; As[(kq + 7) * 68 + r] = a1.w;
        float4 b0 = *(const float4*)&P[(size_t)(m0 + r) * LLEN + l0 + kq];
        float4 b1 = *(const float4*)&P[(size_t)(m0 + r) * LLEN + l0 + kq + 4];
        Bs[(kq + 0) * 68 + r] = b0.x; Bs[(kq + 1) * 68 + r] = b0.y;
        Bs[(kq + 2) * 68 + r] = b0.z; Bs[(kq + 3) * 68 + r] = b0.w;
        Bs[(kq + 4) * 68 + r] = b1.x; Bs[(kq + 5) * 68 + r] = b1.y;
        Bs[(kq + 6) * 68 + r] = b1.z; Bs[(kq + 7) * 68 + r] = b1.w;
        __syncthreads();
#pragma unroll
        for (int k = 0; k < 32; k++) {
            float4 av = *(const float4*)&As[k * 68 + ty * 4];
            float4 bv = *(const float4*)&Bs[k * 68 + tx * 4];
            acc[0][0] += av.x * bv.x; acc[0][1] += av.x * bv.y; acc[0][2] += av.x * bv.z; acc[0][3] += av.x * bv.w;
            acc[1][0] += av.y * bv.x; acc[1][1] += av.y * bv.y; acc[1][2] += av.y * bv.z; acc[1][3] += av.y * bv.w;
            acc[2][0] += av.z * bv.x; acc[2][1] += av.z * bv.y; acc[2][2] += av.z * bv.z; acc[2][3] += av.z * bv.w;
            acc[3][0] += av.w * bv.x; acc[3][1] += av.w * bv.y; acc[3][2] += av.w * bv.z; acc[3][3] += av.w * bv.w;
        }
    }
#pragma unroll
    for (int i = 0; i < 4; i++) {
        const int ch = pyr * C4 + c0 + ty * 4 + i;
        float4 o;
        o.x = acc[i][0]; o.y = acc[i][1]; o.z = acc[i][2]; o.w = acc[i][3];
        *(float4*)&g_cat[(b * 2 * C4 + ch) * LLEN + m0 + tx * 4] = o;
    }
}

// ---------------- K5b: im2col hi/lo bf16: [b][pix][k=ci*9+ky*3+kx] ------------
__global__ void k_im2col() {
    const int idx = blockIdx.x * 256 + threadIdx.x;   // 16*1024*2304
    const int k = idx % CONVK;
    const int rest = idx / CONVK;
    const int pix = rest & 1023, b = rest >> 10;
    const int ci = k / 9, r = k - ci * 9;
    const int ky = r / 3, kx = r - ky * 3;
    const int py = (pix >> 5) + ky - 1, px = (pix & 31) + kx - 1;
    float v = 0.f;
    if (py >= 0 && py < 32 && px >= 0 && px < 32)
        v = g_cat[((b * 2 * C4) + ci) * LLEN + py * 32 + px];
    const __nv_bfloat16 h = __float2bfloat16(v);
    g_imh[(size_t)idx] = h;
    g_iml[(size_t)idx] = __float2bfloat16(v - __bfloat162float(h));
}

// ---------------- K6: fusion conv as HMMA bf16 GEMM (hi/lo split) --------------
// D[co 128][pix 128] = sum_k W[co,k]*Im[pix,k], K = 2304
// 8 warps: warp_m in {0,1} (64 rows), warp_n in {0..3} (32 cols)
// per warp: 4 m16-tiles x 4 n8-tiles, mma.m16n8k16, 3 hi/lo combos
__global__ void __launch_bounds__(256) k_conv_mma() {
    extern __shared__ char dsm[];
    const uint32_t sbase = smem_u32(dsm);
    const uint32_t offAh = 0, offAl = 16384, offBh = 32768, offBl = 49152;

    const int b = blockIdx.z;
    const int co0 = blockIdx.y * 128;
    const int pix0 = blockIdx.x * 128;
    const int t = threadIdx.x;
    const int wid = t >> 5, lane = t & 31;
    const int wm = wid >> 2, wn = wid & 3;

    const __nv_bfloat16* __restrict__ wh = g_wh;
    const __nv_bfloat16* __restrict__ wl = g_wl;
    const __nv_bfloat16* __restrict__ ih = g_imh + ((size_t)b * LLEN + pix0) * CONVK;
    const __nv_bfloat16* __restrict__ il = g_iml + ((size_t)b * LLEN + pix0) * CONVK;

    float acc[4][4][4] = {};   // [mt][nt][frag]

    // ldmatrix lane addressing (within 128x64 bf16 tile, 128B rows, swizzled)
    // A x4: row = wm*64 + mt*16 + (lane&15), col16B = kk*32 + ((lane&16)?16:0)
    // B x2: row = wn*32 + nt*8 + (lane&7),  col16B = kk*32 + ((lane&8)?16:0)
    const int aRow = wm * 64 + (lane & 15);
    const int aColHalf = (lane & 16) ? 16 : 0;
    const int bRow = wn * 32 + (lane & 7);
    const int bColHalf = (lane & 8) ? 16 : 0;

    for (int s = 0; s < 36; s++) {
        const int k0 = s * 64;
        __syncthreads();
        // load 4 tiles of [128 rows][64 bf16] (128 B/row), swizzled
        for (int idx = t; idx < 1024; idx += 256) {
            const int r = idx >> 3, ch = idx & 7;
            const uint32_t sw = swz((uint32_t)(r * 128 + ch * 16));
            const int goff = ch * 8;
            uint4 v;
            v = *(const uint4*)(wh + (size_t)(co0 + r) * CONVK + k0 + goff);
            *(uint4*)(dsm + offAh + sw) = v;
            v = *(const uint4*)(wl + (size_t)(co0 + r) * CONVK + k0 + goff);
            *(uint4*)(dsm + offAl + sw) = v;
            v = *(const uint4*)(ih + (size_t)r * CONVK + k0 + goff);
            *(uint4*)(dsm + offBh + sw) = v;
            v = *(const uint4*)(il + (size_t)r * CONVK + k0 + goff);
            *(uint4*)(dsm + offBl + sw) = v;
        }
        __syncthreads();

#pragma unroll
        for (int kk = 0; kk < 4; kk++) {
            uint32_t Ah[4][4], Al[4][4], Bh[4][2], Bl[4][2];
#pragma unroll
            for (int mt = 0; mt < 4; mt++) {
                const uint32_t boff = swz((uint32_t)((aRow + mt * 16) * 128 + kk * 32 + aColHalf));
                ldsm_x4(Ah[mt][0], Ah[mt][1], Ah[mt][2], Ah[mt][3], sbase + offAh + boff);
                ldsm_x4(Al[mt][0], Al[mt][1], Al[mt][2], Al[mt][3], sbase + offAl + boff);
            }
#pragma unroll
            for (int nt = 0; nt < 4; nt++) {
                const uint32_t boff = swz((uint32_t)((bRow + nt * 8) * 128 + kk * 32 + bColHalf));
                ldsm_x2(Bh[nt][0], Bh[nt][1], sbase + offBh + boff);
                ldsm_x2(Bl[nt][0], Bl[nt][1], sbase + offBl + boff);
            }
#pragma unroll
            for (int mt = 0; mt < 4; mt++)
#pragma unroll
                for (int nt = 0; nt < 4; nt++) {
                    mma_bf16(acc[mt][nt], Ah[mt], Bh[nt]);
                    mma_bf16(acc[mt][nt], Ah[mt], Bl[nt]);
                    mma_bf16(acc[mt][nt], Al[mt], Bh[nt]);
                }
        }
    }

    // epilogue: write directly with constant-channel border contribution
    const float* cbp = &g_contrib[(size_t)b * 9 * Cc];
    const int mBase = co0 + wm * 64 + (lane >> 2);
    const int nBase = pix0 + wn * 32 + (lane & 3) * 2;
#pragma unroll
    for (int mt = 0; mt < 4; mt++) {
#pragma unroll
        for (int half = 0; half < 2; half++) {
            const int co = mBase + mt * 16 + half * 8;
            float* yrow = &g_y[((size_t)b * Cc + co) * LLEN];
#pragma unroll
            for (int nt = 0; nt < 4; nt++) {
#pragma unroll
                for (int e = 0; e < 2; e++) {
                    const int gp = nBase + nt * 8 + e;
                    const int y = gp >> 5, xg = gp & 31;
                    const int rt = (y == 0) ? 0 : ((y == 31) ? 2 : 1);
                    const int ct = (xg == 0) ? 0 : ((xg == 31) ? 2 : 1);
                    const float cc = cbp[(rt * 3 + ct) * Cc + co];
                    yrow[gp] = acc[mt][nt][half * 2 + e] + cc;
                }
            }
        }
    }
}

// ---------------- K7: BN batch statistics -------------------------------------
__global__ void k_stats(const float* __restrict__ bn_scale) {
    const int c = blockIdx.x, t = threadIdx.x;
    double s = 0.0, ss = 0.0;
    for (int idx = t; idx < Nn * LLEN; idx += 256) {
        const int bb = idx >> 10, l = idx & 1023;
        const float v = g_y[((size_t)bb * Cc + c) * LLEN + l];
        s += v; ss += (double)v * v;
    }
    __shared__ double rs[256], rq[256];
    rs[t] = s; rq[t] = ss; __syncthreads();
    for (int o = 128; o > 0; o >>= 1) {
        if (t < o) { rs[t] += rs[t + o]; rq[t] += rq[t + o]; }
        __syncthreads();
    }
    if (t == 0) {
        const double mean = rs[0] / (double)(Nn * LLEN);
        const double var  = rq[0] / (double)(Nn * LLEN) - mean * mean;
        g_stats[c * 2]     = (float)mean;
        g_stats[c * 2 + 1] = bn_scale[c] * rsqrtf((float)var + EPSf);
    }
}

// ---------------- K8: BN apply + ReLU + gamma*y + x ----------------------------
__global__ void k_final(const float* __restrict__ x, const float* __restrict__ bn_bias,
                        const float* __restrict__ gamma, float* __restrict__ out) {
    const int idx = blockIdx.x * 256 + threadIdx.x;
    const float g = gamma[0];
    const int c = (idx >> 10) & (Cc - 1);
    const float v = g_y[idx];
    float tt = (v - g_stats[c * 2]) * g_stats[c * 2 + 1] + bn_bias[c];
    tt = fmaxf(tt, 0.f);
    out[idx] = g * tt + x[idx];
}

// ---------------- launch ------------------------------------------------------
extern "C" void kernel_launch(void* const* d_in, const int* in_sizes, int n_in,
                              void* d_out, int out_size) {
    (void)in_sizes; (void)n_in; (void)out_size;
    const float* x        = (const float*)d_in[0];
    const float* rce_w    = (const float*)d_in[1];
    const float* rce_b    = (const float*)d_in[2];
    const float* q_w      = (const float*)d_in[3];
    const float* q_b      = (const float*)d_in[4];
    const float* k_w      = (const float*)d_in[5];
    const float* k_b      = (const float*)d_in[6];
    const float* value_w  = (const float*)d_in[7];
    const float* value_b  = (const float*)d_in[8];
    const float* fusion_w = (const float*)d_in[9];
    const float* bn_scale = (const float*)d_in[10];
    const float* bn_bias  = (const float*)d_in[11];
    const float* gamma    = (const float*)d_in[12];
    float* out = (float*)d_out;

    cudaFuncSetAttribute(k_attn, cudaFuncAttributeMaxDynamicSharedMemorySize, 81920);
    cudaFuncSetAttribute(k_conv_mma, cudaFuncAttributeMaxDynamicSharedMemorySize, 65536);

    k_value_proj<<<dim3(16, 2, 16), 256>>>(x, value_w, value_b);
    k_prep<<<16, 256>>>(x, rce_w, rce_b, q_w, q_b, k_w, k_b);
    k_mean<<<dim3(128, 16), 256>>>();
    k_wsum<<<512, 128>>>(fusion_w);
    k_const<<<16, 512>>>();
    k_wsplit<<<4608, 256>>>(fusion_w);
    k_attn<<<dim3(8, 2, 16), 256, 81920>>>();
    k_outgemm<<<dim3(16, 2, 32), 256>>>();
    k_im2col<<<147456, 256>>>();
    k_conv_mma<<<dim3(8, 4, 16), 256, 65536>>>();
    k_stats<<<512, 256>>>(bn_scale);
    k_final<<<32768, 256>>>(x, bn_bias, gamma, out);
}

// round 6
// speedup vs baseline: 1.2185x; 1.2185x over previous
#include <cuda_runtime.h>
#include <cuda_bf16.h>
#include <cstdint>
#include <stdint.h>
#include <math.h>

#define Nn 16
#define Cc 512
#define C4 128
#define QKC 16
#define LLEN 1024
#define EPSf 1e-5f
#define CONVK 2304          // 9 taps * 256 attn channels

// ---------------- scratch (device globals; no allocation allowed) ----------------
__device__ float g_value[Nn * C4 * LLEN];                 // proj_value
__device__ float g_qk[2 * 2 * Nn * QKC * LLEN];           // [q/k][pyr][b][qc][l]
__device__ float g_attn[2 * Nn * LLEN * LLEN];            // [pyr][b][m][l] probabilities
__device__ float g_y[Nn * Cc * LLEN];                     // conv output pre-BN
__device__ float g_stats[Cc * 2];
__device__ float g_mean[Nn * C4];
__device__ float g_wsum[9 * Cc * C4];
__device__ float g_contrib[Nn * 9 * Cc];
__device__ __nv_bfloat16 g_wh[Cc * CONVK];                // weight hi  [co][tap*256+cc]
__device__ __nv_bfloat16 g_wl[Cc * CONVK];                // weight lo
__device__ __nv_bfloat16 g_cth[(size_t)Nn * LLEN * 256];  // feat hi  [b][pix][cc]
__device__ __nv_bfloat16 g_ctl[(size_t)Nn * LLEN * 256];  // feat lo

__device__ __forceinline__ int qk_idx(int g, int py, int b, int qc, int l) {
    return (((g * 2 + py) * Nn + b) * QKC + qc) * LLEN + l;
}

// ---------------- PTX helpers (legacy tensor path, sm_80+) ----------------
__device__ __forceinline__ uint32_t smem_u32(const void* p) {
    uint32_t a;
    asm("{ .reg .u64 t; cvta.to.shared.u64 t, %1; cvt.u32.u64 %0, t; }" : "=r"(a) : "l"(p));
    return a;
}
__device__ __forceinline__ void ldsm_x4(uint32_t& r0, uint32_t& r1, uint32_t& r2, uint32_t& r3,
                                        uint32_t addr) {
    asm volatile("ldmatrix.sync.aligned.m8n8.x4.shared.b16 {%0,%1,%2,%3}, [%4];"
                 : "=r"(r0), "=r"(r1), "=r"(r2), "=r"(r3) : "r"(addr));
}
__device__ __forceinline__ void ldsm_x2(uint32_t& r0, uint32_t& r1, uint32_t addr) {
    asm volatile("ldmatrix.sync.aligned.m8n8.x2.shared.b16 {%0,%1}, [%2];"
                 : "=r"(r0), "=r"(r1) : "r"(addr));
}
__device__ __forceinline__ void mma_bf16(float* c, const uint32_t* a, const uint32_t* b) {
    asm volatile(
        "mma.sync.aligned.m16n8k16.row.col.f32.bf16.bf16.f32 "
        "{%0,%1,%2,%3}, {%4,%5,%6,%7}, {%8,%9}, {%0,%1,%2,%3};"
        : "+f"(c[0]), "+f"(c[1]), "+f"(c[2]), "+f"(c[3])
        : "r"(a[0]), "r"(a[1]), "r"(a[2]), "r"(a[3]), "r"(b[0]), "r"(b[1]));
}
__device__ __forceinline__ uint32_t swz(uint32_t boff) {
    return boff ^ ((boff >> 3) & 0x70);
}

// ---------------- K1: value projection GEMM ----
__global__ void k_value_proj(const float* __restrict__ x,
                             const float* __restrict__ w,
                             const float* __restrict__ bias) {
    __shared__ float As[32 * 68];
    __shared__ float Bs[32 * 68];
    const int b  = blockIdx.z;
    const int m0 = blockIdx.y * 64;
    const int n0 = blockIdx.x * 64;
    const float* xb = x + b * Cc * LLEN;
    const int t  = threadIdx.x;
    const int ty = t >> 4, tx = t & 15;
    const int am = t >> 2, akq = (t & 3) * 8;
    const int bk = t >> 3, bnq = (t & 7) * 8;
    float acc[4][4] = {};

    for (int kc = 0; kc < Cc / 32; kc++) {
        const int k0 = kc * 32;
        __syncthreads();
        float4 a0 = *(const float4*)&w[(m0 + am) * Cc + k0 + akq];
        float4 a1 = *(const float4*)&w[(m0 + am) * Cc + k0 + akq + 4];
        As[(akq + 0) * 68 + am] = a0.x; As[(akq + 1) * 68 + am] = a0.y;
        As[(akq + 2) * 68 + am] = a0.z; As[(akq + 3) * 68 + am] = a0.w;
        As[(akq + 4) * 68 + am] = a1.x; As[(akq + 5) * 68 + am] = a1.y;
        As[(akq + 6) * 68 + am] = a1.z; As[(akq + 7) * 68 + am] = a1.w;
        float4 b0 = *(const float4*)&xb[(k0 + bk) * LLEN + n0 + bnq];
        float4 b1 = *(const float4*)&xb[(k0 + bk) * LLEN + n0 + bnq + 4];
        *(float4*)&Bs[bk * 68 + bnq]     = b0;
        *(float4*)&Bs[bk * 68 + bnq + 4] = b1;
        __syncthreads();
#pragma unroll
        for (int k = 0; k < 32; k++) {
            float4 av = *(const float4*)&As[k * 68 + ty * 4];
            float4 bv = *(const float4*)&Bs[k * 68 + tx * 4];
            acc[0][0] += av.x * bv.x; acc[0][1] += av.x * bv.y; acc[0][2] += av.x * bv.z; acc[0][3] += av.x * bv.w;
            acc[1][0] += av.y * bv.x; acc[1][1] += av.y * bv.y; acc[1][2] += av.y * bv.z; acc[1][3] += av.y * bv.w;
            acc[2][0] += av.z * bv.x; acc[2][1] += av.z * bv.y; acc[2][2] += av.z * bv.z; acc[2][3] += av.z * bv.w;
            acc[3][0] += av.w * bv.x; acc[3][1] += av.w * bv.y; acc[3][2] += av.w * bv.z; acc[3][3] += av.w * bv.w;
        }
    }
#pragma unroll
    for (int i = 0; i < 4; i++) {
        const int c = m0 + ty * 4 + i;
        const float bs = bias[c];
        float4 o;
        o.x = acc[i][0] + bs; o.y = acc[i][1] + bs; o.z = acc[i][2] + bs; o.w = acc[i][3] + bs;
        *(float4*)&g_value[(b * C4 + c) * LLEN + n0 + tx * 4] = o;
    }
}

// ---------------- K2: pooling + rce + q/k feats + bilinear upsample -------------
__global__ void k_prep(const float* __restrict__ x,
                       const float* __restrict__ rce_w, const float* __restrict__ rce_b,
                       const float* __restrict__ qw, const float* __restrict__ qb,
                       const float* __restrict__ kw, const float* __restrict__ kb) {
    __shared__ float sp4[Cc * 16];
    __shared__ float f4[C4 * 16];
    __shared__ float f2[C4 * 4];
    __shared__ float qf4[QKC * 16], kf4[QKC * 16];
    __shared__ float qf2[QKC * 4],  kf2[QKC * 4];
    const int b = blockIdx.x, t = threadIdx.x;
    const float* xb = x + b * Cc * LLEN;

    for (int idx = t; idx < Cc * 16; idx += 256) {
        int c = idx >> 4, cell = idx & 15, i = cell >> 2, j = cell & 3;
        float s = 0.f;
        for (int y = 0; y < 8; y++)
#pragma unroll
            for (int xx = 0; xx < 8; xx++)
                s += xb[c * LLEN + (i * 8 + y) * 32 + j * 8 + xx];
        sp4[idx] = s * (1.f / 64.f);
    }
    __syncthreads();

    if (t < C4) {
        float a4[16] = {}, a2[4] = {};
        for (int c = 0; c < Cc; c++) {
            const float w4 = rce_w[(2 * C4 + t) * Cc + c];
            const float w2 = rce_w[(1 * C4 + t) * Cc + c];
            const float* p = &sp4[c * 16];
#pragma unroll
            for (int cell = 0; cell < 16; cell++) a4[cell] += w4 * p[cell];
#pragma unroll
            for (int i = 0; i < 2; i++)
#pragma unroll
                for (int j = 0; j < 2; j++)
                    a2[i * 2 + j] += w2 * 0.25f *
                        (p[(2 * i) * 4 + 2 * j] + p[(2 * i) * 4 + 2 * j + 1] +
                         p[(2 * i + 1) * 4 + 2 * j] + p[(2 * i + 1) * 4 + 2 * j + 1]);
        }
        const float b4 = rce_b[2 * C4 + t], b2v = rce_b[1 * C4 + t];
#pragma unroll
        for (int cell = 0; cell < 16; cell++) f4[t * 16 + cell] = a4[cell] + b4;
#pragma unroll
        for (int cc = 0; cc < 4; cc++) f2[t * 4 + cc] = a2[cc] + b2v;
    }
    __syncthreads();

    {
        const int qc = t >> 4, cell = t & 15;
        float aq = 0.f, ak = 0.f;
        for (int o = 0; o < C4; o++) {
            const float fv = f4[o * 16 + cell];
            aq += qw[qc * C4 + o] * fv;
            ak += kw[qc * C4 + o] * fv;
        }
        qf4[t] = aq + qb[qc]; kf4[t] = ak + kb[qc];
    }
    if (t < 64) {
        const int qc = t >> 2, cc = t & 3;
        float aq = 0.f, ak = 0.f;
        for (int o = 0; o < C4; o++) {
            const float fv = f2[o * 4 + cc];
            aq += qw[qc * C4 + o] * fv;
            ak += kw[qc * C4 + o] * fv;
        }
        qf2[t] = aq + qb[qc]; kf2[t] = ak + kb[qc];
    }
    __syncthreads();

    const float st4 = 3.0f / 31.0f, st2 = 1.0f / 31.0f;
    for (int idx = t; idx < QKC * LLEN; idx += 256) {
        const int qc = idx >> 10, p = idx & 1023, r = p >> 5, cc = p & 31;
        float pr = r * st4;  int lr = (int)pr; lr = lr > 2 ? 2 : lr; float fr = pr - lr;
        float pc = cc * st4; int lc = (int)pc; lc = lc > 2 ? 2 : lc; float fc = pc - lc;
        const float w00 = (1.f - fr) * (1.f - fc), w01 = (1.f - fr) * fc;
        const float w10 = fr * (1.f - fc),         w11 = fr * fc;
        const float* q4 = &qf4[qc * 16]; const float* k4 = &kf4[qc * 16];
        g_qk[qk_idx(0, 1, b, qc, p)] =
            w00 * q4[lr * 4 + lc] + w01 * q4[lr * 4 + lc + 1] +
            w10 * q4[(lr + 1) * 4 + lc] + w11 * q4[(lr + 1) * 4 + lc + 1];
        g_qk[qk_idx(1, 1, b, qc, p)] =
            w00 * k4[lr * 4 + lc] + w01 * k4[lr * 4 + lc + 1] +
            w10 * k4[(lr + 1) * 4 + lc] + w11 * k4[(lr + 1) * 4 + lc + 1];
        const float fr2 = r * st2, fc2 = cc * st2;
        const float u00 = (1.f - fr2) * (1.f - fc2), u01 = (1.f - fr2) * fc2;
        const float u10 = fr2 * (1.f - fc2),          u11 = fr2 * fc2;
        const float* q2 = &qf2[qc * 4]; const float* k2 = &kf2[qc * 4];
        g_qk[qk_idx(0, 0, b, qc, p)] = u00 * q2[0] + u01 * q2[1] + u10 * q2[2] + u11 * q2[3];
        g_qk[qk_idx(1, 0, b, qc, p)] = u00 * k2[0] + u01 * k2[1] + u10 * k2[2] + u11 * k2[3];
    }
}

// ---------------- K3: sz=1 pyramid mean ----------------------------
__global__ void k_mean() {
    const int c = blockIdx.x, b = blockIdx.y, t = threadIdx.x;
    const float* v = &g_value[(b * C4 + c) * LLEN];
    float s = 0.f;
    for (int i = t; i < LLEN; i += 256) s += v[i];
    __shared__ float red[256];
    red[t] = s; __syncthreads();
    for (int o = 128; o > 0; o >>= 1) { if (t < o) red[t] += red[t + o]; __syncthreads(); }
    if (t == 0) g_mean[b * C4 + c] = red[0] * (1.f / LLEN);
}

// ---------------- K3b: border-pattern weight sums ----------------
__global__ void k_wsum(const float* __restrict__ fw) {
    const int co = blockIdx.x, ci = threadIdx.x;
    float w[9];
#pragma unroll
    for (int k = 0; k < 9; k++) w[k] = fw[co * 3456 + ci * 9 + k];
#pragma unroll
    for (int rt = 0; rt < 3; rt++) {
        const int kylo = (rt == 0) ? 1 : 0, kyhi = (rt == 2) ? 1 : 2;
#pragma unroll
        for (int ct = 0; ct < 3; ct++) {
            const int kxlo = (ct == 0) ? 1 : 0, kxhi = (ct == 2) ? 1 : 2;
            float s = 0.f;
            for (int ky = kylo; ky <= kyhi; ky++)
                for (int kx = kxlo; kx <= kxhi; kx++)
                    s += w[ky * 3 + kx];
            g_wsum[((rt * 3 + ct) * Cc + co) * C4 + ci] = s;
        }
    }
}

// ---------------- K3c: constant-channel conv contribution ----------------
__global__ void k_const() {
    __shared__ float sm[C4];
    const int b = blockIdx.x, co = threadIdx.x;
    if (co < C4) sm[co] = g_mean[b * C4 + co];
    __syncthreads();
#pragma unroll
    for (int pat = 0; pat < 9; pat++) {
        const float* ws = &g_wsum[(pat * Cc + co) * C4];
        float s = 0.f;
        for (int ci = 0; ci < C4; ci++) s += sm[ci] * ws[ci];
        g_contrib[(b * 9 + pat) * Cc + co] = s;
    }
}

// ---------------- K3d: weight hi/lo bf16 split, reordered [co][tap*256+cc] -----
__global__ void k_wsplit(const float* __restrict__ fw) {
    const int idx = blockIdx.x * 256 + threadIdx.x;   // 512*2304
    const int co = idx / CONVK, k = idx % CONVK;
    const int tap = k >> 8, cc = k & 255;
    const float v = fw[co * 3456 + 1152 + cc * 9 + tap];
    const __nv_bfloat16 h = __float2bfloat16(v);
    g_wh[idx] = h;
    g_wl[idx] = __float2bfloat16(v - __bfloat162float(h));
}

// ---------------- K4: energy + softmax -> attn probabilities ----------------
__global__ void __launch_bounds__(256) k_attn() {
    extern __shared__ float ks[];
    const int b = blockIdx.z, pyr = blockIdx.y;
    const int mbase = blockIdx.x * 128;
    const int t = threadIdx.x, w = t >> 5, lane = t & 31;
    const float* gq = &g_qk[qk_idx(0, pyr, b, 0, 0)];
    const float* gk = &g_qk[qk_idx(1, pyr, b, 0, 0)];
    for (int idx = t; idx < QKC * LLEN; idx += 256) {
        const int qc = idx >> 10, l = idx & 1023;
        ks[l * 20 + qc] = gk[qc * LLEN + l];
    }
    __syncthreads();
    float* pb = &g_attn[(size_t)(pyr * Nn + b) * LLEN * LLEN];

    for (int pr = 0; pr < 16; pr++) {
        const int m = mbase + pr * 8 + w;
        float q[16];
#pragma unroll
        for (int j = 0; j < 16; j++) q[j] = gq[j * LLEN + m];
        float e[32];
        float mx = -1e30f;
#pragma unroll
        for (int i = 0; i < 32; i++) {
            const int l = i * 32 + lane;
            const float4* kp = (const float4*)&ks[l * 20];
            const float4 k0 = kp[0], k1 = kp[1], k2 = kp[2], k3 = kp[3];
            float s = q[0]*k0.x + q[1]*k0.y + q[2]*k0.z + q[3]*k0.w
                    + q[4]*k1.x + q[5]*k1.y + q[6]*k1.z + q[7]*k1.w
                    + q[8]*k2.x + q[9]*k2.y + q[10]*k2.z + q[11]*k2.w
                    + q[12]*k3.x + q[13]*k3.y + q[14]*k3.z + q[15]*k3.w;
            e[i] = s;
            mx = fmaxf(mx, s);
        }
#pragma unroll
        for (int o = 16; o > 0; o >>= 1)
            mx = fmaxf(mx, __shfl_xor_sync(0xffffffffu, mx, o));
        float sm = 0.f;
#pragma unroll
        for (int i = 0; i < 32; i++) { e[i] = __expf(e[i] - mx); sm += e[i]; }
#pragma unroll
        for (int o = 16; o > 0; o >>= 1)
            sm += __shfl_xor_sync(0xffffffffu, sm, o);
        const float inv = 1.f / sm;
        float* pa = &pb[(size_t)m * LLEN];
#pragma unroll
        for (int i = 0; i < 32; i++)
            pa[i * 32 + lane] = e[i] * inv;
    }
}

// ---------------- K5: out[c][m] = sum_l V[c][l] * P[m][l], writes catT hi/lo ---
__global__ void k_outgemm() {
    __shared__ float As[32 * 68];
    __shared__ float Bs[32 * 68];
    const int z = blockIdx.z; const int b = z >> 1; const int pyr = z & 1;
    const int c0 = blockIdx.y * 64;
    const int m0 = blockIdx.x * 64;
    const float* V = g_value + b * C4 * LLEN;
    const float* P = g_attn + (size_t)(pyr * Nn + b) * LLEN * LLEN;
    const int t = threadIdx.x, ty = t >> 4, tx = t & 15;
    const int r = t >> 2, kq = (t & 3) * 8;
    float acc[4][4] = {};

    for (int kc = 0; kc < LLEN / 32; kc++) {
        const int l0 = kc * 32;
        __syncthreads();
        float4 a0 = *(const float4*)&V[(c0 + r) * LLEN + l0 + kq];
        float4 a1 = *(const float4*)&V[(c0 + r) * LLEN + l0 + kq + 4];
        As[(kq + 0) * 68 + r] = a0.x; As[(kq + 1) * 68 + r] = a0.y;
        As[(kq + 2) * 68 + r] = a0.z; As[(kq + 3) * 68 + r] = a0.w;
        As[(kq + 4) * 68 + r] = a1.x; As[(kq + 5) * 68 + r] = a1.y;
        As[(kq + 6) * 68 + r] = a1.z; As[(kq + 7) * 68 + r] = a1.w;
        float4 b0 = *(const float4*)&P[(size_t)(m0 + r) * LLEN + l0 + kq];
        float4 b1 = *(const float4*)&P[(size_t)(m0 + r) * LLEN + l0 + kq + 4];
        Bs[(kq + 0) * 68 + r] = b0.x; Bs[(kq + 1) * 68 + r] = b0.y;
        Bs[(kq + 2) * 68 + r] = b0.z; Bs[(kq + 3) * 68 + r] = b0.w;
        Bs[(kq + 4) * 68 + r] = b1.x; Bs[(kq + 5) * 68 + r] = b1.y;
        Bs[(kq + 6) * 68 + r] = b1.z; Bs[(kq + 7) * 68 + r] = b1.w;
        __syncthreads();
#pragma unroll
        for (int k = 0; k < 32; k++) {
            float4 av = *(const float4*)&As[k * 68 + ty * 4];
            float4 bv = *(const float4*)&Bs[k * 68 + tx * 4];
            acc[0][0] += av.x * bv.x; acc[0][1] += av.x * bv.y; acc[0][2] += av.x * bv.z; acc[0][3] += av.x * bv.w;
            acc[1][0] += av.y * bv.x; acc[1][1] += av.y * bv.y; acc[1][2] += av.y * bv.z; acc[1][3] += av.y * bv.w;
            acc[2][0] += av.z * bv.x; acc[2][1] += av.z * bv.y; acc[2][2] += av.z * bv.z; acc[2][3] += av.z * bv.w;
            acc[3][0] += av.w * bv.x; acc[3][1] += av.w * bv.y; acc[3][2] += av.w * bv.z; acc[3][3] += av.w * bv.w;
        }
    }
    // epilogue: write transposed bf16 hi/lo feature map [b][pix][cc]
    const int ccBase = pyr * C4 + c0 + ty * 4;
#pragma unroll
    for (int j = 0; j < 4; j++) {
        const int m = m0 + tx * 4 + j;
        __nv_bfloat16 h[4], l[4];
#pragma unroll
        for (int i = 0; i < 4; i++) {
            const float v = acc[i][j];
            h[i] = __float2bfloat16(v);
            l[i] = __float2bfloat16(v - __bfloat162float(h[i]));
        }
        const size_t off = ((size_t)b * LLEN + m) * 256 + ccBase;
        *(uint2*)&g_cth[off] = *(const uint2*)h;
        *(uint2*)&g_ctl[off] = *(const uint2*)l;
    }
}

// ---------------- K6: fusion conv as HMMA bf16 GEMM (hi/lo, shifted-B im2col) --
// D[co 128][pix 128] = sum_{tap,cc} W[co, tap*256+cc] * catT[shift_tap(pix)][cc]
__global__ void __launch_bounds__(256) k_conv_mma() {
    extern __shared__ char dsm[];
    const uint32_t sbase = smem_u32(dsm);
    const uint32_t offAh = 0, offAl = 16384, offBh = 32768, offBl = 49152;

    const int b = blockIdx.z;
    const int co0 = blockIdx.y * 128;
    const int pix0 = blockIdx.x * 128;
    const int t = threadIdx.x;
    const int wid = t >> 5, lane = t & 31;
    const int wm = wid >> 2, wn = wid & 3;

    const __nv_bfloat16* __restrict__ wh = g_wh;
    const __nv_bfloat16* __restrict__ wl = g_wl;
    const __nv_bfloat16* __restrict__ cth = g_cth + (size_t)b * LLEN * 256;
    const __nv_bfloat16* __restrict__ ctl = g_ctl + (size_t)b * LLEN * 256;

    float acc[4][4][4] = {};   // [mt][nt][frag]

    const int aRow = wm * 64 + (lane & 15);
    const int aColHalf = (lane & 16) ? 16 : 0;
    const int bRow = wn * 32 + (lane & 7);
    const int bColHalf = (lane & 8) ? 16 : 0;

    for (int s = 0; s < 36; s++) {
        const int tap = s >> 2;
        const int ky = tap / 3, kx = tap - ky * 3;
        const int ci0 = (s & 3) * 64;
        const int kA = s * 64;
        __syncthreads();
        // stage 4 tiles of [128 rows][64 bf16] (128 B/row), swizzled
        for (int idx = t; idx < 1024; idx += 256) {
            const int r = idx >> 3, ch = idx & 7;
            const uint32_t sw = swz((uint32_t)(r * 128 + ch * 16));
            const int goff = ch * 8;
            uint4 v;
            v = *(const uint4*)(wh + (size_t)(co0 + r) * CONVK + kA + goff);
            *(uint4*)(dsm + offAh + sw) = v;
            v = *(const uint4*)(wl + (size_t)(co0 + r) * CONVK + kA + goff);
            *(uint4*)(dsm + offAl + sw) = v;
            // B: shifted pixel row with border masking
            const int gp = pix0 + r;
            const int sy = (gp >> 5) + ky - 1, sx = (gp & 31) + kx - 1;
            if (sy >= 0 && sy < 32 && sx >= 0 && sx < 32) {
                const size_t src = ((size_t)(sy * 32 + sx)) * 256 + ci0 + goff;
                *(uint4*)(dsm + offBh + sw) = *(const uint4*)(cth + src);
                *(uint4*)(dsm + offBl + sw) = *(const uint4*)(ctl + src);
            } else {
                const uint4 z = make_uint4(0, 0, 0, 0);
                *(uint4*)(dsm + offBh + sw) = z;
                *(uint4*)(dsm + offBl + sw) = z;
            }
        }
        __syncthreads();

#pragma unroll
        for (int kk = 0; kk < 4; kk++) {
            uint32_t Ah[4][4], Al[4][4], Bh[4][2], Bl[4][2];
#pragma unroll
            for (int mt = 0; mt < 4; mt++) {
                const uint32_t boff = swz((uint32_t)((aRow + mt * 16) * 128 + kk * 32 + aColHalf));
                ldsm_x4(Ah[mt][0], Ah[mt][1], Ah[mt][2], Ah[mt][3], sbase + offAh + boff);
                ldsm_x4(Al[mt][0], Al[mt][1], Al[mt][2], Al[mt][3], sbase + offAl + boff);
            }
#pragma unroll
            for (int nt = 0; nt < 4; nt++) {
                const uint32_t boff = swz((uint32_t)((bRow + nt * 8) * 128 + kk * 32 + bColHalf));
                ldsm_x2(Bh[nt][0], Bh[nt][1], sbase + offBh + boff);
                ldsm_x2(Bl[nt][0], Bl[nt][1], sbase + offBl + boff);
            }
#pragma unroll
            for (int mt = 0; mt < 4; mt++)
#pragma unroll
                for (int nt = 0; nt < 4; nt++) {
                    mma_bf16(acc[mt][nt], Ah[mt], Bh[nt]);
                    mma_bf16(acc[mt][nt], Ah[mt], Bl[nt]);
                    mma_bf16(acc[mt][nt], Al[mt], Bh[nt]);
                }
        }
    }

    // epilogue: write with constant-channel border contribution
    const float* cbp = &g_contrib[(size_t)b * 9 * Cc];
    const int mBase = co0 + wm * 64 + (lane >> 2);
    const int nBase = pix0 + wn * 32 + (lane & 3) * 2;
#pragma unroll
    for (int mt = 0; mt < 4; mt++) {
#pragma unroll
        for (int half = 0; half < 2; half++) {
            const int co = mBase + mt * 16 + half * 8;
            float* yrow = &g_y[((size_t)b * Cc + co) * LLEN];
#pragma unroll
            for (int nt = 0; nt < 4; nt++) {
#pragma unroll
                for (int e = 0; e < 2; e++) {
                    const int gp = nBase + nt * 8 + e;
                    const int y = gp >> 5, xg = gp & 31;
                    const int rt = (y == 0) ? 0 : ((y == 31) ? 2 : 1);
                    const int ct = (xg == 0) ? 0 : ((xg == 31) ? 2 : 1);
                    const float cc = cbp[(rt * 3 + ct) * Cc + co];
                    yrow[gp] = acc[mt][nt][half * 2 + e] + cc;
                }
            }
        }
    }
}

// ---------------- K7: BN batch statistics -------------------------------------
__global__ void k_stats(const float* __restrict__ bn_scale) {
    const int c = blockIdx.x, t = threadIdx.x;
    double s = 0.0, ss = 0.0;
    for (int idx = t; idx < Nn * LLEN; idx += 256) {
        const int bb = idx >> 10, l = idx & 1023;
        const float v = g_y[((size_t)bb * Cc + c) * LLEN + l];
        s += v; ss += (double)v * v;
    }
    __shared__ double rs[256], rq[256];
    rs[t] = s; rq[t] = ss; __syncthreads();
    for (int o = 128; o > 0; o >>= 1) {
        if (t < o) { rs[t] += rs[t + o]; rq[t] += rq[t + o]; }
        __syncthreads();
    }
    if (t == 0) {
        const double mean = rs[0] / (double)(Nn * LLEN);
        const double var  = rq[0] / (double)(Nn * LLEN) - mean * mean;
        g_stats[c * 2]     = (float)mean;
        g_stats[c * 2 + 1] = bn_scale[c] * rsqrtf((float)var + EPSf);
    }
}

// ---------------- K8: BN apply + ReLU + gamma*y + x ----------------------------
__global__ void k_final(const float* __restrict__ x, const float* __restrict__ bn_bias,
                        const float* __restrict__ gamma, float* __restrict__ out) {
    const int idx = blockIdx.x * 256 + threadIdx.x;
    const float g = gamma[0];
    const int c = (idx >> 10) & (Cc - 1);
    const float v = g_y[idx];
    float tt = (v - g_stats[c * 2]) * g_stats[c * 2 + 1] + bn_bias[c];
    tt = fmaxf(tt, 0.f);
    out[idx] = g * tt + x[idx];
}

// ---------------- launch ------------------------------------------------------
extern "C" void kernel_launch(void* const* d_in, const int* in_sizes, int n_in,
                              void* d_out, int out_size) {
    (void)in_sizes; (void)n_in; (void)out_size;
    const float* x        = (const float*)d_in[0];
    const float* rce_w    = (const float*)d_in[1];
    const float* rce_b    = (const float*)d_in[2];
    const float* q_w      = (const float*)d_in[3];
    const float* q_b      = (const float*)d_in[4];
    const float* k_w      = (const float*)d_in[5];
    const float* k_b      = (const float*)d_in[6];
    const float* value_w  = (const float*)d_in[7];
    const float* value_b  = (const float*)d_in[8];
    const float* fusion_w = (const float*)d_in[9];
    const float* bn_scale = (const float*)d_in[10];
    const float* bn_bias  = (const float*)d_in[11];
    const float* gamma    = (const float*)d_in[12];
    float* out = (float*)d_out;

    cudaFuncSetAttribute(k_attn, cudaFuncAttributeMaxDynamicSharedMemorySize, 81920);
    cudaFuncSetAttribute(k_conv_mma, cudaFuncAttributeMaxDynamicSharedMemorySize, 65536);

    k_value_proj<<<dim3(16, 2, 16), 256>>>(x, value_w, value_b);
    k_prep<<<16, 256>>>(x, rce_w, rce_b, q_w, q_b, k_w, k_b);
    k_mean<<<dim3(128, 16), 256>>>();
    k_wsum<<<512, 128>>>(fusion_w);
    k_const<<<16, 512>>>();
    k_wsplit<<<4608, 256>>>(fusion_w);
    k_attn<<<dim3(8, 2, 16), 256, 81920>>>();
    k_outgemm<<<dim3(16, 2, 32), 256>>>();
    k_conv_mma<<<dim3(8, 4, 16), 256, 65536>>>();
    k_stats<<<512, 256>>>(bn_scale);
    k_final<<<32768, 256>>>(x, bn_bias, gamma, out);
}

// round 7
// speedup vs baseline: 1.4686x; 1.2052x over previous
#include <cuda_runtime.h>
#include <cuda_bf16.h>
#include <cuda_fp16.h>
#include <cstdint>
#include <stdint.h>
#include <math.h>

#define Nn 16
#define Cc 512
#define C4 128
#define QKC 16
#define LLEN 1024
#define EPSf 1e-5f
#define CONVK 2304          // 9 taps * 256 attn channels

// ---------------- scratch (device globals; no allocation allowed) ----------------
__device__ float g_value[Nn * C4 * LLEN];                 // proj_value
__device__ float g_qk[2 * 2 * Nn * QKC * LLEN];           // [q/k][pyr][b][qc][l]
__device__ float g_attn[2 * Nn * LLEN * LLEN];            // [pyr][b][m][l] probabilities
__device__ float g_y[Nn * Cc * LLEN];                     // conv output pre-BN
__device__ float g_stats[Cc * 2];
__device__ float g_mean[Nn * C4];
__device__ float g_wsum[9 * Cc * C4];
__device__ float g_contrib[Nn * 9 * Cc];
__device__ __half g_wh[Cc * CONVK];                       // weight hi  [co][tap*256+cc]
__device__ __half g_wl[Cc * CONVK];                       // weight lo
__device__ __half g_cth[(size_t)Nn * LLEN * 256];         // feat fp16 [b][pix][cc]

__device__ __forceinline__ int qk_idx(int g, int py, int b, int qc, int l) {
    return (((g * 2 + py) * Nn + b) * QKC + qc) * LLEN + l;
}

// ---------------- PTX helpers (legacy tensor path, sm_80+) ----------------
__device__ __forceinline__ uint32_t smem_u32(const void* p) {
    uint32_t a;
    asm("{ .reg .u64 t; cvta.to.shared.u64 t, %1; cvt.u32.u64 %0, t; }" : "=r"(a) : "l"(p));
    return a;
}
__device__ __forceinline__ void ldsm_x4(uint32_t& r0, uint32_t& r1, uint32_t& r2, uint32_t& r3,
                                        uint32_t addr) {
    asm volatile("ldmatrix.sync.aligned.m8n8.x4.shared.b16 {%0,%1,%2,%3}, [%4];"
                 : "=r"(r0), "=r"(r1), "=r"(r2), "=r"(r3) : "r"(addr));
}
__device__ __forceinline__ void ldsm_x2(uint32_t& r0, uint32_t& r1, uint32_t addr) {
    asm volatile("ldmatrix.sync.aligned.m8n8.x2.shared.b16 {%0,%1}, [%2];"
                 : "=r"(r0), "=r"(r1) : "r"(addr));
}
__device__ __forceinline__ void mma_f16(float* c, const uint32_t* a, const uint32_t* b) {
    asm volatile(
        "mma.sync.aligned.m16n8k16.row.col.f32.f16.f16.f32 "
        "{%0,%1,%2,%3}, {%4,%5,%6,%7}, {%8,%9}, {%0,%1,%2,%3};"
        : "+f"(c[0]), "+f"(c[1]), "+f"(c[2]), "+f"(c[3])
        : "r"(a[0]), "r"(a[1]), "r"(a[2]), "r"(a[3]), "r"(b[0]), "r"(b[1]));
}
__device__ __forceinline__ uint32_t swz(uint32_t boff) {
    return boff ^ ((boff >> 3) & 0x70);
}
__device__ __forceinline__ void cp16(uint32_t dst, const void* src, bool pred) {
    const int sz = pred ? 16 : 0;
    asm volatile("cp.async.cg.shared.global [%0], [%1], 16, %2;"
                 :: "r"(dst), "l"(src), "r"(sz) : "memory");
}
__device__ __forceinline__ void cp_commit() {
    asm volatile("cp.async.commit_group;" ::: "memory");
}

// ---------------- K1: value projection GEMM ----
__global__ void k_value_proj(const float* __restrict__ x,
                             const float* __restrict__ w,
                             const float* __restrict__ bias) {
    __shared__ float As[32 * 68];
    __shared__ float Bs[32 * 68];
    const int b  = blockIdx.z;
    const int m0 = blockIdx.y * 64;
    const int n0 = blockIdx.x * 64;
    const float* xb = x + b * Cc * LLEN;
    const int t  = threadIdx.x;
    const int ty = t >> 4, tx = t & 15;
    const int am = t >> 2, akq = (t & 3) * 8;
    const int bk = t >> 3, bnq = (t & 7) * 8;
    float acc[4][4] = {};

    for (int kc = 0; kc < Cc / 32; kc++) {
        const int k0 = kc * 32;
        __syncthreads();
        float4 a0 = *(const float4*)&w[(m0 + am) * Cc + k0 + akq];
        float4 a1 = *(const float4*)&w[(m0 + am) * Cc + k0 + akq + 4];
        As[(akq + 0) * 68 + am] = a0.x; As[(akq + 1) * 68 + am] = a0.y;
        As[(akq + 2) * 68 + am] = a0.z; As[(akq + 3) * 68 + am] = a0.w;
        As[(akq + 4) * 68 + am] = a1.x; As[(akq + 5) * 68 + am] = a1.y;
        As[(akq + 6) * 68 + am] = a1.z; As[(akq + 7) * 68 + am] = a1.w;
        float4 b0 = *(const float4*)&xb[(k0 + bk) * LLEN + n0 + bnq];
        float4 b1 = *(const float4*)&xb[(k0 + bk) * LLEN + n0 + bnq + 4];
        *(float4*)&Bs[bk * 68 + bnq]     = b0;
        *(float4*)&Bs[bk * 68 + bnq + 4] = b1;
        __syncthreads();
#pragma unroll
        for (int k = 0; k < 32; k++) {
            float4 av = *(const float4*)&As[k * 68 + ty * 4];
            float4 bv = *(const float4*)&Bs[k * 68 + tx * 4];
            acc[0][0] += av.x * bv.x; acc[0][1] += av.x * bv.y; acc[0][2] += av.x * bv.z; acc[0][3] += av.x * bv.w;
            acc[1][0] += av.y * bv.x; acc[1][1] += av.y * bv.y; acc[1][2] += av.y * bv.z; acc[1][3] += av.y * bv.w;
            acc[2][0] += av.z * bv.x; acc[2][1] += av.z * bv.y; acc[2][2] += av.z * bv.z; acc[2][3] += av.z * bv.w;
            acc[3][0] += av.w * bv.x; acc[3][1] += av.w * bv.y; acc[3][2] += av.w * bv.z; acc[3][3] += av.w * bv.w;
        }
    }
#pragma unroll
    for (int i = 0; i < 4; i++) {
        const int c = m0 + ty * 4 + i;
        const float bs = bias[c];
        float4 o;
        o.x = acc[i][0] + bs; o.y = acc[i][1] + bs; o.z = acc[i][2] + bs; o.w = acc[i][3] + bs;
        *(float4*)&g_value[(b * C4 + c) * LLEN + n0 + tx * 4] = o;
    }
}

// ---------------- K2: pooling + rce + q/k feats + bilinear upsample -------------
__global__ void k_prep(const float* __restrict__ x,
                       const float* __restrict__ rce_w, const float* __restrict__ rce_b,
                       const float* __restrict__ qw, const float* __restrict__ qb,
                       const float* __restrict__ kw, const float* __restrict__ kb) {
    __shared__ float sp4[Cc * 16];
    __shared__ float f4[C4 * 16];
    __shared__ float f2[C4 * 4];
    __shared__ float qf4[QKC * 16], kf4[QKC * 16];
    __shared__ float qf2[QKC * 4],  kf2[QKC * 4];
    const int b = blockIdx.x, t = threadIdx.x;
    const float* xb = x + b * Cc * LLEN;

    for (int idx = t; idx < Cc * 16; idx += 256) {
        int c = idx >> 4, cell = idx & 15, i = cell >> 2, j = cell & 3;
        float s = 0.f;
        for (int y = 0; y < 8; y++)
#pragma unroll
            for (int xx = 0; xx < 8; xx++)
                s += xb[c * LLEN + (i * 8 + y) * 32 + j * 8 + xx];
        sp4[idx] = s * (1.f / 64.f);
    }
    __syncthreads();

    if (t < C4) {
        float a4[16] = {}, a2[4] = {};
        for (int c = 0; c < Cc; c++) {
            const float w4 = rce_w[(2 * C4 + t) * Cc + c];
            const float w2 = rce_w[(1 * C4 + t) * Cc + c];
            const float* p = &sp4[c * 16];
#pragma unroll
            for (int cell = 0; cell < 16; cell++) a4[cell] += w4 * p[cell];
#pragma unroll
            for (int i = 0; i < 2; i++)
#pragma unroll
                for (int j = 0; j < 2; j++)
                    a2[i * 2 + j] += w2 * 0.25f *
                        (p[(2 * i) * 4 + 2 * j] + p[(2 * i) * 4 + 2 * j + 1] +
                         p[(2 * i + 1) * 4 + 2 * j] + p[(2 * i + 1) * 4 + 2 * j + 1]);
        }
        const float b4 = rce_b[2 * C4 + t], b2v = rce_b[1 * C4 + t];
#pragma unroll
        for (int cell = 0; cell < 16; cell++) f4[t * 16 + cell] = a4[cell] + b4;
#pragma unroll
        for (int cc = 0; cc < 4; cc++) f2[t * 4 + cc] = a2[cc] + b2v;
    }
    __syncthreads();

    {
        const int qc = t >> 4, cell = t & 15;
        float aq = 0.f, ak = 0.f;
        for (int o = 0; o < C4; o++) {
            const float fv = f4[o * 16 + cell];
            aq += qw[qc * C4 + o] * fv;
            ak += kw[qc * C4 + o] * fv;
        }
        qf4[t] = aq + qb[qc]; kf4[t] = ak + kb[qc];
    }
    if (t < 64) {
        const int qc = t >> 2, cc = t & 3;
        float aq = 0.f, ak = 0.f;
        for (int o = 0; o < C4; o++) {
            const float fv = f2[o * 4 + cc];
            aq += qw[qc * C4 + o] * fv;
            ak += kw[qc * C4 + o] * fv;
        }
        qf2[t] = aq + qb[qc]; kf2[t] = ak + kb[qc];
    }
    __syncthreads();

    const float st4 = 3.0f / 31.0f, st2 = 1.0f / 31.0f;
    for (int idx = t; idx < QKC * LLEN; idx += 256) {
        const int qc = idx >> 10, p = idx & 1023, r = p >> 5, cc = p & 31;
        float pr = r * st4;  int lr = (int)pr; lr = lr > 2 ? 2 : lr; float fr = pr - lr;
        float pc = cc * st4; int lc = (int)pc; lc = lc > 2 ? 2 : lc; float fc = pc - lc;
        const float w00 = (1.f - fr) * (1.f - fc), w01 = (1.f - fr) * fc;
        const float w10 = fr * (1.f - fc),         w11 = fr * fc;
        const float* q4 = &qf4[qc * 16]; const float* k4 = &kf4[qc * 16];
        g_qk[qk_idx(0, 1, b, qc, p)] =
            w00 * q4[lr * 4 + lc] + w01 * q4[lr * 4 + lc + 1] +
            w10 * q4[(lr + 1) * 4 + lc] + w11 * q4[(lr + 1) * 4 + lc + 1];
        g_qk[qk_idx(1, 1, b, qc, p)] =
            w00 * k4[lr * 4 + lc] + w01 * k4[lr * 4 + lc + 1] +
            w10 * k4[(lr + 1) * 4 + lc] + w11 * k4[(lr + 1) * 4 + lc + 1];
        const float fr2 = r * st2, fc2 = cc * st2;
        const float u00 = (1.f - fr2) * (1.f - fc2), u01 = (1.f - fr2) * fc2;
        const float u10 = fr2 * (1.f - fc2),          u11 = fr2 * fc2;
        const float* q2 = &qf2[qc * 4]; const float* k2 = &kf2[qc * 4];
        g_qk[qk_idx(0, 0, b, qc, p)] = u00 * q2[0] + u01 * q2[1] + u10 * q2[2] + u11 * q2[3];
        g_qk[qk_idx(1, 0, b, qc, p)] = u00 * k2[0] + u01 * k2[1] + u10 * k2[2] + u11 * k2[3];
    }
}

// ---------------- K3: sz=1 pyramid mean ----------------------------
__global__ void k_mean() {
    const int c = blockIdx.x, b = blockIdx.y, t = threadIdx.x;
    const float* v = &g_value[(b * C4 + c) * LLEN];
    float s = 0.f;
    for (int i = t; i < LLEN; i += 256) s += v[i];
    __shared__ float red[256];
    red[t] = s; __syncthreads();
    for (int o = 128; o > 0; o >>= 1) { if (t < o) red[t] += red[t + o]; __syncthreads(); }
    if (t == 0) g_mean[b * C4 + c] = red[0] * (1.f / LLEN);
}

// ---------------- K3b: border-pattern weight sums ----------------
__global__ void k_wsum(const float* __restrict__ fw) {
    const int co = blockIdx.x, ci = threadIdx.x;
    float w[9];
#pragma unroll
    for (int k = 0; k < 9; k++) w[k] = fw[co * 3456 + ci * 9 + k];
#pragma unroll
    for (int rt = 0; rt < 3; rt++) {
        const int kylo = (rt == 0) ? 1 : 0, kyhi = (rt == 2) ? 1 : 2;
#pragma unroll
        for (int ct = 0; ct < 3; ct++) {
            const int kxlo = (ct == 0) ? 1 : 0, kxhi = (ct == 2) ? 1 : 2;
            float s = 0.f;
            for (int ky = kylo; ky <= kyhi; ky++)
                for (int kx = kxlo; kx <= kxhi; kx++)
                    s += w[ky * 3 + kx];
            g_wsum[((rt * 3 + ct) * Cc + co) * C4 + ci] = s;
        }
    }
}

// ---------------- K3c: constant-channel conv contribution ----------------
__global__ void k_const() {
    __shared__ float sm[C4];
    const int b = blockIdx.x, co = threadIdx.x;
    if (co < C4) sm[co] = g_mean[b * C4 + co];
    __syncthreads();
#pragma unroll
    for (int pat = 0; pat < 9; pat++) {
        const float* ws = &g_wsum[(pat * Cc + co) * C4];
        float s = 0.f;
        for (int ci = 0; ci < C4; ci++) s += sm[ci] * ws[ci];
        g_contrib[(b * 9 + pat) * Cc + co] = s;
    }
}

// ---------------- K3d: weight hi/lo fp16 split, reordered [co][tap*256+cc] -----
__global__ void k_wsplit(const float* __restrict__ fw) {
    const int idx = blockIdx.x * 256 + threadIdx.x;   // 512*2304
    const int co = idx / CONVK, k = idx % CONVK;
    const int tap = k >> 8, cc = k & 255;
    const float v = fw[co * 3456 + 1152 + cc * 9 + tap];
    const __half h = __float2half(v);
    g_wh[idx] = h;
    g_wl[idx] = __float2half(v - __half2float(h));
}

// ---------------- K4: energy + softmax -> attn probabilities ----------------
__global__ void __launch_bounds__(256) k_attn() {
    extern __shared__ float ks[];
    const int b = blockIdx.z, pyr = blockIdx.y;
    const int mbase = blockIdx.x * 128;
    const int t = threadIdx.x, w = t >> 5, lane = t & 31;
    const float* gq = &g_qk[qk_idx(0, pyr, b, 0, 0)];
    const float* gk = &g_qk[qk_idx(1, pyr, b, 0, 0)];
    for (int idx = t; idx < QKC * LLEN; idx += 256) {
        const int qc = idx >> 10, l = idx & 1023;
        ks[l * 20 + qc] = gk[qc * LLEN + l];
    }
    __syncthreads();
    float* pb = &g_attn[(size_t)(pyr * Nn + b) * LLEN * LLEN];

    for (int pr = 0; pr < 16; pr++) {
        const int m = mbase + pr * 8 + w;
        float q[16];
#pragma unroll
        for (int j = 0; j < 16; j++) q[j] = gq[j * LLEN + m];
        float e[32];
        float mx = -1e30f;
#pragma unroll
        for (int i = 0; i < 32; i++) {
            const int l = i * 32 + lane;
            const float4* kp = (const float4*)&ks[l * 20];
            const float4 k0 = kp[0], k1 = kp[1], k2 = kp[2], k3 = kp[3];
            float s = q[0]*k0.x + q[1]*k0.y + q[2]*k0.z + q[3]*k0.w
                    + q[4]*k1.x + q[5]*k1.y + q[6]*k1.z + q[7]*k1.w
                    + q[8]*k2.x + q[9]*k2.y + q[10]*k2.z + q[11]*k2.w
                    + q[12]*k3.x + q[13]*k3.y + q[14]*k3.z + q[15]*k3.w;
            e[i] = s;
            mx = fmaxf(mx, s);
        }
#pragma unroll
        for (int o = 16; o > 0; o >>= 1)
            mx = fmaxf(mx, __shfl_xor_sync(0xffffffffu, mx, o));
        float sm = 0.f;
#pragma unroll
        for (int i = 0; i < 32; i++) { e[i] = __expf(e[i] - mx); sm += e[i]; }
#pragma unroll
        for (int o = 16; o > 0; o >>= 1)
            sm += __shfl_xor_sync(0xffffffffu, sm, o);
        const float inv = 1.f / sm;
        float* pa = &pb[(size_t)m * LLEN];
#pragma unroll
        for (int i = 0; i < 32; i++)
            pa[i * 32 + lane] = e[i] * inv;
    }
}

// ---------------- K5: out[c][m] = sum_l V[c][l] * P[m][l], writes catT fp16 ----
__global__ void k_outgemm() {
    __shared__ float As[32 * 68];
    __shared__ float Bs[32 * 68];
    const int z = blockIdx.z; const int b = z >> 1; const int pyr = z & 1;
    const int c0 = blockIdx.y * 64;
    const int m0 = blockIdx.x * 64;
    const float* V = g_value + b * C4 * LLEN;
    const float* P = g_attn + (size_t)(pyr * Nn + b) * LLEN * LLEN;
    const int t = threadIdx.x, ty = t >> 4, tx = t & 15;
    const int r = t >> 2, kq = (t & 3) * 8;
    float acc[4][4] = {};

    for (int kc = 0; kc < LLEN / 32; kc++) {
        const int l0 = kc * 32;
        __syncthreads();
        float4 a0 = *(const float4*)&V[(c0 + r) * LLEN + l0 + kq];
        float4 a1 = *(const float4*)&V[(c0 + r) * LLEN + l0 + kq + 4];
        As[(kq + 0) * 68 + r] = a0.x; As[(kq + 1) * 68 + r] = a0.y;
        As[(kq + 2) * 68 + r] = a0.z; As[(kq + 3) * 68 + r] = a0.w;
        As[(kq + 4) * 68 + r] = a1.x; As[(kq + 5) * 68 + r] = a1.y;
        As[(kq + 6) * 68 + r] = a1.z; As[(kq + 7) * 68 + r] = a1.w;
        float4 b0 = *(const float4*)&P[(size_t)(m0 + r) * LLEN + l0 + kq];
        float4 b1 = *(const float4*)&P[(size_t)(m0 + r) * LLEN + l0 + kq + 4];
        Bs[(kq + 0) * 68 + r] = b0.x; Bs[(kq + 1) * 68 + r] = b0.y;
        Bs[(kq + 2) * 68 + r] = b0.z; Bs[(kq + 3) * 68 + r] = b0.w;
        Bs[(kq + 4) * 68 + r] = b1.x; Bs[(kq + 5) * 68 + r] = b1.y;
        Bs[(kq + 6) * 68 + r] = b1.z; Bs[(kq + 7) * 68 + r] = b1.w;
        __syncthreads();
#pragma unroll
        for (int k = 0; k < 32; k++) {
            float4 av = *(const float4*)&As[k * 68 + ty * 4];
            float4 bv = *(const float4*)&Bs[k * 68 + tx * 4];
            acc[0][0] += av.x * bv.x; acc[0][1] += av.x * bv.y; acc[0][2] += av.x * bv.z; acc[0][3] += av.x * bv.w;
            acc[1][0] += av.y * bv.x; acc[1][1] += av.y * bv.y; acc[1][2] += av.y * bv.z; acc[1][3] += av.y * bv.w;
            acc[2][0] += av.z * bv.x; acc[2][1] += av.z * bv.y; acc[2][2] += av.z * bv.z; acc[2][3] += av.z * bv.w;
            acc[3][0] += av.w * bv.x; acc[3][1] += av.w * bv.y; acc[3][2] += av.w * bv.z; acc[3][3] += av.w * bv.w;
        }
    }
    // epilogue: write transposed fp16 feature map [b][pix][cc]
    const int ccBase = pyr * C4 + c0 + ty * 4;
#pragma unroll
    for (int j = 0; j < 4; j++) {
        const int m = m0 + tx * 4 + j;
        __half h[4];
#pragma unroll
        for (int i = 0; i < 4; i++) h[i] = __float2half(acc[i][j]);
        const size_t off = ((size_t)b * LLEN + m) * 256 + ccBase;
        *(uint2*)&g_cth[off] = *(const uint2*)h;
    }
}

// ---------------- K6: fusion conv as fp16 HMMA GEMM (W hi/lo, cp.async 2-buf) --
// D[co 128][pix 128] = sum_{tap,cc} (Wh+Wl)[co, tap*256+cc] * catT[shift_tap(pix)][cc]
#define BUFB 49152
__global__ void __launch_bounds__(512) k_conv_mma() {
    extern __shared__ char dsm[];
    const uint32_t sbase = smem_u32(dsm);
    const uint32_t offAh = 0, offAl = 16384, offB = 32768;

    const int b = blockIdx.z;
    const int co0 = blockIdx.y * 128;
    const int pix0 = blockIdx.x * 128;
    const int t = threadIdx.x;
    const int wid = t >> 5, lane = t & 31;
    const int wm = wid >> 2, wn = wid & 3;   // 4x4 warp grid: 32 rows x 32 cols

    const __half* __restrict__ wh = g_wh;
    const __half* __restrict__ wl = g_wl;
    const __half* __restrict__ cth = g_cth + (size_t)b * LLEN * 256;

    float acc[2][4][4] = {};   // [mt][nt][frag]

    const int aRow = wm * 32 + (lane & 15);
    const int aColHalf = (lane & 16) ? 16 : 0;
    const int bRow = wn * 32 + (lane & 7);
    const int bColHalf = (lane & 8) ? 16 : 0;

    // stage loader: issue cp.async for stage s into buffer buf
    auto stage_load = [&](int s, uint32_t bufOff) {
        const int tap = s >> 2;
        const int ky = tap / 3, kx = tap - ky * 3;
        const int ci0 = (s & 3) * 64;
        const int kA = s * 64;
        for (int idx = t; idx < 1024; idx += 512) {
            const int r = idx >> 3, ch = idx & 7;
            const uint32_t sw = swz((uint32_t)(r * 128 + ch * 16));
            const int goff = ch * 8;
            cp16(sbase + bufOff + offAh + sw, wh + (size_t)(co0 + r) * CONVK + kA + goff, true);
            cp16(sbase + bufOff + offAl + sw, wl + (size_t)(co0 + r) * CONVK + kA + goff, true);
            const int gp = pix0 + r;
            const int sy = (gp >> 5) + ky - 1, sx = (gp & 31) + kx - 1;
            const bool ok = (sy >= 0 && sy < 32 && sx >= 0 && sx < 32);
            const __half* src = ok ? (cth + ((size_t)(sy * 32 + sx)) * 256 + ci0 + goff) : cth;
            cp16(sbase + bufOff + offB + sw, src, ok);
        }
        cp_commit();
    };

    stage_load(0, 0);

    for (int s = 0; s < 36; s++) {
        const uint32_t bufOff = (uint32_t)(s & 1) * BUFB;
        if (s < 35) {
            stage_load(s + 1, (uint32_t)((s + 1) & 1) * BUFB);
            asm volatile("cp.async.wait_group 1;" ::: "memory");
        } else {
            asm volatile("cp.async.wait_group 0;" ::: "memory");
        }
        __syncthreads();

#pragma unroll
        for (int kk = 0; kk < 4; kk++) {
            uint32_t Ah[2][4], Al[2][4], Bf[4][2];
#pragma unroll
            for (int mt = 0; mt < 2; mt++) {
                const uint32_t boff = swz((uint32_t)((aRow + mt * 16) * 128 + kk * 32 + aColHalf));
                ldsm_x4(Ah[mt][0], Ah[mt][1], Ah[mt][2], Ah[mt][3], sbase + bufOff + offAh + boff);
                ldsm_x4(Al[mt][0], Al[mt][1], Al[mt][2], Al[mt][3], sbase + bufOff + offAl + boff);
            }
#pragma unroll
            for (int nt = 0; nt < 4; nt++) {
                const uint32_t boff = swz((uint32_t)((bRow + nt * 8) * 128 + kk * 32 + bColHalf));
                ldsm_x2(Bf[nt][0], Bf[nt][1], sbase + bufOff + offB + boff);
            }
#pragma unroll
            for (int mt = 0; mt < 2; mt++)
#pragma unroll
                for (int nt = 0; nt < 4; nt++) {
                    mma_f16(acc[mt][nt], Ah[mt], Bf[nt]);
                    mma_f16(acc[mt][nt], Al[mt], Bf[nt]);
                }
        }
        __syncthreads();
    }

    // epilogue: write with constant-channel border contribution
    const float* cbp = &g_contrib[(size_t)b * 9 * Cc];
    const int mBase = co0 + wm * 32 + (lane >> 2);
    const int nBase = pix0 + wn * 32 + (lane & 3) * 2;
#pragma unroll
    for (int mt = 0; mt < 2; mt++) {
#pragma unroll
        for (int half = 0; half < 2; half++) {
            const int co = mBase + mt * 16 + half * 8;
            float* yrow = &g_y[((size_t)b * Cc + co) * LLEN];
#pragma unroll
            for (int nt = 0; nt < 4; nt++) {
#pragma unroll
                for (int e = 0; e < 2; e++) {
                    const int gp = nBase + nt * 8 + e;
                    const int y = gp >> 5, xg = gp & 31;
                    const int rt = (y == 0) ? 0 : ((y == 31) ? 2 : 1);
                    const int ct = (xg == 0) ? 0 : ((xg == 31) ? 2 : 1);
                    const float cc = cbp[(rt * 3 + ct) * Cc + co];
                    yrow[gp] = acc[mt][nt][half * 2 + e] + cc;
                }
            }
        }
    }
}

// ---------------- K7: BN batch statistics -------------------------------------
__global__ void k_stats(const float* __restrict__ bn_scale) {
    const int c = blockIdx.x, t = threadIdx.x;
    double s = 0.0, ss = 0.0;
    for (int idx = t; idx < Nn * LLEN; idx += 256) {
        const int bb = idx >> 10, l = idx & 1023;
        const float v = g_y[((size_t)bb * Cc + c) * LLEN + l];
        s += v; ss += (double)v * v;
    }
    __shared__ double rs[256], rq[256];
    rs[t] = s; rq[t] = ss; __syncthreads();
    for (int o = 128; o > 0; o >>= 1) {
        if (t < o) { rs[t] += rs[t + o]; rq[t] += rq[t + o]; }
        __syncthreads();
    }
    if (t == 0) {
        const double mean = rs[0] / (double)(Nn * LLEN);
        const double var  = rq[0] / (double)(Nn * LLEN) - mean * mean;
        g_stats[c * 2]     = (float)mean;
        g_stats[c * 2 + 1] = bn_scale[c] * rsqrtf((float)var + EPSf);
    }
}

// ---------------- K8: BN apply + ReLU + gamma*y + x ----------------------------
__global__ void k_final(const float* __restrict__ x, const float* __restrict__ bn_bias,
                        const float* __restrict__ gamma, float* __restrict__ out) {
    const int idx = blockIdx.x * 256 + threadIdx.x;
    const float g = gamma[0];
    const int c = (idx >> 10) & (Cc - 1);
    const float v = g_y[idx];
    float tt = (v - g_stats[c * 2]) * g_stats[c * 2 + 1] + bn_bias[c];
    tt = fmaxf(tt, 0.f);
    out[idx] = g * tt + x[idx];
}

// ---------------- launch ------------------------------------------------------
extern "C" void kernel_launch(void* const* d_in, const int* in_sizes, int n_in,
                              void* d_out, int out_size) {
    (void)in_sizes; (void)n_in; (void)out_size;
    const float* x        = (const float*)d_in[0];
    const float* rce_w    = (const float*)d_in[1];
    const float* rce_b    = (const float*)d_in[2];
    const float* q_w      = (const float*)d_in[3];
    const float* q_b      = (const float*)d_in[4];
    const float* k_w      = (const float*)d_in[5];
    const float* k_b      = (const float*)d_in[6];
    const float* value_w  = (const float*)d_in[7];
    const float* value_b  = (const float*)d_in[8];
    const float* fusion_w = (const float*)d_in[9];
    const float* bn_scale = (const float*)d_in[10];
    const float* bn_bias  = (const float*)d_in[11];
    const float* gamma    = (const float*)d_in[12];
    float* out = (float*)d_out;

    cudaFuncSetAttribute(k_attn, cudaFuncAttributeMaxDynamicSharedMemorySize, 81920);
    cudaFuncSetAttribute(k_conv_mma, cudaFuncAttributeMaxDynamicSharedMemorySize, 98304);

    k_value_proj<<<dim3(16, 2, 16), 256>>>(x, value_w, value_b);
    k_prep<<<16, 256>>>(x, rce_w, rce_b, q_w, q_b, k_w, k_b);
    k_mean<<<dim3(128, 16), 256>>>();
    k_wsum<<<512, 128>>>(fusion_w);
    k_const<<<16, 512>>>();
    k_wsplit<<<4608, 256>>>(fusion_w);
    k_attn<<<dim3(8, 2, 16), 256, 81920>>>();
    k_outgemm<<<dim3(16, 2, 32), 256>>>();
    k_conv_mma<<<dim3(8, 4, 16), 512, 98304>>>();
    k_stats<<<512, 256>>>(bn_scale);
    k_final<<<32768, 256>>>(x, bn_bias, gamma, out);
}

// round 8
// speedup vs baseline: 1.7143x; 1.1673x over previous
#include <cuda_runtime.h>
#include <cuda_bf16.h>
#include <cuda_fp16.h>
#include <cstdint>
#include <stdint.h>
#include <math.h>

#define Nn 16
#define Cc 512
#define C4 128
#define QKC 16
#define LLEN 1024
#define EPSf 1e-5f
#define CONVK 2304          // 9 taps * 256 attn channels

// ---------------- scratch (device globals; no allocation allowed) ----------------
__device__ float g_value[Nn * C4 * LLEN];                 // proj_value fp32
__device__ float g_qk[2 * 2 * Nn * QKC * LLEN];           // [q/k][pyr][b][qc][l]
__device__ __half g_attnh[(size_t)2 * Nn * LLEN * LLEN];  // [pyr][b][m][l] probs fp16
__device__ float g_y[Nn * Cc * LLEN];                     // conv output pre-BN
__device__ float g_stats[Cc * 2];
__device__ float g_mean[Nn * C4];
__device__ float g_wsum[9 * Cc * C4];
__device__ float g_contrib[Nn * 9 * Cc];
__device__ __half g_wh[Cc * CONVK];                       // weight hi  [co][tap*256+cc]
__device__ __half g_wl[Cc * CONVK];                       // weight lo
__device__ __half g_vh[Nn * C4 * LLEN];                   // V hi fp16 [b][c][l]
__device__ __half g_vl[Nn * C4 * LLEN];                   // V lo fp16
__device__ __half g_cth[(size_t)Nn * LLEN * 256];         // feat fp16 [b][pix][cc]

__device__ __forceinline__ int qk_idx(int g, int py, int b, int qc, int l) {
    return (((g * 2 + py) * Nn + b) * QKC + qc) * LLEN + l;
}

// ---------------- PTX helpers (legacy tensor path, sm_80+) ----------------
__device__ __forceinline__ uint32_t smem_u32(const void* p) {
    uint32_t a;
    asm("{ .reg .u64 t; cvta.to.shared.u64 t, %1; cvt.u32.u64 %0, t; }" : "=r"(a) : "l"(p));
    return a;
}
__device__ __forceinline__ void ldsm_x4(uint32_t& r0, uint32_t& r1, uint32_t& r2, uint32_t& r3,
                                        uint32_t addr) {
    asm volatile("ldmatrix.sync.aligned.m8n8.x4.shared.b16 {%0,%1,%2,%3}, [%4];"
                 : "=r"(r0), "=r"(r1), "=r"(r2), "=r"(r3) : "r"(addr));
}
__device__ __forceinline__ void ldsm_x2(uint32_t& r0, uint32_t& r1, uint32_t addr) {
    asm volatile("ldmatrix.sync.aligned.m8n8.x2.shared.b16 {%0,%1}, [%2];"
                 : "=r"(r0), "=r"(r1) : "r"(addr));
}
__device__ __forceinline__ void mma_f16(float* c, const uint32_t* a, const uint32_t* b) {
    asm volatile(
        "mma.sync.aligned.m16n8k16.row.col.f32.f16.f16.f32 "
        "{%0,%1,%2,%3}, {%4,%5,%6,%7}, {%8,%9}, {%0,%1,%2,%3};"
        : "+f"(c[0]), "+f"(c[1]), "+f"(c[2]), "+f"(c[3])
        : "r"(a[0]), "r"(a[1]), "r"(a[2]), "r"(a[3]), "r"(b[0]), "r"(b[1]));
}
__device__ __forceinline__ uint32_t swz(uint32_t boff) {
    return boff ^ ((boff >> 3) & 0x70);
}
__device__ __forceinline__ void cp16(uint32_t dst, const void* src, bool pred) {
    const int sz = pred ? 16 : 0;
    asm volatile("cp.async.cg.shared.global [%0], [%1], 16, %2;"
                 :: "r"(dst), "l"(src), "r"(sz) : "memory");
}
__device__ __forceinline__ void cp_commit() {
    asm volatile("cp.async.commit_group;" ::: "memory");
}

// ---------------- K1: value projection GEMM ----
__global__ void k_value_proj(const float* __restrict__ x,
                             const float* __restrict__ w,
                             const float* __restrict__ bias) {
    __shared__ float As[32 * 68];
    __shared__ float Bs[32 * 68];
    const int b  = blockIdx.z;
    const int m0 = blockIdx.y * 64;
    const int n0 = blockIdx.x * 64;
    const float* xb = x + b * Cc * LLEN;
    const int t  = threadIdx.x;
    const int ty = t >> 4, tx = t & 15;
    const int am = t >> 2, akq = (t & 3) * 8;
    const int bk = t >> 3, bnq = (t & 7) * 8;
    float acc[4][4] = {};

    for (int kc = 0; kc < Cc / 32; kc++) {
        const int k0 = kc * 32;
        __syncthreads();
        float4 a0 = *(const float4*)&w[(m0 + am) * Cc + k0 + akq];
        float4 a1 = *(const float4*)&w[(m0 + am) * Cc + k0 + akq + 4];
        As[(akq + 0) * 68 + am] = a0.x; As[(akq + 1) * 68 + am] = a0.y;
        As[(akq + 2) * 68 + am] = a0.z; As[(akq + 3) * 68 + am] = a0.w;
        As[(akq + 4) * 68 + am] = a1.x; As[(akq + 5) * 68 + am] = a1.y;
        As[(akq + 6) * 68 + am] = a1.z; As[(akq + 7) * 68 + am] = a1.w;
        float4 b0 = *(const float4*)&xb[(k0 + bk) * LLEN + n0 + bnq];
        float4 b1 = *(const float4*)&xb[(k0 + bk) * LLEN + n0 + bnq + 4];
        *(float4*)&Bs[bk * 68 + bnq]     = b0;
        *(float4*)&Bs[bk * 68 + bnq + 4] = b1;
        __syncthreads();
#pragma unroll
        for (int k = 0; k < 32; k++) {
            float4 av = *(const float4*)&As[k * 68 + ty * 4];
            float4 bv = *(const float4*)&Bs[k * 68 + tx * 4];
            acc[0][0] += av.x * bv.x; acc[0][1] += av.x * bv.y; acc[0][2] += av.x * bv.z; acc[0][3] += av.x * bv.w;
            acc[1][0] += av.y * bv.x; acc[1][1] += av.y * bv.y; acc[1][2] += av.y * bv.z; acc[1][3] += av.y * bv.w;
            acc[2][0] += av.z * bv.x; acc[2][1] += av.z * bv.y; acc[2][2] += av.z * bv.z; acc[2][3] += av.z * bv.w;
            acc[3][0] += av.w * bv.x; acc[3][1] += av.w * bv.y; acc[3][2] += av.w * bv.z; acc[3][3] += av.w * bv.w;
        }
    }
#pragma unroll
    for (int i = 0; i < 4; i++) {
        const int c = m0 + ty * 4 + i;
        const float bs = bias[c];
        float4 o;
        o.x = acc[i][0] + bs; o.y = acc[i][1] + bs; o.z = acc[i][2] + bs; o.w = acc[i][3] + bs;
        *(float4*)&g_value[(b * C4 + c) * LLEN + n0 + tx * 4] = o;
    }
}

// ---------------- K1b: V hi/lo fp16 split ----------------
__global__ void k_vsplit() {
    const int idx = blockIdx.x * 256 + threadIdx.x;   // Nn*C4*LLEN
    const float v = g_value[idx];
    const __half h = __float2half(v);
    g_vh[idx] = h;
    g_vl[idx] = __float2half(v - __half2float(h));
}

// ---------------- K2: pooling + rce + q/k feats + bilinear upsample -------------
__global__ void k_prep(const float* __restrict__ x,
                       const float* __restrict__ rce_w, const float* __restrict__ rce_b,
                       const float* __restrict__ qw, const float* __restrict__ qb,
                       const float* __restrict__ kw, const float* __restrict__ kb) {
    __shared__ float sp4[Cc * 16];
    __shared__ float f4[C4 * 16];
    __shared__ float f2[C4 * 4];
    __shared__ float qf4[QKC * 16], kf4[QKC * 16];
    __shared__ float qf2[QKC * 4],  kf2[QKC * 4];
    const int b = blockIdx.x, t = threadIdx.x;
    const float* xb = x + b * Cc * LLEN;

    for (int idx = t; idx < Cc * 16; idx += 256) {
        int c = idx >> 4, cell = idx & 15, i = cell >> 2, j = cell & 3;
        float s = 0.f;
        for (int y = 0; y < 8; y++)
#pragma unroll
            for (int xx = 0; xx < 8; xx++)
                s += xb[c * LLEN + (i * 8 + y) * 32 + j * 8 + xx];
        sp4[idx] = s * (1.f / 64.f);
    }
    __syncthreads();

    if (t < C4) {
        float a4[16] = {}, a2[4] = {};
        for (int c = 0; c < Cc; c++) {
            const float w4 = rce_w[(2 * C4 + t) * Cc + c];
            const float w2 = rce_w[(1 * C4 + t) * Cc + c];
            const float* p = &sp4[c * 16];
#pragma unroll
            for (int cell = 0; cell < 16; cell++) a4[cell] += w4 * p[cell];
#pragma unroll
            for (int i = 0; i < 2; i++)
#pragma unroll
                for (int j = 0; j < 2; j++)
                    a2[i * 2 + j] += w2 * 0.25f *
                        (p[(2 * i) * 4 + 2 * j] + p[(2 * i) * 4 + 2 * j + 1] +
                         p[(2 * i + 1) * 4 + 2 * j] + p[(2 * i + 1) * 4 + 2 * j + 1]);
        }
        const float b4 = rce_b[2 * C4 + t], b2v = rce_b[1 * C4 + t];
#pragma unroll
        for (int cell = 0; cell < 16; cell++) f4[t * 16 + cell] = a4[cell] + b4;
#pragma unroll
        for (int cc = 0; cc < 4; cc++) f2[t * 4 + cc] = a2[cc] + b2v;
    }
    __syncthreads();

    {
        const int qc = t >> 4, cell = t & 15;
        float aq = 0.f, ak = 0.f;
        for (int o = 0; o < C4; o++) {
            const float fv = f4[o * 16 + cell];
            aq += qw[qc * C4 + o] * fv;
            ak += kw[qc * C4 + o] * fv;
        }
        qf4[t] = aq + qb[qc]; kf4[t] = ak + kb[qc];
    }
    if (t < 64) {
        const int qc = t >> 2, cc = t & 3;
        float aq = 0.f, ak = 0.f;
        for (int o = 0; o < C4; o++) {
            const float fv = f2[o * 4 + cc];
            aq += qw[qc * C4 + o] * fv;
            ak += kw[qc * C4 + o] * fv;
        }
        qf2[t] = aq + qb[qc]; kf2[t] = ak + kb[qc];
    }
    __syncthreads();

    const float st4 = 3.0f / 31.0f, st2 = 1.0f / 31.0f;
    for (int idx = t; idx < QKC * LLEN; idx += 256) {
        const int qc = idx >> 10, p = idx & 1023, r = p >> 5, cc = p & 31;
        float pr = r * st4;  int lr = (int)pr; lr = lr > 2 ? 2 : lr; float fr = pr - lr;
        float pc = cc * st4; int lc = (int)pc; lc = lc > 2 ? 2 : lc; float fc = pc - lc;
        const float w00 = (1.f - fr) * (1.f - fc), w01 = (1.f - fr) * fc;
        const float w10 = fr * (1.f - fc),         w11 = fr * fc;
        const float* q4 = &qf4[qc * 16]; const float* k4 = &kf4[qc * 16];
        g_qk[qk_idx(0, 1, b, qc, p)] =
            w00 * q4[lr * 4 + lc] + w01 * q4[lr * 4 + lc + 1] +
            w10 * q4[(lr + 1) * 4 + lc] + w11 * q4[(lr + 1) * 4 + lc + 1];
        g_qk[qk_idx(1, 1, b, qc, p)] =
            w00 * k4[lr * 4 + lc] + w01 * k4[lr * 4 + lc + 1] +
            w10 * k4[(lr + 1) * 4 + lc] + w11 * k4[(lr + 1) * 4 + lc + 1];
        const float fr2 = r * st2, fc2 = cc * st2;
        const float u00 = (1.f - fr2) * (1.f - fc2), u01 = (1.f - fr2) * fc2;
        const float u10 = fr2 * (1.f - fc2),          u11 = fr2 * fc2;
        const float* q2 = &qf2[qc * 4]; const float* k2 = &kf2[qc * 4];
        g_qk[qk_idx(0, 0, b, qc, p)] = u00 * q2[0] + u01 * q2[1] + u10 * q2[2] + u11 * q2[3];
        g_qk[qk_idx(1, 0, b, qc, p)] = u00 * k2[0] + u01 * k2[1] + u10 * k2[2] + u11 * k2[3];
    }
}

// ---------------- K3: sz=1 pyramid mean ----------------------------
__global__ void k_mean() {
    const int c = blockIdx.x, b = blockIdx.y, t = threadIdx.x;
    const float* v = &g_value[(b * C4 + c) * LLEN];
    float s = 0.f;
    for (int i = t; i < LLEN; i += 256) s += v[i];
    __shared__ float red[256];
    red[t] = s; __syncthreads();
    for (int o = 128; o > 0; o >>= 1) { if (t < o) red[t] += red[t + o]; __syncthreads(); }
    if (t == 0) g_mean[b * C4 + c] = red[0] * (1.f / LLEN);
}

// ---------------- K3b: border-pattern weight sums ----------------
__global__ void k_wsum(const float* __restrict__ fw) {
    const int co = blockIdx.x, ci = threadIdx.x;
    float w[9];
#pragma unroll
    for (int k = 0; k < 9; k++) w[k] = fw[co * 3456 + ci * 9 + k];
#pragma unroll
    for (int rt = 0; rt < 3; rt++) {
        const int kylo = (rt == 0) ? 1 : 0, kyhi = (rt == 2) ? 1 : 2;
#pragma unroll
        for (int ct = 0; ct < 3; ct++) {
            const int kxlo = (ct == 0) ? 1 : 0, kxhi = (ct == 2) ? 1 : 2;
            float s = 0.f;
            for (int ky = kylo; ky <= kyhi; ky++)
                for (int kx = kxlo; kx <= kxhi; kx++)
                    s += w[ky * 3 + kx];
            g_wsum[((rt * 3 + ct) * Cc + co) * C4 + ci] = s;
        }
    }
}

// ---------------- K3c: constant-channel conv contribution ----------------
__global__ void k_const() {
    __shared__ float sm[C4];
    const int b = blockIdx.x, co = threadIdx.x;
    if (co < C4) sm[co] = g_mean[b * C4 + co];
    __syncthreads();
#pragma unroll
    for (int pat = 0; pat < 9; pat++) {
        const float* ws = &g_wsum[(pat * Cc + co) * C4];
        float s = 0.f;
        for (int ci = 0; ci < C4; ci++) s += sm[ci] * ws[ci];
        g_contrib[(b * 9 + pat) * Cc + co] = s;
    }
}

// ---------------- K3d: weight hi/lo fp16 split, reordered [co][tap*256+cc] -----
__global__ void k_wsplit(const float* __restrict__ fw) {
    const int idx = blockIdx.x * 256 + threadIdx.x;   // 512*2304
    const int co = idx / CONVK, k = idx % CONVK;
    const int tap = k >> 8, cc = k & 255;
    const float v = fw[co * 3456 + 1152 + cc * 9 + tap];
    const __half h = __float2half(v);
    g_wh[idx] = h;
    g_wl[idx] = __float2half(v - __half2float(h));
}

// ---------------- K4: energy + softmax -> attn probabilities (fp16 out) --------
__global__ void __launch_bounds__(256) k_attn() {
    extern __shared__ float ks[];
    const int b = blockIdx.z, pyr = blockIdx.y;
    const int mbase = blockIdx.x * 128;
    const int t = threadIdx.x, w = t >> 5, lane = t & 31;
    const float* gq = &g_qk[qk_idx(0, pyr, b, 0, 0)];
    const float* gk = &g_qk[qk_idx(1, pyr, b, 0, 0)];
    for (int idx = t; idx < QKC * LLEN; idx += 256) {
        const int qc = idx >> 10, l = idx & 1023;
        ks[l * 20 + qc] = gk[qc * LLEN + l];
    }
    __syncthreads();
    __half* pb = &g_attnh[(size_t)(pyr * Nn + b) * LLEN * LLEN];

    for (int pr = 0; pr < 16; pr++) {
        const int m = mbase + pr * 8 + w;
        float q[16];
#pragma unroll
        for (int j = 0; j < 16; j++) q[j] = gq[j * LLEN + m];
        float e[32];
        float mx = -1e30f;
#pragma unroll
        for (int i = 0; i < 32; i++) {
            const int l = i * 32 + lane;
            const float4* kp = (const float4*)&ks[l * 20];
            const float4 k0 = kp[0], k1 = kp[1], k2 = kp[2], k3 = kp[3];
            float s = q[0]*k0.x + q[1]*k0.y + q[2]*k0.z + q[3]*k0.w
                    + q[4]*k1.x + q[5]*k1.y + q[6]*k1.z + q[7]*k1.w
                    + q[8]*k2.x + q[9]*k2.y + q[10]*k2.z + q[11]*k2.w
                    + q[12]*k3.x + q[13]*k3.y + q[14]*k3.z + q[15]*k3.w;
            e[i] = s;
            mx = fmaxf(mx, s);
        }
#pragma unroll
        for (int o = 16; o > 0; o >>= 1)
            mx = fmaxf(mx, __shfl_xor_sync(0xffffffffu, mx, o));
        float sm = 0.f;
#pragma unroll
        for (int i = 0; i < 32; i++) { e[i] = __expf(e[i] - mx); sm += e[i]; }
#pragma unroll
        for (int o = 16; o > 0; o >>= 1)
            sm += __shfl_xor_sync(0xffffffffu, sm, o);
        const float inv = 1.f / sm;
        __half* pa = &pb[(size_t)m * LLEN];
#pragma unroll
        for (int i = 0; i < 32; i++)
            pa[i * 32 + lane] = __float2half(e[i] * inv);
    }
}

// ---------------- K5: HMMA out-GEMM: catT[pix][c] = sum_l V[c][l]*P[pix][l] ----
// A = V hi/lo fp16 [c 128][l], B = P fp16 [pix 128][l], K = 1024 (16 stages)
#define BUFO 49152
__global__ void __launch_bounds__(512) k_outgemm_mma() {
    extern __shared__ char dsm[];
    const uint32_t sbase = smem_u32(dsm);
    const uint32_t offAh = 0, offAl = 16384, offB = 32768;

    const int z = blockIdx.z; const int b = z >> 1; const int pyr = z & 1;
    const int pix0 = blockIdx.x * 128;
    const int t = threadIdx.x;
    const int wid = t >> 5, lane = t & 31;
    const int wm = wid >> 2, wn = wid & 3;   // 4x4 warps: 32 c-rows x 32 pix-cols

    const __half* __restrict__ vh = g_vh + (size_t)b * C4 * LLEN;
    const __half* __restrict__ vl = g_vl + (size_t)b * C4 * LLEN;
    const __half* __restrict__ P  = g_attnh + (size_t)(pyr * Nn + b) * LLEN * LLEN;

    float acc[2][4][4] = {};

    const int aRow = wm * 32 + (lane & 15);
    const int aColHalf = (lane & 16) ? 16 : 0;
    const int bRow = wn * 32 + (lane & 7);
    const int bColHalf = (lane & 8) ? 16 : 0;

    auto stage_load = [&](int s, uint32_t bufOff) {
        const int l0 = s * 64;
        for (int idx = t; idx < 1024; idx += 512) {
            const int r = idx >> 3, ch = idx & 7;
            const uint32_t sw = swz((uint32_t)(r * 128 + ch * 16));
            const int goff = ch * 8;
            cp16(sbase + bufOff + offAh + sw, vh + (size_t)r * LLEN + l0 + goff, true);
            cp16(sbase + bufOff + offAl + sw, vl + (size_t)r * LLEN + l0 + goff, true);
            cp16(sbase + bufOff + offB + sw, P + (size_t)(pix0 + r) * LLEN + l0 + goff, true);
        }
        cp_commit();
    };

    stage_load(0, 0);

    for (int s = 0; s < 16; s++) {
        const uint32_t bufOff = (uint32_t)(s & 1) * BUFO;
        if (s < 15) {
            stage_load(s + 1, (uint32_t)((s + 1) & 1) * BUFO);
            asm volatile("cp.async.wait_group 1;" ::: "memory");
        } else {
            asm volatile("cp.async.wait_group 0;" ::: "memory");
        }
        __syncthreads();

#pragma unroll
        for (int kk = 0; kk < 4; kk++) {
            uint32_t Ah[2][4], Al[2][4], Bf[4][2];
#pragma unroll
            for (int mt = 0; mt < 2; mt++) {
                const uint32_t boff = swz((uint32_t)((aRow + mt * 16) * 128 + kk * 32 + aColHalf));
                ldsm_x4(Ah[mt][0], Ah[mt][1], Ah[mt][2], Ah[mt][3], sbase + bufOff + offAh + boff);
                ldsm_x4(Al[mt][0], Al[mt][1], Al[mt][2], Al[mt][3], sbase + bufOff + offAl + boff);
            }
#pragma unroll
            for (int nt = 0; nt < 4; nt++) {
                const uint32_t boff = swz((uint32_t)((bRow + nt * 8) * 128 + kk * 32 + bColHalf));
                ldsm_x2(Bf[nt][0], Bf[nt][1], sbase + bufOff + offB + boff);
            }
#pragma unroll
            for (int mt = 0; mt < 2; mt++)
#pragma unroll
                for (int nt = 0; nt < 4; nt++) {
                    mma_f16(acc[mt][nt], Ah[mt], Bf[nt]);
                    mma_f16(acc[mt][nt], Al[mt], Bf[nt]);
                }
        }
        __syncthreads();
    }

    // epilogue: smem transpose [pixLocal][c] (pitch 136), then coalesced fp16 store
    __half* eb = (__half*)dsm;
    const int cBase = wm * 32 + (lane >> 2);
    const int pBase = wn * 32 + (lane & 3) * 2;
#pragma unroll
    for (int mt = 0; mt < 2; mt++)
#pragma unroll
        for (int half = 0; half < 2; half++) {
            const int c = cBase + mt * 16 + half * 8;
#pragma unroll
            for (int nt = 0; nt < 4; nt++)
#pragma unroll
                for (int e = 0; e < 2; e++) {
                    const int p = pBase + nt * 8 + e;
                    eb[p * 136 + c] = __float2half(acc[mt][nt][half * 2 + e]);
                }
        }
    __syncthreads();
    for (int idx = t; idx < 128 * 16; idx += 512) {
        const int row = idx >> 4, ch = idx & 15;
        const uint4 v = *(const uint4*)&eb[row * 136 + ch * 8];
        *(uint4*)&g_cth[((size_t)(b * LLEN + pix0 + row)) * 256 + pyr * C4 + ch * 8] = v;
    }
}

// ---------------- K6: fusion conv as fp16 HMMA GEMM (W hi/lo, cp.async 2-buf) --
#define BUFB 49152
__global__ void __launch_bounds__(512) k_conv_mma() {
    extern __shared__ char dsm[];
    const uint32_t sbase = smem_u32(dsm);
    const uint32_t offAh = 0, offAl = 16384, offB = 32768;

    const int b = blockIdx.z;
    const int co0 = blockIdx.y * 128;
    const int pix0 = blockIdx.x * 128;
    const int t = threadIdx.x;
    const int wid = t >> 5, lane = t & 31;
    const int wm = wid >> 2, wn = wid & 3;

    const __half* __restrict__ wh = g_wh;
    const __half* __restrict__ wl = g_wl;
    const __half* __restrict__ cth = g_cth + (size_t)b * LLEN * 256;

    float acc[2][4][4] = {};

    const int aRow = wm * 32 + (lane & 15);
    const int aColHalf = (lane & 16) ? 16 : 0;
    const int bRow = wn * 32 + (lane & 7);
    const int bColHalf = (lane & 8) ? 16 : 0;

    auto stage_load = [&](int s, uint32_t bufOff) {
        const int tap = s >> 2;
        const int ky = tap / 3, kx = tap - ky * 3;
        const int ci0 = (s & 3) * 64;
        const int kA = s * 64;
        for (int idx = t; idx < 1024; idx += 512) {
            const int r = idx >> 3, ch = idx & 7;
            const uint32_t sw = swz((uint32_t)(r * 128 + ch * 16));
            const int goff = ch * 8;
            cp16(sbase + bufOff + offAh + sw, wh + (size_t)(co0 + r) * CONVK + kA + goff, true);
            cp16(sbase + bufOff + offAl + sw, wl + (size_t)(co0 + r) * CONVK + kA + goff, true);
            const int gp = pix0 + r;
            const int sy = (gp >> 5) + ky - 1, sx = (gp & 31) + kx - 1;
            const bool ok = (sy >= 0 && sy < 32 && sx >= 0 && sx < 32);
            const __half* src = ok ? (cth + ((size_t)(sy * 32 + sx)) * 256 + ci0 + goff) : cth;
            cp16(sbase + bufOff + offB + sw, src, ok);
        }
        cp_commit();
    };

    stage_load(0, 0);

    for (int s = 0; s < 36; s++) {
        const uint32_t bufOff = (uint32_t)(s & 1) * BUFB;
        if (s < 35) {
            stage_load(s + 1, (uint32_t)((s + 1) & 1) * BUFB);
            asm volatile("cp.async.wait_group 1;" ::: "memory");
        } else {
            asm volatile("cp.async.wait_group 0;" ::: "memory");
        }
        __syncthreads();

#pragma unroll
        for (int kk = 0; kk < 4; kk++) {
            uint32_t Ah[2][4], Al[2][4], Bf[4][2];
#pragma unroll
            for (int mt = 0; mt < 2; mt++) {
                const uint32_t boff = swz((uint32_t)((aRow + mt * 16) * 128 + kk * 32 + aColHalf));
                ldsm_x4(Ah[mt][0], Ah[mt][1], Ah[mt][2], Ah[mt][3], sbase + bufOff + offAh + boff);
                ldsm_x4(Al[mt][0], Al[mt][1], Al[mt][2], Al[mt][3], sbase + bufOff + offAl + boff);
            }
#pragma unroll
            for (int nt = 0; nt < 4; nt++) {
                const uint32_t boff = swz((uint32_t)((bRow + nt * 8) * 128 + kk * 32 + bColHalf));
                ldsm_x2(Bf[nt][0], Bf[nt][1], sbase + bufOff + offB + boff);
            }
#pragma unroll
            for (int mt = 0; mt < 2; mt++)
#pragma unroll
                for (int nt = 0; nt < 4; nt++) {
                    mma_f16(acc[mt][nt], Ah[mt], Bf[nt]);
                    mma_f16(acc[mt][nt], Al[mt], Bf[nt]);
                }
        }
        __syncthreads();
    }

    const float* cbp = &g_contrib[(size_t)b * 9 * Cc];
    const int mBase = co0 + wm * 32 + (lane >> 2);
    const int nBase = pix0 + wn * 32 + (lane & 3) * 2;
#pragma unroll
    for (int mt = 0; mt < 2; mt++) {
#pragma unroll
        for (int half = 0; half < 2; half++) {
            const int co = mBase + mt * 16 + half * 8;
            float* yrow = &g_y[((size_t)b * Cc + co) * LLEN];
#pragma unroll
            for (int nt = 0; nt < 4; nt++) {
#pragma unroll
                for (int e = 0; e < 2; e++) {
                    const int gp = nBase + nt * 8 + e;
                    const int y = gp >> 5, xg = gp & 31;
                    const int rt = (y == 0) ? 0 : ((y == 31) ? 2 : 1);
                    const int ct = (xg == 0) ? 0 : ((xg == 31) ? 2 : 1);
                    const float cc = cbp[(rt * 3 + ct) * Cc + co];
                    yrow[gp] = acc[mt][nt][half * 2 + e] + cc;
                }
            }
        }
    }
}

// ---------------- K7: BN batch statistics -------------------------------------
__global__ void k_stats(const float* __restrict__ bn_scale) {
    const int c = blockIdx.x, t = threadIdx.x;
    double s = 0.0, ss = 0.0;
    for (int idx = t; idx < Nn * LLEN; idx += 256) {
        const int bb = idx >> 10, l = idx & 1023;
        const float v = g_y[((size_t)bb * Cc + c) * LLEN + l];
        s += v; ss += (double)v * v;
    }
    __shared__ double rs[256], rq[256];
    rs[t] = s; rq[t] = ss; __syncthreads();
    for (int o = 128; o > 0; o >>= 1) {
        if (t < o) { rs[t] += rs[t + o]; rq[t] += rq[t + o]; }
        __syncthreads();
    }
    if (t == 0) {
        const double mean = rs[0] / (double)(Nn * LLEN);
        const double var  = rq[0] / (double)(Nn * LLEN) - mean * mean;
        g_stats[c * 2]     = (float)mean;
        g_stats[c * 2 + 1] = bn_scale[c] * rsqrtf((float)var + EPSf);
    }
}

// ---------------- K8: BN apply + ReLU + gamma*y + x ----------------------------
__global__ void k_final(const float* __restrict__ x, const float* __restrict__ bn_bias,
                        const float* __restrict__ gamma, float* __restrict__ out) {
    const int idx = blockIdx.x * 256 + threadIdx.x;
    const float g = gamma[0];
    const int c = (idx >> 10) & (Cc - 1);
    const float v = g_y[idx];
    float tt = (v - g_stats[c * 2]) * g_stats[c * 2 + 1] + bn_bias[c];
    tt = fmaxf(tt, 0.f);
    out[idx] = g * tt + x[idx];
}

// ---------------- launch ------------------------------------------------------
extern "C" void kernel_launch(void* const* d_in, const int* in_sizes, int n_in,
                              void* d_out, int out_size) {
    (void)in_sizes; (void)n_in; (void)out_size;
    const float* x        = (const float*)d_in[0];
    const float* rce_w    = (const float*)d_in[1];
    const float* rce_b    = (const float*)d_in[2];
    const float* q_w      = (const float*)d_in[3];
    const float* q_b      = (const float*)d_in[4];
    const float* k_w      = (const float*)d_in[5];
    const float* k_b      = (const float*)d_in[6];
    const float* value_w  = (const float*)d_in[7];
    const float* value_b  = (const float*)d_in[8];
    const float* fusion_w = (const float*)d_in[9];
    const float* bn_scale = (const float*)d_in[10];
    const float* bn_bias  = (const float*)d_in[11];
    const float* gamma    = (const float*)d_in[12];
    float* out = (float*)d_out;

    cudaFuncSetAttribute(k_attn, cudaFuncAttributeMaxDynamicSharedMemorySize, 81920);
    cudaFuncSetAttribute(k_conv_mma, cudaFuncAttributeMaxDynamicSharedMemorySize, 98304);
    cudaFuncSetAttribute(k_outgemm_mma, cudaFuncAttributeMaxDynamicSharedMemorySize, 98304);

    k_value_proj<<<dim3(16, 2, 16), 256>>>(x, value_w, value_b);
    k_vsplit<<<8192, 256>>>();
    k_prep<<<16, 256>>>(x, rce_w, rce_b, q_w, q_b, k_w, k_b);
    k_mean<<<dim3(128, 16), 256>>>();
    k_wsum<<<512, 128>>>(fusion_w);
    k_const<<<16, 512>>>();
    k_wsplit<<<4608, 256>>>(fusion_w);
    k_attn<<<dim3(8, 2, 16), 256, 81920>>>();
    k_outgemm_mma<<<dim3(8, 1, 32), 512, 98304>>>();
    k_conv_mma<<<dim3(8, 4, 16), 512, 98304>>>();
    k_stats<<<512, 256>>>(bn_scale);
    k_final<<<32768, 256>>>(x, bn_bias, gamma, out);
}

// round 9
// speedup vs baseline: 1.9134x; 1.1162x over previous
#include <cuda_runtime.h>
#include <cuda_bf16.h>
#include <cuda_fp16.h>
#include <cstdint>
#include <stdint.h>
#include <math.h>

#define Nn 16
#define Cc 512
#define C4 128
#define QKC 16
#define LLEN 1024
#define EPSf 1e-5f
#define CONVK 2304          // 9 taps * 256 attn channels

// ---------------- scratch (device globals; no allocation allowed) ----------------
__device__ float g_value[Nn * C4 * LLEN];                 // proj_value fp32
__device__ float g_qk[2 * 2 * Nn * QKC * LLEN];           // [q/k][pyr][b][qc][l]
__device__ __half g_attnh[(size_t)2 * Nn * LLEN * LLEN];  // [pyr][b][m][l] probs fp16
__device__ float g_y[Nn * Cc * LLEN];                     // conv output pre-BN
__device__ float g_stats[Cc * 2];
__device__ float g_mean[Nn * C4];
__device__ float g_wsum[9 * Cc * C4];
__device__ float g_contrib[Nn * 9 * Cc];
__device__ __half g_wh[Cc * CONVK];                       // weight fp16 [co][tap*256+cc]
__device__ __half g_vh[Nn * C4 * LLEN];                   // V fp16 [b][c][l]
__device__ __half g_cth[(size_t)Nn * LLEN * 256];         // feat fp16 [b][pix][cc]

__device__ __forceinline__ int qk_idx(int g, int py, int b, int qc, int l) {
    return (((g * 2 + py) * Nn + b) * QKC + qc) * LLEN + l;
}

// ---------------- PTX helpers (legacy tensor path, sm_80+) ----------------
__device__ __forceinline__ uint32_t smem_u32(const void* p) {
    uint32_t a;
    asm("{ .reg .u64 t; cvta.to.shared.u64 t, %1; cvt.u32.u64 %0, t; }" : "=r"(a) : "l"(p));
    return a;
}
__device__ __forceinline__ void ldsm_x4(uint32_t& r0, uint32_t& r1, uint32_t& r2, uint32_t& r3,
                                        uint32_t addr) {
    asm volatile("ldmatrix.sync.aligned.m8n8.x4.shared.b16 {%0,%1,%2,%3}, [%4];"
                 : "=r"(r0), "=r"(r1), "=r"(r2), "=r"(r3) : "r"(addr));
}
__device__ __forceinline__ void ldsm_x2(uint32_t& r0, uint32_t& r1, uint32_t addr) {
    asm volatile("ldmatrix.sync.aligned.m8n8.x2.shared.b16 {%0,%1}, [%2];"
                 : "=r"(r0), "=r"(r1) : "r"(addr));
}
__device__ __forceinline__ void mma_f16(float* c, const uint32_t* a, const uint32_t* b) {
    asm volatile(
        "mma.sync.aligned.m16n8k16.row.col.f32.f16.f16.f32 "
        "{%0,%1,%2,%3}, {%4,%5,%6,%7}, {%8,%9}, {%0,%1,%2,%3};"
        : "+f"(c[0]), "+f"(c[1]), "+f"(c[2]), "+f"(c[3])
        : "r"(a[0]), "r"(a[1]), "r"(a[2]), "r"(a[3]), "r"(b[0]), "r"(b[1]));
}
__device__ __forceinline__ uint32_t swz(uint32_t boff) {
    return boff ^ ((boff >> 3) & 0x70);
}
__device__ __forceinline__ void cp16(uint32_t dst, const void* src, bool pred) {
    const int sz = pred ? 16 : 0;
    asm volatile("cp.async.cg.shared.global [%0], [%1], 16, %2;"
                 :: "r"(dst), "l"(src), "r"(sz) : "memory");
}
__device__ __forceinline__ void cp_commit() {
    asm volatile("cp.async.commit_group;" ::: "memory");
}

// ---------------- K1: value projection GEMM (also emits fp16 V) ----
__global__ void k_value_proj(const float* __restrict__ x,
                             const float* __restrict__ w,
                             const float* __restrict__ bias) {
    __shared__ float As[32 * 68];
    __shared__ float Bs[32 * 68];
    const int b  = blockIdx.z;
    const int m0 = blockIdx.y * 64;
    const int n0 = blockIdx.x * 64;
    const float* xb = x + b * Cc * LLEN;
    const int t  = threadIdx.x;
    const int ty = t >> 4, tx = t & 15;
    const int am = t >> 2, akq = (t & 3) * 8;
    const int bk = t >> 3, bnq = (t & 7) * 8;
    float acc[4][4] = {};

    for (int kc = 0; kc < Cc / 32; kc++) {
        const int k0 = kc * 32;
        __syncthreads();
        float4 a0 = *(const float4*)&w[(m0 + am) * Cc + k0 + akq];
        float4 a1 = *(const float4*)&w[(m0 + am) * Cc + k0 + akq + 4];
        As[(akq + 0) * 68 + am] = a0.x; As[(akq + 1) * 68 + am] = a0.y;
        As[(akq + 2) * 68 + am] = a0.z; As[(akq + 3) * 68 + am] = a0.w;
        As[(akq + 4) * 68 + am] = a1.x; As[(akq + 5) * 68 + am] = a1.y;
        As[(akq + 6) * 68 + am] = a1.z; As[(akq + 7) * 68 + am] = a1.w;
        float4 b0 = *(const float4*)&xb[(k0 + bk) * LLEN + n0 + bnq];
        float4 b1 = *(const float4*)&xb[(k0 + bk) * LLEN + n0 + bnq + 4];
        *(float4*)&Bs[bk * 68 + bnq]     = b0;
        *(float4*)&Bs[bk * 68 + bnq + 4] = b1;
        __syncthreads();
#pragma unroll
        for (int k = 0; k < 32; k++) {
            float4 av = *(const float4*)&As[k * 68 + ty * 4];
            float4 bv = *(const float4*)&Bs[k * 68 + tx * 4];
            acc[0][0] += av.x * bv.x; acc[0][1] += av.x * bv.y; acc[0][2] += av.x * bv.z; acc[0][3] += av.x * bv.w;
            acc[1][0] += av.y * bv.x; acc[1][1] += av.y * bv.y; acc[1][2] += av.y * bv.z; acc[1][3] += av.y * bv.w;
            acc[2][0] += av.z * bv.x; acc[2][1] += av.z * bv.y; acc[2][2] += av.z * bv.z; acc[2][3] += av.z * bv.w;
            acc[3][0] += av.w * bv.x; acc[3][1] += av.w * bv.y; acc[3][2] += av.w * bv.z; acc[3][3] += av.w * bv.w;
        }
    }
#pragma unroll
    for (int i = 0; i < 4; i++) {
        const int c = m0 + ty * 4 + i;
        const float bs = bias[c];
        float4 o;
        o.x = acc[i][0] + bs; o.y = acc[i][1] + bs; o.z = acc[i][2] + bs; o.w = acc[i][3] + bs;
        const size_t off = (size_t)(b * C4 + c) * LLEN + n0 + tx * 4;
        *(float4*)&g_value[off] = o;
        __half h[4] = {__float2half(o.x), __float2half(o.y), __float2half(o.z), __float2half(o.w)};
        *(uint2*)&g_vh[off] = *(const uint2*)h;
    }
}

// ---------------- K2: pooling + rce + q/k feats + bilinear upsample -------------
__global__ void k_prep(const float* __restrict__ x,
                       const float* __restrict__ rce_w, const float* __restrict__ rce_b,
                       const float* __restrict__ qw, const float* __restrict__ qb,
                       const float* __restrict__ kw, const float* __restrict__ kb) {
    __shared__ float sp4[Cc * 16];
    __shared__ float f4[C4 * 16];
    __shared__ float f2[C4 * 4];
    __shared__ float qf4[QKC * 16], kf4[QKC * 16];
    __shared__ float qf2[QKC * 4],  kf2[QKC * 4];
    const int b = blockIdx.x, t = threadIdx.x;
    const float* xb = x + b * Cc * LLEN;

    for (int idx = t; idx < Cc * 16; idx += 256) {
        int c = idx >> 4, cell = idx & 15, i = cell >> 2, j = cell & 3;
        float s = 0.f;
        for (int y = 0; y < 8; y++)
#pragma unroll
            for (int xx = 0; xx < 8; xx++)
                s += xb[c * LLEN + (i * 8 + y) * 32 + j * 8 + xx];
        sp4[idx] = s * (1.f / 64.f);
    }
    __syncthreads();

    if (t < C4) {
        float a4[16] = {}, a2[4] = {};
        for (int c = 0; c < Cc; c++) {
            const float w4 = rce_w[(2 * C4 + t) * Cc + c];
            const float w2 = rce_w[(1 * C4 + t) * Cc + c];
            const float* p = &sp4[c * 16];
#pragma unroll
            for (int cell = 0; cell < 16; cell++) a4[cell] += w4 * p[cell];
#pragma unroll
            for (int i = 0; i < 2; i++)
#pragma unroll
                for (int j = 0; j < 2; j++)
                    a2[i * 2 + j] += w2 * 0.25f *
                        (p[(2 * i) * 4 + 2 * j] + p[(2 * i) * 4 + 2 * j + 1] +
                         p[(2 * i + 1) * 4 + 2 * j] + p[(2 * i + 1) * 4 + 2 * j + 1]);
        }
        const float b4 = rce_b[2 * C4 + t], b2v = rce_b[1 * C4 + t];
#pragma unroll
        for (int cell = 0; cell < 16; cell++) f4[t * 16 + cell] = a4[cell] + b4;
#pragma unroll
        for (int cc = 0; cc < 4; cc++) f2[t * 4 + cc] = a2[cc] + b2v;
    }
    __syncthreads();

    {
        const int qc = t >> 4, cell = t & 15;
        float aq = 0.f, ak = 0.f;
        for (int o = 0; o < C4; o++) {
            const float fv = f4[o * 16 + cell];
            aq += qw[qc * C4 + o] * fv;
            ak += kw[qc * C4 + o] * fv;
        }
        qf4[t] = aq + qb[qc]; kf4[t] = ak + kb[qc];
    }
    if (t < 64) {
        const int qc = t >> 2, cc = t & 3;
        float aq = 0.f, ak = 0.f;
        for (int o = 0; o < C4; o++) {
            const float fv = f2[o * 4 + cc];
            aq += qw[qc * C4 + o] * fv;
            ak += kw[qc * C4 + o] * fv;
        }
        qf2[t] = aq + qb[qc]; kf2[t] = ak + kb[qc];
    }
    __syncthreads();

    const float st4 = 3.0f / 31.0f, st2 = 1.0f / 31.0f;
    for (int idx = t; idx < QKC * LLEN; idx += 256) {
        const int qc = idx >> 10, p = idx & 1023, r = p >> 5, cc = p & 31;
        float pr = r * st4;  int lr = (int)pr; lr = lr > 2 ? 2 : lr; float fr = pr - lr;
        float pc = cc * st4; int lc = (int)pc; lc = lc > 2 ? 2 : lc; float fc = pc - lc;
        const float w00 = (1.f - fr) * (1.f - fc), w01 = (1.f - fr) * fc;
        const float w10 = fr * (1.f - fc),         w11 = fr * fc;
        const float* q4 = &qf4[qc * 16]; const float* k4 = &kf4[qc * 16];
        g_qk[qk_idx(0, 1, b, qc, p)] =
            w00 * q4[lr * 4 + lc] + w01 * q4[lr * 4 + lc + 1] +
            w10 * q4[(lr + 1) * 4 + lc] + w11 * q4[(lr + 1) * 4 + lc + 1];
        g_qk[qk_idx(1, 1, b, qc, p)] =
            w00 * k4[lr * 4 + lc] + w01 * k4[lr * 4 + lc + 1] +
            w10 * k4[(lr + 1) * 4 + lc] + w11 * k4[(lr + 1) * 4 + lc + 1];
        const float fr2 = r * st2, fc2 = cc * st2;
        const float u00 = (1.f - fr2) * (1.f - fc2), u01 = (1.f - fr2) * fc2;
        const float u10 = fr2 * (1.f - fc2),          u11 = fr2 * fc2;
        const float* q2 = &qf2[qc * 4]; const float* k2 = &kf2[qc * 4];
        g_qk[qk_idx(0, 0, b, qc, p)] = u00 * q2[0] + u01 * q2[1] + u10 * q2[2] + u11 * q2[3];
        g_qk[qk_idx(1, 0, b, qc, p)] = u00 * k2[0] + u01 * k2[1] + u10 * k2[2] + u11 * k2[3];
    }
}

// ---------------- K3: sz=1 pyramid mean ----------------------------
__global__ void k_mean() {
    const int c = blockIdx.x, b = blockIdx.y, t = threadIdx.x;
    const float* v = &g_value[(b * C4 + c) * LLEN];
    float s = 0.f;
    for (int i = t; i < LLEN; i += 256) s += v[i];
    __shared__ float red[256];
    red[t] = s; __syncthreads();
    for (int o = 128; o > 0; o >>= 1) { if (t < o) red[t] += red[t + o]; __syncthreads(); }
    if (t == 0) g_mean[b * C4 + c] = red[0] * (1.f / LLEN);
}

// ---------------- K3b: border-pattern weight sums ----------------
__global__ void k_wsum(const float* __restrict__ fw) {
    const int co = blockIdx.x, ci = threadIdx.x;
    float w[9];
#pragma unroll
    for (int k = 0; k < 9; k++) w[k] = fw[co * 3456 + ci * 9 + k];
#pragma unroll
    for (int rt = 0; rt < 3; rt++) {
        const int kylo = (rt == 0) ? 1 : 0, kyhi = (rt == 2) ? 1 : 2;
#pragma unroll
        for (int ct = 0; ct < 3; ct++) {
            const int kxlo = (ct == 0) ? 1 : 0, kxhi = (ct == 2) ? 1 : 2;
            float s = 0.f;
            for (int ky = kylo; ky <= kyhi; ky++)
                for (int kx = kxlo; kx <= kxhi; kx++)
                    s += w[ky * 3 + kx];
            g_wsum[((rt * 3 + ct) * Cc + co) * C4 + ci] = s;
        }
    }
}

// ---------------- K3c: constant-channel conv contribution ----------------
__global__ void k_const() {
    __shared__ float sm[C4];
    const int b = blockIdx.x, co = threadIdx.x;
    if (co < C4) sm[co] = g_mean[b * C4 + co];
    __syncthreads();
#pragma unroll
    for (int pat = 0; pat < 9; pat++) {
        const float* ws = &g_wsum[(pat * Cc + co) * C4];
        float s = 0.f;
        for (int ci = 0; ci < C4; ci++) s += sm[ci] * ws[ci];
        g_contrib[(b * 9 + pat) * Cc + co] = s;
    }
}

// ---------------- K3d: weight fp16, reordered [co][tap*256+cc] -----------------
__global__ void k_wsplit(const float* __restrict__ fw) {
    const int idx = blockIdx.x * 256 + threadIdx.x;   // 512*2304
    const int co = idx / CONVK, k = idx % CONVK;
    const int tap = k >> 8, cc = k & 255;
    g_wh[idx] = __float2half(fw[co * 3456 + 1152 + cc * 9 + tap]);
}

// ---------------- K4: energy + softmax -> attn probabilities (fp16 out) --------
__global__ void __launch_bounds__(256) k_attn() {
    extern __shared__ float ks[];
    const int b = blockIdx.z, pyr = blockIdx.y;
    const int mbase = blockIdx.x * 128;
    const int t = threadIdx.x, w = t >> 5, lane = t & 31;
    const float* gq = &g_qk[qk_idx(0, pyr, b, 0, 0)];
    const float* gk = &g_qk[qk_idx(1, pyr, b, 0, 0)];
    for (int idx = t; idx < QKC * LLEN; idx += 256) {
        const int qc = idx >> 10, l = idx & 1023;
        ks[l * 20 + qc] = gk[qc * LLEN + l];
    }
    __syncthreads();
    __half* pb = &g_attnh[(size_t)(pyr * Nn + b) * LLEN * LLEN];

    for (int pr = 0; pr < 16; pr++) {
        const int m = mbase + pr * 8 + w;
        float q[16];
#pragma unroll
        for (int j = 0; j < 16; j++) q[j] = gq[j * LLEN + m];
        float e[32];
        float mx = -1e30f;
#pragma unroll
        for (int i = 0; i < 32; i++) {
            const int l = i * 32 + lane;
            const float4* kp = (const float4*)&ks[l * 20];
            const float4 k0 = kp[0], k1 = kp[1], k2 = kp[2], k3 = kp[3];
            float s = q[0]*k0.x + q[1]*k0.y + q[2]*k0.z + q[3]*k0.w
                    + q[4]*k1.x + q[5]*k1.y + q[6]*k1.z + q[7]*k1.w
                    + q[8]*k2.x + q[9]*k2.y + q[10]*k2.z + q[11]*k2.w
                    + q[12]*k3.x + q[13]*k3.y + q[14]*k3.z + q[15]*k3.w;
            e[i] = s;
            mx = fmaxf(mx, s);
        }
#pragma unroll
        for (int o = 16; o > 0; o >>= 1)
            mx = fmaxf(mx, __shfl_xor_sync(0xffffffffu, mx, o));
        float sm = 0.f;
#pragma unroll
        for (int i = 0; i < 32; i++) { e[i] = __expf(e[i] - mx); sm += e[i]; }
#pragma unroll
        for (int o = 16; o > 0; o >>= 1)
            sm += __shfl_xor_sync(0xffffffffu, sm, o);
        const float inv = 1.f / sm;
        __half* pa = &pb[(size_t)m * LLEN];
#pragma unroll
        for (int i = 0; i < 32; i++)
            pa[i * 32 + lane] = __float2half(e[i] * inv);
    }
}

// ---------------- K5: HMMA out-GEMM: catT[pix][c] = sum_l V[c][l]*P[pix][l] ----
#define BUFO 32768
__global__ void __launch_bounds__(512) k_outgemm_mma() {
    extern __shared__ char dsm[];
    const uint32_t sbase = smem_u32(dsm);
    const uint32_t offA = 0, offB = 16384;

    const int z = blockIdx.z; const int b = z >> 1; const int pyr = z & 1;
    const int pix0 = blockIdx.x * 128;
    const int t = threadIdx.x;
    const int wid = t >> 5, lane = t & 31;
    const int wm = wid >> 2, wn = wid & 3;

    const __half* __restrict__ vh = g_vh + (size_t)b * C4 * LLEN;
    const __half* __restrict__ P  = g_attnh + (size_t)(pyr * Nn + b) * LLEN * LLEN;

    float acc[2][4][4] = {};

    const int aRow = wm * 32 + (lane & 15);
    const int aColHalf = (lane & 16) ? 16 : 0;
    const int bRow = wn * 32 + (lane & 7);
    const int bColHalf = (lane & 8) ? 16 : 0;

    auto stage_load = [&](int s, uint32_t bufOff) {
        const int l0 = s * 64;
        for (int idx = t; idx < 1024; idx += 512) {
            const int r = idx >> 3, ch = idx & 7;
            const uint32_t sw = swz((uint32_t)(r * 128 + ch * 16));
            const int goff = ch * 8;
            cp16(sbase + bufOff + offA + sw, vh + (size_t)r * LLEN + l0 + goff, true);
            cp16(sbase + bufOff + offB + sw, P + (size_t)(pix0 + r) * LLEN + l0 + goff, true);
        }
        cp_commit();
    };

    stage_load(0, 0);

    for (int s = 0; s < 16; s++) {
        const uint32_t bufOff = (uint32_t)(s & 1) * BUFO;
        if (s < 15) {
            stage_load(s + 1, (uint32_t)((s + 1) & 1) * BUFO);
            asm volatile("cp.async.wait_group 1;" ::: "memory");
        } else {
            asm volatile("cp.async.wait_group 0;" ::: "memory");
        }
        __syncthreads();

#pragma unroll
        for (int kk = 0; kk < 4; kk++) {
            uint32_t Af[2][4], Bf[4][2];
#pragma unroll
            for (int mt = 0; mt < 2; mt++) {
                const uint32_t boff = swz((uint32_t)((aRow + mt * 16) * 128 + kk * 32 + aColHalf));
                ldsm_x4(Af[mt][0], Af[mt][1], Af[mt][2], Af[mt][3], sbase + bufOff + offA + boff);
            }
#pragma unroll
            for (int nt = 0; nt < 4; nt++) {
                const uint32_t boff = swz((uint32_t)((bRow + nt * 8) * 128 + kk * 32 + bColHalf));
                ldsm_x2(Bf[nt][0], Bf[nt][1], sbase + bufOff + offB + boff);
            }
#pragma unroll
            for (int mt = 0; mt < 2; mt++)
#pragma unroll
                for (int nt = 0; nt < 4; nt++)
                    mma_f16(acc[mt][nt], Af[mt], Bf[nt]);
        }
        __syncthreads();
    }

    // epilogue: smem transpose [pixLocal][c] (pitch 136), then coalesced fp16 store
    __half* eb = (__half*)dsm;
    const int cBase = wm * 32 + (lane >> 2);
    const int pBase = wn * 32 + (lane & 3) * 2;
#pragma unroll
    for (int mt = 0; mt < 2; mt++)
#pragma unroll
        for (int half = 0; half < 2; half++) {
            const int c = cBase + mt * 16 + half * 8;
#pragma unroll
            for (int nt = 0; nt < 4; nt++)
#pragma unroll
                for (int e = 0; e < 2; e++) {
                    const int p = pBase + nt * 8 + e;
                    eb[p * 136 + c] = __float2half(acc[mt][nt][half * 2 + e]);
                }
        }
    __syncthreads();
    for (int idx = t; idx < 128 * 16; idx += 512) {
        const int row = idx >> 4, ch = idx & 15;
        const uint4 v = *(const uint4*)&eb[row * 136 + ch * 8];
        *(uint4*)&g_cth[((size_t)(b * LLEN + pix0 + row)) * 256 + pyr * C4 + ch * 8] = v;
    }
}

// ---------------- K6: fusion conv as fp16 HMMA GEMM (cp.async 2-buf) -----------
#define BUFB 32768
__global__ void __launch_bounds__(512) k_conv_mma() {
    extern __shared__ char dsm[];
    const uint32_t sbase = smem_u32(dsm);
    const uint32_t offA = 0, offB = 16384;

    const int b = blockIdx.z;
    const int co0 = blockIdx.y * 128;
    const int pix0 = blockIdx.x * 128;
    const int t = threadIdx.x;
    const int wid = t >> 5, lane = t & 31;
    const int wm = wid >> 2, wn = wid & 3;

    const __half* __restrict__ wh = g_wh;
    const __half* __restrict__ cth = g_cth + (size_t)b * LLEN * 256;

    float acc[2][4][4] = {};

    const int aRow = wm * 32 + (lane & 15);
    const int aColHalf = (lane & 16) ? 16 : 0;
    const int bRow = wn * 32 + (lane & 7);
    const int bColHalf = (lane & 8) ? 16 : 0;

    auto stage_load = [&](int s, uint32_t bufOff) {
        const int tap = s >> 2;
        const int ky = tap / 3, kx = tap - ky * 3;
        const int ci0 = (s & 3) * 64;
        const int kA = s * 64;
        for (int idx = t; idx < 1024; idx += 512) {
            const int r = idx >> 3, ch = idx & 7;
            const uint32_t sw = swz((uint32_t)(r * 128 + ch * 16));
            const int goff = ch * 8;
            cp16(sbase + bufOff + offA + sw, wh + (size_t)(co0 + r) * CONVK + kA + goff, true);
            const int gp = pix0 + r;
            const int sy = (gp >> 5) + ky - 1, sx = (gp & 31) + kx - 1;
            const bool ok = (sy >= 0 && sy < 32 && sx >= 0 && sx < 32);
            const __half* src = ok ? (cth + ((size_t)(sy * 32 + sx)) * 256 + ci0 + goff) : cth;
            cp16(sbase + bufOff + offB + sw, src, ok);
        }
        cp_commit();
    };

    stage_load(0, 0);

    for (int s = 0; s < 36; s++) {
        const uint32_t bufOff = (uint32_t)(s & 1) * BUFB;
        if (s < 35) {
            stage_load(s + 1, (uint32_t)((s + 1) & 1) * BUFB);
            asm volatile("cp.async.wait_group 1;" ::: "memory");
        } else {
            asm volatile("cp.async.wait_group 0;" ::: "memory");
        }
        __syncthreads();

#pragma unroll
        for (int kk = 0; kk < 4; kk++) {
            uint32_t Af[2][4], Bf[4][2];
#pragma unroll
            for (int mt = 0; mt < 2; mt++) {
                const uint32_t boff = swz((uint32_t)((aRow + mt * 16) * 128 + kk * 32 + aColHalf));
                ldsm_x4(Af[mt][0], Af[mt][1], Af[mt][2], Af[mt][3], sbase + bufOff + offA + boff);
            }
#pragma unroll
            for (int nt = 0; nt < 4; nt++) {
                const uint32_t boff = swz((uint32_t)((bRow + nt * 8) * 128 + kk * 32 + bColHalf));
                ldsm_x2(Bf[nt][0], Bf[nt][1], sbase + bufOff + offB + boff);
            }
#pragma unroll
            for (int mt = 0; mt < 2; mt++)
#pragma unroll
                for (int nt = 0; nt < 4; nt++)
                    mma_f16(acc[mt][nt], Af[mt], Bf[nt]);
        }
        __syncthreads();
    }

    const float* cbp = &g_contrib[(size_t)b * 9 * Cc];
    const int mBase = co0 + wm * 32 + (lane >> 2);
    const int nBase = pix0 + wn * 32 + (lane & 3) * 2;
#pragma unroll
    for (int mt = 0; mt < 2; mt++) {
#pragma unroll
        for (int half = 0; half < 2; half++) {
            const int co = mBase + mt * 16 + half * 8;
            float* yrow = &g_y[((size_t)b * Cc + co) * LLEN];
#pragma unroll
            for (int nt = 0; nt < 4; nt++) {
#pragma unroll
                for (int e = 0; e < 2; e++) {
                    const int gp = nBase + nt * 8 + e;
                    const int y = gp >> 5, xg = gp & 31;
                    const int rt = (y == 0) ? 0 : ((y == 31) ? 2 : 1);
                    const int ct = (xg == 0) ? 0 : ((xg == 31) ? 2 : 1);
                    const float cc = cbp[(rt * 3 + ct) * Cc + co];
                    yrow[gp] = acc[mt][nt][half * 2 + e] + cc;
                }
            }
        }
    }
}

// ---------------- K7: BN batch statistics -------------------------------------
__global__ void k_stats(const float* __restrict__ bn_scale) {
    const int c = blockIdx.x, t = threadIdx.x;
    double s = 0.0, ss = 0.0;
    for (int idx = t; idx < Nn * LLEN; idx += 256) {
        const int bb = idx >> 10, l = idx & 1023;
        const float v = g_y[((size_t)bb * Cc + c) * LLEN + l];
        s += v; ss += (double)v * v;
    }
    __shared__ double rs[256], rq[256];
    rs[t] = s; rq[t] = ss; __syncthreads();
    for (int o = 128; o > 0; o >>= 1) {
        if (t < o) { rs[t] += rs[t + o]; rq[t] += rq[t + o]; }
        __syncthreads();
    }
    if (t == 0) {
        const double mean = rs[0] / (double)(Nn * LLEN);
        const double var  = rq[0] / (double)(Nn * LLEN) - mean * mean;
        g_stats[c * 2]     = (float)mean;
        g_stats[c * 2 + 1] = bn_scale[c] * rsqrtf((float)var + EPSf);
    }
}

// ---------------- K8: BN apply + ReLU + gamma*y + x ----------------------------
__global__ void k_final(const float* __restrict__ x, const float* __restrict__ bn_bias,
                        const float* __restrict__ gamma, float* __restrict__ out) {
    const int idx = blockIdx.x * 256 + threadIdx.x;
    const float g = gamma[0];
    const int c = (idx >> 10) & (Cc - 1);
    const float v = g_y[idx];
    float tt = (v - g_stats[c * 2]) * g_stats[c * 2 + 1] + bn_bias[c];
    tt = fmaxf(tt, 0.f);
    out[idx] = g * tt + x[idx];
}

// ---------------- launch ------------------------------------------------------
extern "C" void kernel_launch(void* const* d_in, const int* in_sizes, int n_in,
                              void* d_out, int out_size) {
    (void)in_sizes; (void)n_in; (void)out_size;
    const float* x        = (const float*)d_in[0];
    const float* rce_w    = (const float*)d_in[1];
    const float* rce_b    = (const float*)d_in[2];
    const float* q_w      = (const float*)d_in[3];
    const float* q_b      = (const float*)d_in[4];
    const float* k_w      = (const float*)d_in[5];
    const float* k_b      = (const float*)d_in[6];
    const float* value_w  = (const float*)d_in[7];
    const float* value_b  = (const float*)d_in[8];
    const float* fusion_w = (const float*)d_in[9];
    const float* bn_scale = (const float*)d_in[10];
    const float* bn_bias  = (const float*)d_in[11];
    const float* gamma    = (const float*)d_in[12];
    float* out = (float*)d_out;

    cudaFuncSetAttribute(k_attn, cudaFuncAttributeMaxDynamicSharedMemorySize, 81920);
    cudaFuncSetAttribute(k_conv_mma, cudaFuncAttributeMaxDynamicSharedMemorySize, 65536);
    cudaFuncSetAttribute(k_outgemm_mma, cudaFuncAttributeMaxDynamicSharedMemorySize, 65536);

    k_value_proj<<<dim3(16, 2, 16), 256>>>(x, value_w, value_b);
    k_prep<<<16, 256>>>(x, rce_w, rce_b, q_w, q_b, k_w, k_b);
    k_mean<<<dim3(128, 16), 256>>>();
    k_wsum<<<512, 128>>>(fusion_w);
    k_const<<<16, 512>>>();
    k_wsplit<<<4608, 256>>>(fusion_w);
    k_attn<<<dim3(8, 2, 16), 256, 81920>>>();
    k_outgemm_mma<<<dim3(8, 1, 32), 512, 65536>>>();
    k_conv_mma<<<dim3(8, 4, 16), 512, 65536>>>();
    k_stats<<<512, 256>>>(bn_scale);
    k_final<<<32768, 256>>>(x, bn_bias, gamma, out);
}

// round 10
// speedup vs baseline: 1.9733x; 1.0313x over previous
#include <cuda_runtime.h>
#include <cuda_bf16.h>
#include <cuda_fp16.h>
#include <cstdint>
#include <stdint.h>
#include <math.h>

#define Nn 16
#define Cc 512
#define C4 128
#define QKC 16
#define LLEN 1024
#define EPSf 1e-5f
#define CONVK 2304          // 9 taps * 256 attn channels

// ---------------- scratch (device globals; no allocation allowed) ----------------
__device__ float g_value[Nn * C4 * LLEN];                 // proj_value fp32
__device__ float g_qk[2 * 2 * Nn * QKC * LLEN];           // [q/k][pyr][b][qc][l]
__device__ __half g_attnh[(size_t)2 * Nn * LLEN * LLEN];  // [pyr][b][m][l] probs fp16
__device__ float g_y[Nn * Cc * LLEN];                     // conv output pre-BN
__device__ float g_stats[Cc * 2];
__device__ float g_mean[Nn * C4];
__device__ float g_wsum[9 * Cc * C4];
__device__ float g_contrib[Nn * 9 * Cc];
__device__ __half g_wh[Cc * CONVK];                       // weight fp16 [co][tap*256+cc]
__device__ __half g_vh[Nn * C4 * LLEN];                   // V fp16 [b][c][l]
__device__ __half g_cth[(size_t)Nn * LLEN * 256];         // feat fp16 [b][pix][cc]

__device__ __forceinline__ int qk_idx(int g, int py, int b, int qc, int l) {
    return (((g * 2 + py) * Nn + b) * QKC + qc) * LLEN + l;
}

// ---------------- PTX helpers (legacy tensor path, sm_80+) ----------------
__device__ __forceinline__ uint32_t smem_u32(const void* p) {
    uint32_t a;
    asm("{ .reg .u64 t; cvta.to.shared.u64 t, %1; cvt.u32.u64 %0, t; }" : "=r"(a) : "l"(p));
    return a;
}
__device__ __forceinline__ void ldsm_x4(uint32_t& r0, uint32_t& r1, uint32_t& r2, uint32_t& r3,
                                        uint32_t addr) {
    asm volatile("ldmatrix.sync.aligned.m8n8.x4.shared.b16 {%0,%1,%2,%3}, [%4];"
                 : "=r"(r0), "=r"(r1), "=r"(r2), "=r"(r3) : "r"(addr));
}
__device__ __forceinline__ void ldsm_x2(uint32_t& r0, uint32_t& r1, uint32_t addr) {
    asm volatile("ldmatrix.sync.aligned.m8n8.x2.shared.b16 {%0,%1}, [%2];"
                 : "=r"(r0), "=r"(r1) : "r"(addr));
}
__device__ __forceinline__ void mma_f16(float* c, const uint32_t* a, const uint32_t* b) {
    asm volatile(
        "mma.sync.aligned.m16n8k16.row.col.f32.f16.f16.f32 "
        "{%0,%1,%2,%3}, {%4,%5,%6,%7}, {%8,%9}, {%0,%1,%2,%3};"
        : "+f"(c[0]), "+f"(c[1]), "+f"(c[2]), "+f"(c[3])
        : "r"(a[0]), "r"(a[1]), "r"(a[2]), "r"(a[3]), "r"(b[0]), "r"(b[1]));
}
__device__ __forceinline__ uint32_t swz(uint32_t boff) {
    return boff ^ ((boff >> 3) & 0x70);
}
__device__ __forceinline__ void cp16(uint32_t dst, const void* src, bool pred) {
    const int sz = pred ? 16 : 0;
    asm volatile("cp.async.cg.shared.global [%0], [%1], 16, %2;"
                 :: "r"(dst), "l"(src), "r"(sz) : "memory");
}
__device__ __forceinline__ void cp_commit() {
    asm volatile("cp.async.commit_group;" ::: "memory");
}
// FMA-pipe exp: e^x with x<=0; degree-5 Taylor of 2^f on [-0.5,0.5] + exponent add.
// Relative error ~2e-6 — far below the fp16 prob storage rounding.
__device__ __forceinline__ float fexp(float x) {
    float y = fmaxf(x * 1.44269504f, -80.f);
    float r = rintf(y);
    float f = y - r;
    float p = 1.3333558e-3f;
    p = fmaf(p, f, 9.6181291e-3f);
    p = fmaf(p, f, 5.5504109e-2f);
    p = fmaf(p, f, 2.4022651e-1f);
    p = fmaf(p, f, 6.9314718e-1f);
    p = fmaf(p, f, 1.0f);
    return __int_as_float(__float_as_int(p) + (((int)r) << 23));
}

// ---------------- K1: value projection GEMM (also emits fp16 V) ----
__global__ void k_value_proj(const float* __restrict__ x,
                             const float* __restrict__ w,
                             const float* __restrict__ bias) {
    __shared__ float As[32 * 68];
    __shared__ float Bs[32 * 68];
    const int b  = blockIdx.z;
    const int m0 = blockIdx.y * 64;
    const int n0 = blockIdx.x * 64;
    const float* xb = x + b * Cc * LLEN;
    const int t  = threadIdx.x;
    const int ty = t >> 4, tx = t & 15;
    const int am = t >> 2, akq = (t & 3) * 8;
    const int bk = t >> 3, bnq = (t & 7) * 8;
    float acc[4][4] = {};

    for (int kc = 0; kc < Cc / 32; kc++) {
        const int k0 = kc * 32;
        __syncthreads();
        float4 a0 = *(const float4*)&w[(m0 + am) * Cc + k0 + akq];
        float4 a1 = *(const float4*)&w[(m0 + am) * Cc + k0 + akq + 4];
        As[(akq + 0) * 68 + am] = a0.x; As[(akq + 1) * 68 + am] = a0.y;
        As[(akq + 2) * 68 + am] = a0.z; As[(akq + 3) * 68 + am] = a0.w;
        As[(akq + 4) * 68 + am] = a1.x; As[(akq + 5) * 68 + am] = a1.y;
        As[(akq + 6) * 68 + am] = a1.z; As[(akq + 7) * 68 + am] = a1.w;
        float4 b0 = *(const float4*)&xb[(k0 + bk) * LLEN + n0 + bnq];
        float4 b1 = *(const float4*)&xb[(k0 + bk) * LLEN + n0 + bnq + 4];
        *(float4*)&Bs[bk * 68 + bnq]     = b0;
        *(float4*)&Bs[bk * 68 + bnq + 4] = b1;
        __syncthreads();
#pragma unroll
        for (int k = 0; k < 32; k++) {
            float4 av = *(const float4*)&As[k * 68 + ty * 4];
            float4 bv = *(const float4*)&Bs[k * 68 + tx * 4];
            acc[0][0] += av.x * bv.x; acc[0][1] += av.x * bv.y; acc[0][2] += av.x * bv.z; acc[0][3] += av.x * bv.w;
            acc[1][0] += av.y * bv.x; acc[1][1] += av.y * bv.y; acc[1][2] += av.y * bv.z; acc[1][3] += av.y * bv.w;
            acc[2][0] += av.z * bv.x; acc[2][1] += av.z * bv.y; acc[2][2] += av.z * bv.z; acc[2][3] += av.z * bv.w;
            acc[3][0] += av.w * bv.x; acc[3][1] += av.w * bv.y; acc[3][2] += av.w * bv.z; acc[3][3] += av.w * bv.w;
        }
    }
#pragma unroll
    for (int i = 0; i < 4; i++) {
        const int c = m0 + ty * 4 + i;
        const float bs = bias[c];
        float4 o;
        o.x = acc[i][0] + bs; o.y = acc[i][1] + bs; o.z = acc[i][2] + bs; o.w = acc[i][3] + bs;
        const size_t off = (size_t)(b * C4 + c) * LLEN + n0 + tx * 4;
        *(float4*)&g_value[off] = o;
        __half h[4] = {__float2half(o.x), __float2half(o.y), __float2half(o.z), __float2half(o.w)};
        *(uint2*)&g_vh[off] = *(const uint2*)h;
    }
}

// ---------------- K2: pooling + rce + q/k feats + bilinear upsample -------------
__global__ void k_prep(const float* __restrict__ x,
                       const float* __restrict__ rce_w, const float* __restrict__ rce_b,
                       const float* __restrict__ qw, const float* __restrict__ qb,
                       const float* __restrict__ kw, const float* __restrict__ kb) {
    __shared__ float sp4[Cc * 16];
    __shared__ float f4[C4 * 16];
    __shared__ float f2[C4 * 4];
    __shared__ float qf4[QKC * 16], kf4[QKC * 16];
    __shared__ float qf2[QKC * 4],  kf2[QKC * 4];
    const int b = blockIdx.x, t = threadIdx.x;
    const float* xb = x + b * Cc * LLEN;

    for (int idx = t; idx < Cc * 16; idx += 256) {
        int c = idx >> 4, cell = idx & 15, i = cell >> 2, j = cell & 3;
        float s = 0.f;
        for (int y = 0; y < 8; y++)
#pragma unroll
            for (int xx = 0; xx < 8; xx++)
                s += xb[c * LLEN + (i * 8 + y) * 32 + j * 8 + xx];
        sp4[idx] = s * (1.f / 64.f);
    }
    __syncthreads();

    if (t < C4) {
        float a4[16] = {}, a2[4] = {};
        for (int c = 0; c < Cc; c++) {
            const float w4 = rce_w[(2 * C4 + t) * Cc + c];
            const float w2 = rce_w[(1 * C4 + t) * Cc + c];
            const float* p = &sp4[c * 16];
#pragma unroll
            for (int cell = 0; cell < 16; cell++) a4[cell] += w4 * p[cell];
#pragma unroll
            for (int i = 0; i < 2; i++)
#pragma unroll
                for (int j = 0; j < 2; j++)
                    a2[i * 2 + j] += w2 * 0.25f *
                        (p[(2 * i) * 4 + 2 * j] + p[(2 * i) * 4 + 2 * j + 1] +
                         p[(2 * i + 1) * 4 + 2 * j] + p[(2 * i + 1) * 4 + 2 * j + 1]);
        }
        const float b4 = rce_b[2 * C4 + t], b2v = rce_b[1 * C4 + t];
#pragma unroll
        for (int cell = 0; cell < 16; cell++) f4[t * 16 + cell] = a4[cell] + b4;
#pragma unroll
        for (int cc = 0; cc < 4; cc++) f2[t * 4 + cc] = a2[cc] + b2v;
    }
    __syncthreads();

    {
        const int qc = t >> 4, cell = t & 15;
        float aq = 0.f, ak = 0.f;
        for (int o = 0; o < C4; o++) {
            const float fv = f4[o * 16 + cell];
            aq += qw[qc * C4 + o] * fv;
            ak += kw[qc * C4 + o] * fv;
        }
        qf4[t] = aq + qb[qc]; kf4[t] = ak + kb[qc];
    }
    if (t < 64) {
        const int qc = t >> 2, cc = t & 3;
        float aq = 0.f, ak = 0.f;
        for (int o = 0; o < C4; o++) {
            const float fv = f2[o * 4 + cc];
            aq += qw[qc * C4 + o] * fv;
            ak += kw[qc * C4 + o] * fv;
        }
        qf2[t] = aq + qb[qc]; kf2[t] = ak + kb[qc];
    }
    __syncthreads();

    const float st4 = 3.0f / 31.0f, st2 = 1.0f / 31.0f;
    for (int idx = t; idx < QKC * LLEN; idx += 256) {
        const int qc = idx >> 10, p = idx & 1023, r = p >> 5, cc = p & 31;
        float pr = r * st4;  int lr = (int)pr; lr = lr > 2 ? 2 : lr; float fr = pr - lr;
        float pc = cc * st4; int lc = (int)pc; lc = lc > 2 ? 2 : lc; float fc = pc - lc;
        const float w00 = (1.f - fr) * (1.f - fc), w01 = (1.f - fr) * fc;
        const float w10 = fr * (1.f - fc),         w11 = fr * fc;
        const float* q4 = &qf4[qc * 16]; const float* k4 = &kf4[qc * 16];
        g_qk[qk_idx(0, 1, b, qc, p)] =
            w00 * q4[lr * 4 + lc] + w01 * q4[lr * 4 + lc + 1] +
            w10 * q4[(lr + 1) * 4 + lc] + w11 * q4[(lr + 1) * 4 + lc + 1];
        g_qk[qk_idx(1, 1, b, qc, p)] =
            w00 * k4[lr * 4 + lc] + w01 * k4[lr * 4 + lc + 1] +
            w10 * k4[(lr + 1) * 4 + lc] + w11 * k4[(lr + 1) * 4 + lc + 1];
        const float fr2 = r * st2, fc2 = cc * st2;
        const float u00 = (1.f - fr2) * (1.f - fc2), u01 = (1.f - fr2) * fc2;
        const float u10 = fr2 * (1.f - fc2),          u11 = fr2 * fc2;
        const float* q2 = &qf2[qc * 4]; const float* k2 = &kf2[qc * 4];
        g_qk[qk_idx(0, 0, b, qc, p)] = u00 * q2[0] + u01 * q2[1] + u10 * q2[2] + u11 * q2[3];
        g_qk[qk_idx(1, 0, b, qc, p)] = u00 * k2[0] + u01 * k2[1] + u10 * k2[2] + u11 * k2[3];
    }
}

// ---------------- K3: sz=1 pyramid mean ----------------------------
__global__ void k_mean() {
    const int c = blockIdx.x, b = blockIdx.y, t = threadIdx.x;
    const float* v = &g_value[(b * C4 + c) * LLEN];
    float s = 0.f;
    for (int i = t; i < LLEN; i += 256) s += v[i];
    __shared__ float red[256];
    red[t] = s; __syncthreads();
    for (int o = 128; o > 0; o >>= 1) { if (t < o) red[t] += red[t + o]; __syncthreads(); }
    if (t == 0) g_mean[b * C4 + c] = red[0] * (1.f / LLEN);
}

// ---------------- K3b: border-pattern weight sums ----------------
__global__ void k_wsum(const float* __restrict__ fw) {
    const int co = blockIdx.x, ci = threadIdx.x;
    float w[9];
#pragma unroll
    for (int k = 0; k < 9; k++) w[k] = fw[co * 3456 + ci * 9 + k];
#pragma unroll
    for (int rt = 0; rt < 3; rt++) {
        const int kylo = (rt == 0) ? 1 : 0, kyhi = (rt == 2) ? 1 : 2;
#pragma unroll
        for (int ct = 0; ct < 3; ct++) {
            const int kxlo = (ct == 0) ? 1 : 0, kxhi = (ct == 2) ? 1 : 2;
            float s = 0.f;
            for (int ky = kylo; ky <= kyhi; ky++)
                for (int kx = kxlo; kx <= kxhi; kx++)
                    s += w[ky * 3 + kx];
            g_wsum[((rt * 3 + ct) * Cc + co) * C4 + ci] = s;
        }
    }
}

// ---------------- K3c: constant-channel conv contribution ----------------
__global__ void k_const() {
    __shared__ float sm[C4];
    const int b = blockIdx.x, co = threadIdx.x;
    if (co < C4) sm[co] = g_mean[b * C4 + co];
    __syncthreads();
#pragma unroll
    for (int pat = 0; pat < 9; pat++) {
        const float* ws = &g_wsum[(pat * Cc + co) * C4];
        float s = 0.f;
        for (int ci = 0; ci < C4; ci++) s += sm[ci] * ws[ci];
        g_contrib[(b * 9 + pat) * Cc + co] = s;
    }
}

// ---------------- K3d: weight fp16, reordered [co][tap*256+cc] -----------------
__global__ void k_wsplit(const float* __restrict__ fw) {
    const int idx = blockIdx.x * 256 + threadIdx.x;   // 512*2304
    const int co = idx / CONVK, k = idx % CONVK;
    const int tap = k >> 8, cc = k & 255;
    g_wh[idx] = __float2half(fw[co * 3456 + 1152 + cc * 9 + tap]);
}

// ---------------- K4: energy + softmax -> attn probabilities (fp16 out) --------
__global__ void __launch_bounds__(256, 2) k_attn() {
    extern __shared__ float ks[];
    const int b = blockIdx.z, pyr = blockIdx.y;
    const int mbase = blockIdx.x * 128;
    const int t = threadIdx.x, w = t >> 5, lane = t & 31;
    const float* gq = &g_qk[qk_idx(0, pyr, b, 0, 0)];
    const float* gk = &g_qk[qk_idx(1, pyr, b, 0, 0)];
    for (int idx = t; idx < QKC * LLEN; idx += 256) {
        const int qc = idx >> 10, l = idx & 1023;
        ks[l * 20 + qc] = gk[qc * LLEN + l];
    }
    __syncthreads();
    __half* pb = &g_attnh[(size_t)(pyr * Nn + b) * LLEN * LLEN];

    for (int pr = 0; pr < 16; pr++) {
        const int m = mbase + pr * 8 + w;
        float q[16];
#pragma unroll
        for (int j = 0; j < 16; j++) q[j] = gq[j * LLEN + m];
        float e[32];
        float mx = -1e30f;
#pragma unroll
        for (int i = 0; i < 32; i++) {
            const int l = i * 32 + lane;
            const float4* kp = (const float4*)&ks[l * 20];
            const float4 k0 = kp[0], k1 = kp[1], k2 = kp[2], k3 = kp[3];
            float s = q[0]*k0.x + q[1]*k0.y + q[2]*k0.z + q[3]*k0.w
                    + q[4]*k1.x + q[5]*k1.y + q[6]*k1.z + q[7]*k1.w
                    + q[8]*k2.x + q[9]*k2.y + q[10]*k2.z + q[11]*k2.w
                    + q[12]*k3.x + q[13]*k3.y + q[14]*k3.z + q[15]*k3.w;
            e[i] = s;
            mx = fmaxf(mx, s);
        }
#pragma unroll
        for (int o = 16; o > 0; o >>= 1)
            mx = fmaxf(mx, __shfl_xor_sync(0xffffffffu, mx, o));
        float sm = 0.f;
#pragma unroll
        for (int i = 0; i < 32; i++) { e[i] = fexp(e[i] - mx); sm += e[i]; }
#pragma unroll
        for (int o = 16; o > 0; o >>= 1)
            sm += __shfl_xor_sync(0xffffffffu, sm, o);
        const float inv = 1.f / sm;
        __half* pa = &pb[(size_t)m * LLEN];
#pragma unroll
        for (int i = 0; i < 32; i++)
            pa[i * 32 + lane] = __float2half(e[i] * inv);
    }
}

// ---------------- K5: HMMA out-GEMM: catT[pix][c] = sum_l V[c][l]*P[pix][l] ----
#define BUFO 32768
__global__ void __launch_bounds__(512) k_outgemm_mma() {
    extern __shared__ char dsm[];
    const uint32_t sbase = smem_u32(dsm);
    const uint32_t offA = 0, offB = 16384;

    const int z = blockIdx.z; const int b = z >> 1; const int pyr = z & 1;
    const int pix0 = blockIdx.x * 128;
    const int t = threadIdx.x;
    const int wid = t >> 5, lane = t & 31;
    const int wm = wid >> 2, wn = wid & 3;

    const __half* __restrict__ vh = g_vh + (size_t)b * C4 * LLEN;
    const __half* __restrict__ P  = g_attnh + (size_t)(pyr * Nn + b) * LLEN * LLEN;

    float acc[2][4][4] = {};

    const int aRow = wm * 32 + (lane & 15);
    const int aColHalf = (lane & 16) ? 16 : 0;
    const int bRow = wn * 32 + (lane & 7);
    const int bColHalf = (lane & 8) ? 16 : 0;

    auto stage_load = [&](int s, uint32_t bufOff) {
        const int l0 = s * 64;
        for (int idx = t; idx < 1024; idx += 512) {
            const int r = idx >> 3, ch = idx & 7;
            const uint32_t sw = swz((uint32_t)(r * 128 + ch * 16));
            const int goff = ch * 8;
            cp16(sbase + bufOff + offA + sw, vh + (size_t)r * LLEN + l0 + goff, true);
            cp16(sbase + bufOff + offB + sw, P + (size_t)(pix0 + r) * LLEN + l0 + goff, true);
        }
        cp_commit();
    };

    stage_load(0, 0);

    for (int s = 0; s < 16; s++) {
        const uint32_t bufOff = (uint32_t)(s & 1) * BUFO;
        if (s < 15) {
            stage_load(s + 1, (uint32_t)((s + 1) & 1) * BUFO);
            asm volatile("cp.async.wait_group 1;" ::: "memory");
        } else {
            asm volatile("cp.async.wait_group 0;" ::: "memory");
        }
        __syncthreads();

#pragma unroll
        for (int kk = 0; kk < 4; kk++) {
            uint32_t Af[2][4], Bf[4][2];
#pragma unroll
            for (int mt = 0; mt < 2; mt++) {
                const uint32_t boff = swz((uint32_t)((aRow + mt * 16) * 128 + kk * 32 + aColHalf));
                ldsm_x4(Af[mt][0], Af[mt][1], Af[mt][2], Af[mt][3], sbase + bufOff + offA + boff);
            }
#pragma unroll
            for (int nt = 0; nt < 4; nt++) {
                const uint32_t boff = swz((uint32_t)((bRow + nt * 8) * 128 + kk * 32 + bColHalf));
                ldsm_x2(Bf[nt][0], Bf[nt][1], sbase + bufOff + offB + boff);
            }
#pragma unroll
            for (int mt = 0; mt < 2; mt++)
#pragma unroll
                for (int nt = 0; nt < 4; nt++)
                    mma_f16(acc[mt][nt], Af[mt], Bf[nt]);
        }
        __syncthreads();
    }

    // epilogue: smem transpose [pixLocal][c] (pitch 136), then coalesced fp16 store
    __half* eb = (__half*)dsm;
    const int cBase = wm * 32 + (lane >> 2);
    const int pBase = wn * 32 + (lane & 3) * 2;
#pragma unroll
    for (int mt = 0; mt < 2; mt++)
#pragma unroll
        for (int half = 0; half < 2; half++) {
            const int c = cBase + mt * 16 + half * 8;
#pragma unroll
            for (int nt = 0; nt < 4; nt++)
#pragma unroll
                for (int e = 0; e < 2; e++) {
                    const int p = pBase + nt * 8 + e;
                    eb[p * 136 + c] = __float2half(acc[mt][nt][half * 2 + e]);
                }
        }
    __syncthreads();
    for (int idx = t; idx < 128 * 16; idx += 512) {
        const int row = idx >> 4, ch = idx & 15;
        const uint4 v = *(const uint4*)&eb[row * 136 + ch * 8];
        *(uint4*)&g_cth[((size_t)(b * LLEN + pix0 + row)) * 256 + pyr * C4 + ch * 8] = v;
    }
}

// ---------------- K6: fusion conv as fp16 HMMA GEMM (cp.async 2-buf) -----------
#define BUFB 32768
__global__ void __launch_bounds__(512) k_conv_mma() {
    extern __shared__ char dsm[];
    const uint32_t sbase = smem_u32(dsm);
    const uint32_t offA = 0, offB = 16384;

    const int b = blockIdx.z;
    const int co0 = blockIdx.y * 128;
    const int pix0 = blockIdx.x * 128;
    const int t = threadIdx.x;
    const int wid = t >> 5, lane = t & 31;
    const int wm = wid >> 2, wn = wid & 3;

    const __half* __restrict__ wh = g_wh;
    const __half* __restrict__ cth = g_cth + (size_t)b * LLEN * 256;

    float acc[2][4][4] = {};

    const int aRow = wm * 32 + (lane & 15);
    const int aColHalf = (lane & 16) ? 16 : 0;
    const int bRow = wn * 32 + (lane & 7);
    const int bColHalf = (lane & 8) ? 16 : 0;

    auto stage_load = [&](int s, uint32_t bufOff) {
        const int tap = s >> 2;
        const int ky = tap / 3, kx = tap - ky * 3;
        const int ci0 = (s & 3) * 64;
        const int kA = s * 64;
        for (int idx = t; idx < 1024; idx += 512) {
            const int r = idx >> 3, ch = idx & 7;
            const uint32_t sw = swz((uint32_t)(r * 128 + ch * 16));
            const int goff = ch * 8;
            cp16(sbase + bufOff + offA + sw, wh + (size_t)(co0 + r) * CONVK + kA + goff, true);
            const int gp = pix0 + r;
            const int sy = (gp >> 5) + ky - 1, sx = (gp & 31) + kx - 1;
            const bool ok = (sy >= 0 && sy < 32 && sx >= 0 && sx < 32);
            const __half* src = ok ? (cth + ((size_t)(sy * 32 + sx)) * 256 + ci0 + goff) : cth;
            cp16(sbase + bufOff + offB + sw, src, ok);
        }
        cp_commit();
    };

    stage_load(0, 0);

    for (int s = 0; s < 36; s++) {
        const uint32_t bufOff = (uint32_t)(s & 1) * BUFB;
        if (s < 35) {
            stage_load(s + 1, (uint32_t)((s + 1) & 1) * BUFB);
            asm volatile("cp.async.wait_group 1;" ::: "memory");
        } else {
            asm volatile("cp.async.wait_group 0;" ::: "memory");
        }
        __syncthreads();

#pragma unroll
        for (int kk = 0; kk < 4; kk++) {
            uint32_t Af[2][4], Bf[4][2];
#pragma unroll
            for (int mt = 0; mt < 2; mt++) {
                const uint32_t boff = swz((uint32_t)((aRow + mt * 16) * 128 + kk * 32 + aColHalf));
                ldsm_x4(Af[mt][0], Af[mt][1], Af[mt][2], Af[mt][3], sbase + bufOff + offA + boff);
            }
#pragma unroll
            for (int nt = 0; nt < 4; nt++) {
                const uint32_t boff = swz((uint32_t)((bRow + nt * 8) * 128 + kk * 32 + bColHalf));
                ldsm_x2(Bf[nt][0], Bf[nt][1], sbase + bufOff + offB + boff);
            }
#pragma unroll
            for (int mt = 0; mt < 2; mt++)
#pragma unroll
                for (int nt = 0; nt < 4; nt++)
                    mma_f16(acc[mt][nt], Af[mt], Bf[nt]);
        }
        __syncthreads();
    }

    const float* cbp = &g_contrib[(size_t)b * 9 * Cc];
    const int mBase = co0 + wm * 32 + (lane >> 2);
    const int nBase = pix0 + wn * 32 + (lane & 3) * 2;
#pragma unroll
    for (int mt = 0; mt < 2; mt++) {
#pragma unroll
        for (int half = 0; half < 2; half++) {
            const int co = mBase + mt * 16 + half * 8;
            float* yrow = &g_y[((size_t)b * Cc + co) * LLEN];
#pragma unroll
            for (int nt = 0; nt < 4; nt++) {
#pragma unroll
                for (int e = 0; e < 2; e++) {
                    const int gp = nBase + nt * 8 + e;
                    const int y = gp >> 5, xg = gp & 31;
                    const int rt = (y == 0) ? 0 : ((y == 31) ? 2 : 1);
                    const int ct = (xg == 0) ? 0 : ((xg == 31) ? 2 : 1);
                    const float cc = cbp[(rt * 3 + ct) * Cc + co];
                    yrow[gp] = acc[mt][nt][half * 2 + e] + cc;
                }
            }
        }
    }
}

// ---------------- K7: BN batch statistics -------------------------------------
__global__ void k_stats(const float* __restrict__ bn_scale) {
    const int c = blockIdx.x, t = threadIdx.x;
    double s = 0.0, ss = 0.0;
    for (int idx = t; idx < Nn * LLEN; idx += 256) {
        const int bb = idx >> 10, l = idx & 1023;
        const float v = g_y[((size_t)bb * Cc + c) * LLEN + l];
        s += v; ss += (double)v * v;
    }
    __shared__ double rs[256], rq[256];
    rs[t] = s; rq[t] = ss; __syncthreads();
    for (int o = 128; o > 0; o >>= 1) {
        if (t < o) { rs[t] += rs[t + o]; rq[t] += rq[t + o]; }
        __syncthreads();
    }
    if (t == 0) {
        const double mean = rs[0] / (double)(Nn * LLEN);
        const double var  = rq[0] / (double)(Nn * LLEN) - mean * mean;
        g_stats[c * 2]     = (float)mean;
        g_stats[c * 2 + 1] = bn_scale[c] * rsqrtf((float)var + EPSf);
    }
}

// ---------------- K8: BN apply + ReLU + gamma*y + x ----------------------------
__global__ void k_final(const float* __restrict__ x, const float* __restrict__ bn_bias,
                        const float* __restrict__ gamma, float* __restrict__ out) {
    const int idx = blockIdx.x * 256 + threadIdx.x;
    const float g = gamma[0];
    const int c = (idx >> 10) & (Cc - 1);
    const float v = g_y[idx];
    float tt = (v - g_stats[c * 2]) * g_stats[c * 2 + 1] + bn_bias[c];
    tt = fmaxf(tt, 0.f);
    out[idx] = g * tt + x[idx];
}

// ---------------- launch ------------------------------------------------------
extern "C" void kernel_launch(void* const* d_in, const int* in_sizes, int n_in,
                              void* d_out, int out_size) {
    (void)in_sizes; (void)n_in; (void)out_size;
    const float* x        = (const float*)d_in[0];
    const float* rce_w    = (const float*)d_in[1];
    const float* rce_b    = (const float*)d_in[2];
    const float* q_w      = (const float*)d_in[3];
    const float* q_b      = (const float*)d_in[4];
    const float* k_w      = (const float*)d_in[5];
    const float* k_b      = (const float*)d_in[6];
    const float* value_w  = (const float*)d_in[7];
    const float* value_b  = (const float*)d_in[8];
    const float* fusion_w = (const float*)d_in[9];
    const float* bn_scale = (const float*)d_in[10];
    const float* bn_bias  = (const float*)d_in[11];
    const float* gamma    = (const float*)d_in[12];
    float* out = (float*)d_out;

    cudaFuncSetAttribute(k_attn, cudaFuncAttributeMaxDynamicSharedMemorySize, 81920);
    cudaFuncSetAttribute(k_conv_mma, cudaFuncAttributeMaxDynamicSharedMemorySize, 65536);
    cudaFuncSetAttribute(k_outgemm_mma, cudaFuncAttributeMaxDynamicSharedMemorySize, 65536);

    k_value_proj<<<dim3(16, 2, 16), 256>>>(x, value_w, value_b);
    k_prep<<<16, 256>>>(x, rce_w, rce_b, q_w, q_b, k_w, k_b);
    k_mean<<<dim3(128, 16), 256>>>();
    k_wsum<<<512, 128>>>(fusion_w);
    k_const<<<16, 512>>>();
    k_wsplit<<<4608, 256>>>(fusion_w);
    k_attn<<<dim3(8, 2, 16), 256, 81920>>>();
    k_outgemm_mma<<<dim3(8, 1, 32), 512, 65536>>>();
    k_conv_mma<<<dim3(8, 4, 16), 512, 65536>>>();
    k_stats<<<512, 256>>>(bn_scale);
    k_final<<<32768, 256>>>(x, bn_bias, gamma, out);
}

// round 12
// speedup vs baseline: 2.4579x; 1.2455x over previous
#include <cuda_runtime.h>
#include <cuda_bf16.h>
#include <cuda_fp16.h>
#include <cstdint>
#include <stdint.h>
#include <math.h>

#define Nn 16
#define Cc 512
#define C4 128
#define QKC 16
#define LLEN 1024
#define EPSf 1e-5f
#define CONVK 2304          // 9 taps * 256 attn channels

// ---------------- scratch (device globals; no allocation allowed) ----------------
__device__ float g_value[Nn * C4 * LLEN];                 // proj_value fp32
__device__ float g_qk[2 * 2 * Nn * QKC * LLEN];           // [q/k][pyr][b][qc][l]
__device__ __half g_attnh[(size_t)2 * Nn * LLEN * LLEN];  // [pyr][b][m][l] probs fp16
__device__ float g_y[Nn * Cc * LLEN];                     // conv output pre-BN
__device__ float g_stats[Cc * 2];
__device__ float g_mean[Nn * C4];
__device__ float g_wsum[9 * Cc * C4];
__device__ float g_contrib[Nn * 9 * Cc];
__device__ float g_sp4[Nn * Cc * 16];                     // pooled 4x4 per (b,c)
__device__ __half g_wh[Cc * CONVK];                       // weight fp16 [co][tap*256+cc]
__device__ __half g_vh[Nn * C4 * LLEN];                   // V fp16 [b][c][l]
__device__ __half g_cth[(size_t)Nn * LLEN * 256];         // feat fp16 [b][pix][cc]

__device__ __forceinline__ int qk_idx(int g, int py, int b, int qc, int l) {
    return (((g * 2 + py) * Nn + b) * QKC + qc) * LLEN + l;
}

// ---------------- PTX helpers (legacy tensor path, sm_80+) ----------------
__device__ __forceinline__ uint32_t smem_u32(const void* p) {
    uint32_t a;
    asm("{ .reg .u64 t; cvta.to.shared.u64 t, %1; cvt.u32.u64 %0, t; }" : "=r"(a) : "l"(p));
    return a;
}
__device__ __forceinline__ void ldsm_x4(uint32_t& r0, uint32_t& r1, uint32_t& r2, uint32_t& r3,
                                        uint32_t addr) {
    asm volatile("ldmatrix.sync.aligned.m8n8.x4.shared.b16 {%0,%1,%2,%3}, [%4];"
                 : "=r"(r0), "=r"(r1), "=r"(r2), "=r"(r3) : "r"(addr));
}
__device__ __forceinline__ void ldsm_x2(uint32_t& r0, uint32_t& r1, uint32_t addr) {
    asm volatile("ldmatrix.sync.aligned.m8n8.x2.shared.b16 {%0,%1}, [%2];"
                 : "=r"(r0), "=r"(r1) : "r"(addr));
}
__device__ __forceinline__ void mma_f16(float* c, const uint32_t* a, const uint32_t* b) {
    asm volatile(
        "mma.sync.aligned.m16n8k16.row.col.f32.f16.f16.f32 "
        "{%0,%1,%2,%3}, {%4,%5,%6,%7}, {%8,%9}, {%0,%1,%2,%3};"
        : "+f"(c[0]), "+f"(c[1]), "+f"(c[2]), "+f"(c[3])
        : "r"(a[0]), "r"(a[1]), "r"(a[2]), "r"(a[3]), "r"(b[0]), "r"(b[1]));
}
__device__ __forceinline__ uint32_t swz(uint32_t boff) {
    return boff ^ ((boff >> 3) & 0x70);
}
__device__ __forceinline__ void cp16(uint32_t dst, const void* src, bool pred) {
    const int sz = pred ? 16 : 0;
    asm volatile("cp.async.cg.shared.global [%0], [%1], 16, %2;"
                 :: "r"(dst), "l"(src), "r"(sz) : "memory");
}
__device__ __forceinline__ void cp_commit() {
    asm volatile("cp.async.commit_group;" ::: "memory");
}
// FMA-pipe exp (x<=0): degree-5 Taylor of 2^f + exponent add. rel err ~2e-6.
__device__ __forceinline__ float fexp(float x) {
    float y = fmaxf(x * 1.44269504f, -80.f);
    float r = rintf(y);
    float f = y - r;
    float p = 1.3333558e-3f;
    p = fmaf(p, f, 9.6181291e-3f);
    p = fmaf(p, f, 5.5504109e-2f);
    p = fmaf(p, f, 2.4022651e-1f);
    p = fmaf(p, f, 6.9314718e-1f);
    p = fmaf(p, f, 1.0f);
    return __int_as_float(__float_as_int(p) + (((int)r) << 23));
}

// ---------------- K1: value projection GEMM (also emits fp16 V) ----
__global__ void k_value_proj(const float* __restrict__ x,
                             const float* __restrict__ w,
                             const float* __restrict__ bias) {
    __shared__ float As[32 * 68];
    __shared__ float Bs[32 * 68];
    const int b  = blockIdx.z;
    const int m0 = blockIdx.y * 64;
    const int n0 = blockIdx.x * 64;
    const float* xb = x + b * Cc * LLEN;
    const int t  = threadIdx.x;
    const int ty = t >> 4, tx = t & 15;
    const int am = t >> 2, akq = (t & 3) * 8;
    const int bk = t >> 3, bnq = (t & 7) * 8;
    float acc[4][4] = {};

    for (int kc = 0; kc < Cc / 32; kc++) {
        const int k0 = kc * 32;
        __syncthreads();
        float4 a0 = *(const float4*)&w[(m0 + am) * Cc + k0 + akq];
        float4 a1 = *(const float4*)&w[(m0 + am) * Cc + k0 + akq + 4];
        As[(akq + 0) * 68 + am] = a0.x; As[(akq + 1) * 68 + am] = a0.y;
        As[(akq + 2) * 68 + am] = a0.z; As[(akq + 3) * 68 + am] = a0.w;
        As[(akq + 4) * 68 + am] = a1.x; As[(akq + 5) * 68 + am] = a1.y;
        As[(akq + 6) * 68 + am] = a1.z; As[(akq + 7) * 68 + am] = a1.w;
        float4 b0 = *(const float4*)&xb[(k0 + bk) * LLEN + n0 + bnq];
        float4 b1 = *(const float4*)&xb[(k0 + bk) * LLEN + n0 + bnq + 4];
        *(float4*)&Bs[bk * 68 + bnq]     = b0;
        *(float4*)&Bs[bk * 68 + bnq + 4] = b1;
        __syncthreads();
#pragma unroll
        for (int k = 0; k < 32; k++) {
            float4 av = *(const float4*)&As[k * 68 + ty * 4];
            float4 bv = *(const float4*)&Bs[k * 68 + tx * 4];
            acc[0][0] += av.x * bv.x; acc[0][1] += av.x * bv.y; acc[0][2] += av.x * bv.z; acc[0][3] += av.x * bv.w;
            acc[1][0] += av.y * bv.x; acc[1][1] += av.y * bv.y; acc[1][2] += av.y * bv.z; acc[1][3] += av.y * bv.w;
            acc[2][0] += av.z * bv.x; acc[2][1] += av.z * bv.y; acc[2][2] += av.z * bv.z; acc[2][3] += av.z * bv.w;
            acc[3][0] += av.w * bv.x; acc[3][1] += av.w * bv.y; acc[3][2] += av.w * bv.z; acc[3][3] += av.w * bv.w;
        }
    }
#pragma unroll
    for (int i = 0; i < 4; i++) {
        const int c = m0 + ty * 4 + i;
        const float bs = bias[c];
        float4 o;
        o.x = acc[i][0] + bs; o.y = acc[i][1] + bs; o.z = acc[i][2] + bs; o.w = acc[i][3] + bs;
        const size_t off = (size_t)(b * C4 + c) * LLEN + n0 + tx * 4;
        *(float4*)&g_value[off] = o;
        __half h[4] = {__float2half(o.x), __float2half(o.y), __float2half(o.z), __float2half(o.w)};
        *(uint2*)&g_vh[off] = *(const uint2*)h;
    }
}

// ---------------- K1c: adaptive avg pool to 4x4 (parallel over 128 CTAs) --------
__global__ void k_pool(const float* __restrict__ x) {
    const int b = blockIdx.x, cg = blockIdx.y;     // cg: 64-channel group
    const int t = threadIdx.x;
    const int c = cg * 64 + (t >> 2);              // 256 threads: 64 c x 4 cells-of-4
    const int cellq = (t & 3) * 4;
    const float* xc = x + ((size_t)b * Cc + c) * LLEN;
#pragma unroll
    for (int cq = 0; cq < 4; cq++) {
        const int cell = cellq + cq;
        const int i = cell >> 2, j = cell & 3;
        float s = 0.f;
        for (int y = 0; y < 8; y++) {
            const float* row = &xc[(i * 8 + y) * 32 + j * 8];
#pragma unroll
            for (int xx = 0; xx < 8; xx++) s += row[xx];
        }
        g_sp4[(b * Cc + c) * 16 + cell] = s * (1.f / 64.f);
    }
}

// ---------------- K2: rce + q/k feats + bilinear upsample ----------------------
__global__ void k_prep(const float* __restrict__ rce_w, const float* __restrict__ rce_b,
                       const float* __restrict__ qw, const float* __restrict__ qb,
                       const float* __restrict__ kw, const float* __restrict__ kb) {
    __shared__ float sp4[Cc * 16];
    __shared__ float f4[C4 * 16];
    __shared__ float f2[C4 * 4];
    __shared__ float qf4[QKC * 16], kf4[QKC * 16];
    __shared__ float qf2[QKC * 4],  kf2[QKC * 4];
    const int b = blockIdx.x, t = threadIdx.x;

    for (int idx = t; idx < Cc * 16 / 4; idx += 256)
        *(float4*)&sp4[idx * 4] = *(const float4*)&g_sp4[b * Cc * 16 + idx * 4];
    __syncthreads();

    if (t < C4) {
        float a4[16] = {}, a2[4] = {};
        for (int c = 0; c < Cc; c++) {
            const float w4 = rce_w[(2 * C4 + t) * Cc + c];
            const float w2 = rce_w[(1 * C4 + t) * Cc + c];
            const float* p = &sp4[c * 16];
#pragma unroll
            for (int cell = 0; cell < 16; cell++) a4[cell] += w4 * p[cell];
#pragma unroll
            for (int i = 0; i < 2; i++)
#pragma unroll
                for (int j = 0; j < 2; j++)
                    a2[i * 2 + j] += w2 * 0.25f *
                        (p[(2 * i) * 4 + 2 * j] + p[(2 * i) * 4 + 2 * j + 1] +
                         p[(2 * i + 1) * 4 + 2 * j] + p[(2 * i + 1) * 4 + 2 * j + 1]);
        }
        const float b4 = rce_b[2 * C4 + t], b2v = rce_b[1 * C4 + t];
#pragma unroll
        for (int cell = 0; cell < 16; cell++) f4[t * 16 + cell] = a4[cell] + b4;
#pragma unroll
        for (int cc = 0; cc < 4; cc++) f2[t * 4 + cc] = a2[cc] + b2v;
    }
    __syncthreads();

    {
        const int qc = t >> 4, cell = t & 15;
        float aq = 0.f, ak = 0.f;
        for (int o = 0; o < C4; o++) {
            const float fv = f4[o * 16 + cell];
            aq += qw[qc * C4 + o] * fv;
            ak += kw[qc * C4 + o] * fv;
        }
        qf4[t] = aq + qb[qc]; kf4[t] = ak + kb[qc];
    }
    if (t < 64) {
        const int qc = t >> 2, cc = t & 3;
        float aq = 0.f, ak = 0.f;
        for (int o = 0; o < C4; o++) {
            const float fv = f2[o * 4 + cc];
            aq += qw[qc * C4 + o] * fv;
            ak += kw[qc * C4 + o] * fv;
        }
        qf2[t] = aq + qb[qc]; kf2[t] = ak + kb[qc];
    }
    __syncthreads();

    const float st4 = 3.0f / 31.0f, st2 = 1.0f / 31.0f;
    for (int idx = t; idx < QKC * LLEN; idx += 256) {
        const int qc = idx >> 10, p = idx & 1023, r = p >> 5, cc = p & 31;
        float pr = r * st4;  int lr = (int)pr; lr = lr > 2 ? 2 : lr; float fr = pr - lr;
        float pc = cc * st4; int lc = (int)pc; lc = lc > 2 ? 2 : lc; float fc = pc - lc;
        const float w00 = (1.f - fr) * (1.f - fc), w01 = (1.f - fr) * fc;
        const float w10 = fr * (1.f - fc),         w11 = fr * fc;
        const float* q4 = &qf4[qc * 16]; const float* k4 = &kf4[qc * 16];
        g_qk[qk_idx(0, 1, b, qc, p)] =
            w00 * q4[lr * 4 + lc] + w01 * q4[lr * 4 + lc + 1] +
            w10 * q4[(lr + 1) * 4 + lc] + w11 * q4[(lr + 1) * 4 + lc + 1];
        g_qk[qk_idx(1, 1, b, qc, p)] =
            w00 * k4[lr * 4 + lc] + w01 * k4[lr * 4 + lc + 1] +
            w10 * k4[(lr + 1) * 4 + lc] + w11 * k4[(lr + 1) * 4 + lc + 1];
        const float fr2 = r * st2, fc2 = cc * st2;
        const float u00 = (1.f - fr2) * (1.f - fc2), u01 = (1.f - fr2) * fc2;
        const float u10 = fr2 * (1.f - fc2),          u11 = fr2 * fc2;
        const float* q2 = &qf2[qc * 4]; const float* k2 = &kf2[qc * 4];
        g_qk[qk_idx(0, 0, b, qc, p)] = u00 * q2[0] + u01 * q2[1] + u10 * q2[2] + u11 * q2[3];
        g_qk[qk_idx(1, 0, b, qc, p)] = u00 * k2[0] + u01 * k2[1] + u10 * k2[2] + u11 * k2[3];
    }
}

// ---------------- K3: sz=1 pyramid mean ----------------------------
__global__ void k_mean() {
    const int c = blockIdx.x, b = blockIdx.y, t = threadIdx.x;
    const float* v = &g_value[(b * C4 + c) * LLEN];
    float s = 0.f;
    for (int i = t; i < LLEN; i += 256) s += v[i];
    __shared__ float red[256];
    red[t] = s; __syncthreads();
    for (int o = 128; o > 0; o >>= 1) { if (t < o) red[t] += red[t + o]; __syncthreads(); }
    if (t == 0) g_mean[b * C4 + c] = red[0] * (1.f / LLEN);
}

// ---------------- K3b: border-pattern weight sums ----------------
__global__ void k_wsum(const float* __restrict__ fw) {
    const int co = blockIdx.x, ci = threadIdx.x;
    float w[9];
#pragma unroll
    for (int k = 0; k < 9; k++) w[k] = fw[co * 3456 + ci * 9 + k];
#pragma unroll
    for (int rt = 0; rt < 3; rt++) {
        const int kylo = (rt == 0) ? 1 : 0, kyhi = (rt == 2) ? 1 : 2;
#pragma unroll
        for (int ct = 0; ct < 3; ct++) {
            const int kxlo = (ct == 0) ? 1 : 0, kxhi = (ct == 2) ? 1 : 2;
            float s = 0.f;
            for (int ky = kylo; ky <= kyhi; ky++)
                for (int kx = kxlo; kx <= kxhi; kx++)
                    s += w[ky * 3 + kx];
            g_wsum[((rt * 3 + ct) * Cc + co) * C4 + ci] = s;
        }
    }
}

// ---------------- K3c: constant-channel conv contribution ----------------
__global__ void k_const() {
    __shared__ float sm[C4];
    const int b = blockIdx.x, co = threadIdx.x;
    if (co < C4) sm[co] = g_mean[b * C4 + co];
    __syncthreads();
#pragma unroll
    for (int pat = 0; pat < 9; pat++) {
        const float* ws = &g_wsum[(pat * Cc + co) * C4];
        float s = 0.f;
        for (int ci = 0; ci < C4; ci++) s += sm[ci] * ws[ci];
        g_contrib[(b * 9 + pat) * Cc + co] = s;
    }
}

// ---------------- K3d: weight fp16, reordered [co][tap*256+cc] -----------------
__global__ void k_wsplit(const float* __restrict__ fw) {
    const int idx = blockIdx.x * 256 + threadIdx.x;   // 512*2304
    const int co = idx / CONVK, k = idx % CONVK;
    const int tap = k >> 8, cc = k & 255;
    g_wh[idx] = __float2half(fw[co * 3456 + 1152 + cc * 9 + tap]);
}

// ---------------- K4: energy + softmax -> attn probabilities (fp16 k, fp16 out) -
// ks: fp16 [l][qc], pitch 24 halfs (48 B, 16B-aligned rows; conflict-free phases)
__global__ void __launch_bounds__(256, 2) k_attn() {
    extern __shared__ __half ksh[];
    const int b = blockIdx.z, pyr = blockIdx.y;
    const int mbase = blockIdx.x * 128;
    const int t = threadIdx.x, w = t >> 5, lane = t & 31;
    const float* gq = &g_qk[qk_idx(0, pyr, b, 0, 0)];
    const float* gk = &g_qk[qk_idx(1, pyr, b, 0, 0)];
    for (int idx = t; idx < QKC * LLEN; idx += 256) {
        const int qc = idx >> 10, l = idx & 1023;
        ksh[l * 24 + qc] = __float2half(gk[qc * LLEN + l]);
    }
    __syncthreads();
    __half* pb = &g_attnh[(size_t)(pyr * Nn + b) * LLEN * LLEN];

    for (int pr = 0; pr < 16; pr++) {
        const int m = mbase + pr * 8 + w;
        float q[16];
#pragma unroll
        for (int j = 0; j < 16; j++) q[j] = gq[j * LLEN + m];
        float e[32];
        float mx = -1e30f;
#pragma unroll
        for (int i = 0; i < 32; i++) {
            const int l = i * 32 + lane;
            const uint4 kA = *(const uint4*)&ksh[l * 24];
            const uint4 kB = *(const uint4*)&ksh[l * 24 + 8];
            const __half2* hA = (const __half2*)&kA;
            const __half2* hB = (const __half2*)&kB;
            float s = 0.f;
#pragma unroll
            for (int j = 0; j < 4; j++) {
                const float2 fa = __half22float2(hA[j]);
                const float2 fb = __half22float2(hB[j]);
                s = fmaf(q[2 * j], fa.x, s);
                s = fmaf(q[2 * j + 1], fa.y, s);
                s = fmaf(q[8 + 2 * j], fb.x, s);
                s = fmaf(q[9 + 2 * j], fb.y, s);
            }
            e[i] = s;
            mx = fmaxf(mx, s);
        }
#pragma unroll
        for (int o = 16; o > 0; o >>= 1)
            mx = fmaxf(mx, __shfl_xor_sync(0xffffffffu, mx, o));
        float sm = 0.f;
#pragma unroll
        for (int i = 0; i < 32; i++) { e[i] = fexp(e[i] - mx); sm += e[i]; }
#pragma unroll
        for (int o = 16; o > 0; o >>= 1)
            sm += __shfl_xor_sync(0xffffffffu, sm, o);
        const float inv = 1.f / sm;
        __half* pa = &pb[(size_t)m * LLEN];
#pragma unroll
        for (int i = 0; i < 32; i++)
            pa[i * 32 + lane] = __float2half(e[i] * inv);
    }
}

// ---------------- K5: HMMA out-GEMM: catT[pix][c] = sum_l V[c][l]*P[pix][l] ----
#define BUFO 32768
__global__ void __launch_bounds__(512) k_outgemm_mma() {
    extern __shared__ char dsm[];
    const uint32_t sbase = smem_u32(dsm);
    const uint32_t offA = 0, offB = 16384;

    const int z = blockIdx.z; const int b = z >> 1; const int pyr = z & 1;
    const int pix0 = blockIdx.x * 128;
    const int t = threadIdx.x;
    const int wid = t >> 5, lane = t & 31;
    const int wm = wid >> 2, wn = wid & 3;

    const __half* __restrict__ vh = g_vh + (size_t)b * C4 * LLEN;
    const __half* __restrict__ P  = g_attnh + (size_t)(pyr * Nn + b) * LLEN * LLEN;

    float acc[2][4][4] = {};

    const int aRow = wm * 32 + (lane & 15);
    const int aColHalf = (lane & 16) ? 16 : 0;
    const int bRow = wn * 32 + (lane & 7);
    const int bColHalf = (lane & 8) ? 16 : 0;

    auto stage_load = [&](int s, uint32_t bufOff) {
        const int l0 = s * 64;
        for (int idx = t; idx < 1024; idx += 512) {
            const int r = idx >> 3, ch = idx & 7;
            const uint32_t sw = swz((uint32_t)(r * 128 + ch * 16));
            const int goff = ch * 8;
            cp16(sbase + bufOff + offA + sw, vh + (size_t)r * LLEN + l0 + goff, true);
            cp16(sbase + bufOff + offB + sw, P + (size_t)(pix0 + r) * LLEN + l0 + goff, true);
        }
        cp_commit();
    };

    stage_load(0, 0);

    for (int s = 0; s < 16; s++) {
        const uint32_t bufOff = (uint32_t)(s & 1) * BUFO;
        if (s < 15) {
            stage_load(s + 1, (uint32_t)((s + 1) & 1) * BUFO);
            asm volatile("cp.async.wait_group 1;" ::: "memory");
        } else {
            asm volatile("cp.async.wait_group 0;" ::: "memory");
        }
        __syncthreads();

#pragma unroll
        for (int kk = 0; kk < 4; kk++) {
            uint32_t Af[2][4], Bf[4][2];
#pragma unroll
            for (int mt = 0; mt < 2; mt++) {
                const uint32_t boff = swz((uint32_t)((aRow + mt * 16) * 128 + kk * 32 + aColHalf));
                ldsm_x4(Af[mt][0], Af[mt][1], Af[mt][2], Af[mt][3], sbase + bufOff + offA + boff);
            }
#pragma unroll
            for (int nt = 0; nt < 4; nt++) {
                const uint32_t boff = swz((uint32_t)((bRow + nt * 8) * 128 + kk * 32 + bColHalf));
                ldsm_x2(Bf[nt][0], Bf[nt][1], sbase + bufOff + offB + boff);
            }
#pragma unroll
            for (int mt = 0; mt < 2; mt++)
#pragma unroll
                for (int nt = 0; nt < 4; nt++)
                    mma_f16(acc[mt][nt], Af[mt], Bf[nt]);
        }
        __syncthreads();
    }

    // epilogue: smem transpose [pixLocal][c] (pitch 136), then coalesced fp16 store
    __half* eb = (__half*)dsm;
    const int cBase = wm * 32 + (lane >> 2);
    const int pBase = wn * 32 + (lane & 3) * 2;
#pragma unroll
    for (int mt = 0; mt < 2; mt++)
#pragma unroll
        for (int half = 0; half < 2; half++) {
            const int c = cBase + mt * 16 + half * 8;
#pragma unroll
            for (int nt = 0; nt < 4; nt++)
#pragma unroll
                for (int e = 0; e < 2; e++) {
                    const int p = pBase + nt * 8 + e;
                    eb[p * 136 + c] = __float2half(acc[mt][nt][half * 2 + e]);
                }
        }
    __syncthreads();
    for (int idx = t; idx < 128 * 16; idx += 512) {
        const int row = idx >> 4, ch = idx & 15;
        const uint4 v = *(const uint4*)&eb[row * 136 + ch * 8];
        *(uint4*)&g_cth[((size_t)(b * LLEN + pix0 + row)) * 256 + pyr * C4 + ch * 8] = v;
    }
}

// ---------------- K6: fusion conv as fp16 HMMA GEMM (cp.async 2-buf) -----------
#define BUFB 32768
__global__ void __launch_bounds__(512) k_conv_mma() {
    extern __shared__ char dsm[];
    const uint32_t sbase = smem_u32(dsm);
    const uint32_t offA = 0, offB = 16384;

    const int b = blockIdx.z;
    const int co0 = blockIdx.y * 128;
    const int pix0 = blockIdx.x * 128;
    const int t = threadIdx.x;
    const int wid = t >> 5, lane = t & 31;
    const int wm = wid >> 2, wn = wid & 3;

    const __half* __restrict__ wh = g_wh;
    const __half* __restrict__ cth = g_cth + (size_t)b * LLEN * 256;

    float acc[2][4][4] = {};

    const int aRow = wm * 32 + (lane & 15);
    const int aColHalf = (lane & 16) ? 16 : 0;
    const int bRow = wn * 32 + (lane & 7);
    const int bColHalf = (lane & 8) ? 16 : 0;

    auto stage_load = [&](int s, uint32_t bufOff) {
        const int tap = s >> 2;
        const int ky = tap / 3, kx = tap - ky * 3;
        const int ci0 = (s & 3) * 64;
        const int kA = s * 64;
        for (int idx = t; idx < 1024; idx += 512) {
            const int r = idx >> 3, ch = idx & 7;
            const uint32_t sw = swz((uint32_t)(r * 128 + ch * 16));
            const int goff = ch * 8;
            cp16(sbase + bufOff + offA + sw, wh + (size_t)(co0 + r) * CONVK + kA + goff, true);
            const int gp = pix0 + r;
            const int sy = (gp >> 5) + ky - 1, sx = (gp & 31) + kx - 1;
            const bool ok = (sy >= 0 && sy < 32 && sx >= 0 && sx < 32);
            const __half* src = ok ? (cth + ((size_t)(sy * 32 + sx)) * 256 + ci0 + goff) : cth;
            cp16(sbase + bufOff + offB + sw, src, ok);
        }
        cp_commit();
    };

    stage_load(0, 0);

    for (int s = 0; s < 36; s++) {
        const uint32_t bufOff = (uint32_t)(s & 1) * BUFB;
        if (s < 35) {
            stage_load(s + 1, (uint32_t)((s + 1) & 1) * BUFB);
            asm volatile("cp.async.wait_group 1;" ::: "memory");
        } else {
            asm volatile("cp.async.wait_group 0;" ::: "memory");
        }
        __syncthreads();

#pragma unroll
        for (int kk = 0; kk < 4; kk++) {
            uint32_t Af[2][4], Bf[4][2];
#pragma unroll
            for (int mt = 0; mt < 2; mt++) {
                const uint32_t boff = swz((uint32_t)((aRow + mt * 16) * 128 + kk * 32 + aColHalf));
                ldsm_x4(Af[mt][0], Af[mt][1], Af[mt][2], Af[mt][3], sbase + bufOff + offA + boff);
            }
#pragma unroll
            for (int nt = 0; nt < 4; nt++) {
                const uint32_t boff = swz((uint32_t)((bRow + nt * 8) * 128 + kk * 32 + bColHalf));
                ldsm_x2(Bf[nt][0], Bf[nt][1], sbase + bufOff + offB + boff);
            }
#pragma unroll
            for (int mt = 0; mt < 2; mt++)
#pragma unroll
                for (int nt = 0; nt < 4; nt++)
                    mma_f16(acc[mt][nt], Af[mt], Bf[nt]);
        }
        __syncthreads();
    }

    const float* cbp = &g_contrib[(size_t)b * 9 * Cc];
    const int mBase = co0 + wm * 32 + (lane >> 2);
    const int nBase = pix0 + wn * 32 + (lane & 3) * 2;
#pragma unroll
    for (int mt = 0; mt < 2; mt++) {
#pragma unroll
        for (int half = 0; half < 2; half++) {
            const int co = mBase + mt * 16 + half * 8;
            float* yrow = &g_y[((size_t)b * Cc + co) * LLEN];
#pragma unroll
            for (int nt = 0; nt < 4; nt++) {
#pragma unroll
                for (int e = 0; e < 2; e++) {
                    const int gp = nBase + nt * 8 + e;
                    const int y = gp >> 5, xg = gp & 31;
                    const int rt = (y == 0) ? 0 : ((y == 31) ? 2 : 1);
                    const int ct = (xg == 0) ? 0 : ((xg == 31) ? 2 : 1);
                    const float cc = cbp[(rt * 3 + ct) * Cc + co];
                    yrow[gp] = acc[mt][nt][half * 2 + e] + cc;
                }
            }
        }
    }
}

// ---------------- K7: BN batch statistics -------------------------------------
__global__ void k_stats(const float* __restrict__ bn_scale) {
    const int c = blockIdx.x, t = threadIdx.x;
    double s = 0.0, ss = 0.0;
    for (int idx = t; idx < Nn * LLEN; idx += 256) {
        const int bb = idx >> 10, l = idx & 1023;
        const float v = g_y[((size_t)bb * Cc + c) * LLEN + l];
        s += v; ss += (double)v * v;
    }
    __shared__ double rs[256], rq[256];
    rs[t] = s; rq[t] = ss; __syncthreads();
    for (int o = 128; o > 0; o >>= 1) {
        if (t < o) { rs[t] += rs[t + o]; rq[t] += rq[t + o]; }
        __syncthreads();
    }
    if (t == 0) {
        const double mean = rs[0] / (double)(Nn * LLEN);
        const double var  = rq[0] / (double)(Nn * LLEN) - mean * mean;
        g_stats[c * 2]     = (float)mean;
        g_stats[c * 2 + 1] = bn_scale[c] * rsqrtf((float)var + EPSf);
    }
}

// ---------------- K8: BN apply + ReLU + gamma*y + x ----------------------------
__global__ void k_final(const float* __restrict__ x, const float* __restrict__ bn_bias,
                        const float* __restrict__ gamma, float* __restrict__ out) {
    const int idx = blockIdx.x * 256 + threadIdx.x;
    const float g = gamma[0];
    const int c = (idx >> 10) & (Cc - 1);
    const float v = g_y[idx];
    float tt = (v - g_stats[c * 2]) * g_stats[c * 2 + 1] + bn_bias[c];
    tt = fmaxf(tt, 0.f);
    out[idx] = g * tt + x[idx];
}

// ---------------- launch ------------------------------------------------------
extern "C" void kernel_launch(void* const* d_in, const int* in_sizes, int n_in,
                              void* d_out, int out_size) {
    (void)in_sizes; (void)n_in; (void)out_size;
    const float* x        = (const float*)d_in[0];
    const float* rce_w    = (const float*)d_in[1];
    const float* rce_b    = (const float*)d_in[2];
    const float* q_w      = (const float*)d_in[3];
    const float* q_b      = (const float*)d_in[4];
    const float* k_w      = (const float*)d_in[5];
    const float* k_b      = (const float*)d_in[6];
    const float* value_w  = (const float*)d_in[7];
    const float* value_b  = (const float*)d_in[8];
    const float* fusion_w = (const float*)d_in[9];
    const float* bn_scale = (const float*)d_in[10];
    const float* bn_bias  = (const float*)d_in[11];
    const float* gamma    = (const float*)d_in[12];
    float* out = (float*)d_out;

    cudaFuncSetAttribute(k_attn, cudaFuncAttributeMaxDynamicSharedMemorySize, 49152);
    cudaFuncSetAttribute(k_conv_mma, cudaFuncAttributeMaxDynamicSharedMemorySize, 65536);
    cudaFuncSetAttribute(k_outgemm_mma, cudaFuncAttributeMaxDynamicSharedMemorySize, 65536);

    // Launch order chosen so launch #4 (= ncu capture target) is k_outgemm_mma.
    k_pool<<<dim3(16, 8), 256>>>(x);
    k_value_proj<<<dim3(16, 2, 16), 256>>>(x, value_w, value_b);
    k_prep<<<16, 256>>>(rce_w, rce_b, q_w, q_b, k_w, k_b);
    k_attn<<<dim3(8, 2, 16), 256, 49152>>>();
    k_outgemm_mma<<<dim3(8, 1, 32), 512, 65536>>>();
    k_mean<<<dim3(128, 16), 256>>>();
    k_wsum<<<512, 128>>>(fusion_w);
    k_const<<<16, 512>>>();
    k_wsplit<<<4608, 256>>>(fusion_w);
    k_conv_mma<<<dim3(8, 4, 16), 512, 65536>>>();
    k_stats<<<512, 256>>>(bn_scale);
    k_final<<<32768, 256>>>(x, bn_bias, gamma, out);
}

// round 13
// speedup vs baseline: 2.7361x; 1.1132x over previous
#include <cuda_runtime.h>
#include <cuda_bf16.h>
#include <cuda_fp16.h>
#include <cstdint>
#include <stdint.h>
#include <math.h>

#define Nn 16
#define Cc 512
#define C4 128
#define QKC 16
#define LLEN 1024
#define EPSf 1e-5f
#define CONVK 2304          // 9 taps * 256 attn channels

// ---------------- scratch (device globals; no allocation allowed) ----------------
__device__ float g_qk[2 * 2 * Nn * QKC * LLEN];           // [q/k][pyr][b][qc][l]
__device__ __half g_attnh[(size_t)2 * Nn * LLEN * LLEN];  // [pyr][b][m][l] probs fp16
__device__ float g_y[Nn * Cc * LLEN];                     // conv output pre-BN
__device__ float g_stats[Cc * 2];
__device__ float g_mean[Nn * C4];
__device__ float g_wsum[9 * Cc * C4];
__device__ float g_contrib[Nn * 9 * Cc];
__device__ float g_sp4[Nn * Cc * 16];                     // pooled 4x4 per (b,c)
__device__ __half g_wh[Cc * CONVK];                       // fusion weight fp16 [co][tap*256+cc]
__device__ __half g_wv[C4 * Cc];                          // value weight fp16 [c][k]
__device__ __half g_xh[(size_t)Nn * LLEN * Cc];           // x transposed fp16 [b][l][c]
__device__ __half g_vh[Nn * C4 * LLEN];                   // V fp16 [b][c][l]
__device__ __half g_cth[(size_t)Nn * LLEN * 256];         // feat fp16 [b][pix][cc]

__device__ __forceinline__ int qk_idx(int g, int py, int b, int qc, int l) {
    return (((g * 2 + py) * Nn + b) * QKC + qc) * LLEN + l;
}

// ---------------- PTX helpers (legacy tensor path, sm_80+) ----------------
__device__ __forceinline__ uint32_t smem_u32(const void* p) {
    uint32_t a;
    asm("{ .reg .u64 t; cvta.to.shared.u64 t, %1; cvt.u32.u64 %0, t; }" : "=r"(a) : "l"(p));
    return a;
}
__device__ __forceinline__ void ldsm_x4(uint32_t& r0, uint32_t& r1, uint32_t& r2, uint32_t& r3,
                                        uint32_t addr) {
    asm volatile("ldmatrix.sync.aligned.m8n8.x4.shared.b16 {%0,%1,%2,%3}, [%4];"
                 : "=r"(r0), "=r"(r1), "=r"(r2), "=r"(r3) : "r"(addr));
}
__device__ __forceinline__ void ldsm_x2(uint32_t& r0, uint32_t& r1, uint32_t addr) {
    asm volatile("ldmatrix.sync.aligned.m8n8.x2.shared.b16 {%0,%1}, [%2];"
                 : "=r"(r0), "=r"(r1) : "r"(addr));
}
__device__ __forceinline__ void mma_f16(float* c, const uint32_t* a, const uint32_t* b) {
    asm volatile(
        "mma.sync.aligned.m16n8k16.row.col.f32.f16.f16.f32 "
        "{%0,%1,%2,%3}, {%4,%5,%6,%7}, {%8,%9}, {%0,%1,%2,%3};"
        : "+f"(c[0]), "+f"(c[1]), "+f"(c[2]), "+f"(c[3])
        : "r"(a[0]), "r"(a[1]), "r"(a[2]), "r"(a[3]), "r"(b[0]), "r"(b[1]));
}
__device__ __forceinline__ uint32_t swz(uint32_t boff) {
    return boff ^ ((boff >> 3) & 0x70);
}
__device__ __forceinline__ void cp16(uint32_t dst, const void* src, bool pred) {
    const int sz = pred ? 16 : 0;
    asm volatile("cp.async.cg.shared.global [%0], [%1], 16, %2;"
                 :: "r"(dst), "l"(src), "r"(sz) : "memory");
}
__device__ __forceinline__ void cp_commit() {
    asm volatile("cp.async.commit_group;" ::: "memory");
}
// FMA-pipe exp (x<=0): degree-5 Taylor of 2^f + exponent add. rel err ~2e-6.
__device__ __forceinline__ float fexp(float x) {
    float y = fmaxf(x * 1.44269504f, -80.f);
    float r = rintf(y);
    float f = y - r;
    float p = 1.3333558e-3f;
    p = fmaf(p, f, 9.6181291e-3f);
    p = fmaf(p, f, 5.5504109e-2f);
    p = fmaf(p, f, 2.4022651e-1f);
    p = fmaf(p, f, 6.9314718e-1f);
    p = fmaf(p, f, 1.0f);
    return __int_as_float(__float_as_int(p) + (((int)r) << 23));
}

// ---------------- K0a: transpose-convert x -> xh fp16 [b][l][c] -----------------
__global__ void k_xh(const float* __restrict__ x) {
    __shared__ float tile[32][33];
    const int b = blockIdx.z, c0 = blockIdx.y * 32, l0 = blockIdx.x * 32;
    const int t = threadIdx.x;
    const int col = t & 31, row = t >> 5;   // 8 rows per pass
    for (int r = row; r < 32; r += 8)
        tile[r][col] = x[((size_t)b * Cc + c0 + r) * LLEN + l0 + col];
    __syncthreads();
    for (int r = row; r < 32; r += 8)
        g_xh[((size_t)b * LLEN + l0 + r) * Cc + c0 + col] = __float2half(tile[col][r]);
}

// ---------------- K0b: value weight fp16 ----------------------------------------
__global__ void k_wv(const float* __restrict__ w) {
    const int idx = blockIdx.x * 256 + threadIdx.x;   // C4*Cc = 65536
    g_wv[idx] = __float2half(w[idx]);
}

// ---------------- K1: value projection as HMMA GEMM -----------------------------
// vh[b][c][l] = sum_k wv[c][k] * xh[b][l][k] + bias[c]; K=512 (8 stages)
#define BUFV 32768
__global__ void __launch_bounds__(512) k_vproj_mma(const float* __restrict__ bias) {
    extern __shared__ char dsm[];
    const uint32_t sbase = smem_u32(dsm);
    const uint32_t offA = 0, offB = 16384;

    const int b = blockIdx.z;
    const int pix0 = blockIdx.x * 128;
    const int t = threadIdx.x;
    const int wid = t >> 5, lane = t & 31;
    const int wm = wid >> 2, wn = wid & 3;

    const __half* __restrict__ wv = g_wv;
    const __half* __restrict__ xh = g_xh + (size_t)b * LLEN * Cc;

    float acc[2][4][4] = {};

    const int aRow = wm * 32 + (lane & 15);
    const int aColHalf = (lane & 16) ? 16 : 0;
    const int bRow = wn * 32 + (lane & 7);
    const int bColHalf = (lane & 8) ? 16 : 0;

    auto stage_load = [&](int s, uint32_t bufOff) {
        const int k0 = s * 64;
        for (int idx = t; idx < 1024; idx += 512) {
            const int r = idx >> 3, ch = idx & 7;
            const uint32_t sw = swz((uint32_t)(r * 128 + ch * 16));
            const int goff = ch * 8;
            cp16(sbase + bufOff + offA + sw, wv + (size_t)r * Cc + k0 + goff, true);
            cp16(sbase + bufOff + offB + sw, xh + (size_t)(pix0 + r) * Cc + k0 + goff, true);
        }
        cp_commit();
    };

    stage_load(0, 0);

    for (int s = 0; s < 8; s++) {
        const uint32_t bufOff = (uint32_t)(s & 1) * BUFV;
        if (s < 7) {
            stage_load(s + 1, (uint32_t)((s + 1) & 1) * BUFV);
            asm volatile("cp.async.wait_group 1;" ::: "memory");
        } else {
            asm volatile("cp.async.wait_group 0;" ::: "memory");
        }
        __syncthreads();

#pragma unroll
        for (int kk = 0; kk < 4; kk++) {
            uint32_t Af[2][4], Bf[4][2];
#pragma unroll
            for (int mt = 0; mt < 2; mt++) {
                const uint32_t boff = swz((uint32_t)((aRow + mt * 16) * 128 + kk * 32 + aColHalf));
                ldsm_x4(Af[mt][0], Af[mt][1], Af[mt][2], Af[mt][3], sbase + bufOff + offA + boff);
            }
#pragma unroll
            for (int nt = 0; nt < 4; nt++) {
                const uint32_t boff = swz((uint32_t)((bRow + nt * 8) * 128 + kk * 32 + bColHalf));
                ldsm_x2(Bf[nt][0], Bf[nt][1], sbase + bufOff + offB + boff);
            }
#pragma unroll
            for (int mt = 0; mt < 2; mt++)
#pragma unroll
                for (int nt = 0; nt < 4; nt++)
                    mma_f16(acc[mt][nt], Af[mt], Bf[nt]);
        }
        __syncthreads();
    }

    const int mBase = wm * 32 + (lane >> 2);
    const int nBase = pix0 + wn * 32 + (lane & 3) * 2;
#pragma unroll
    for (int mt = 0; mt < 2; mt++) {
#pragma unroll
        for (int half = 0; half < 2; half++) {
            const int co = mBase + mt * 16 + half * 8;
            const float bs = bias[co];
#pragma unroll
            for (int nt = 0; nt < 4; nt++) {
                const int l = nBase + nt * 8;
                const __half2 hv = __floats2half2_rn(acc[mt][nt][half * 2] + bs,
                                                     acc[mt][nt][half * 2 + 1] + bs);
                *(__half2*)&g_vh[((size_t)b * C4 + co) * LLEN + l] = hv;
            }
        }
    }
}

// ---------------- K1c: adaptive avg pool to 4x4 (parallel over 128 CTAs) --------
__global__ void k_pool(const float* __restrict__ x) {
    const int b = blockIdx.x, cg = blockIdx.y;
    const int t = threadIdx.x;
    const int c = cg * 64 + (t >> 2);
    const int cellq = (t & 3) * 4;
    const float* xc = x + ((size_t)b * Cc + c) * LLEN;
#pragma unroll
    for (int cq = 0; cq < 4; cq++) {
        const int cell = cellq + cq;
        const int i = cell >> 2, j = cell & 3;
        float s = 0.f;
        for (int y = 0; y < 8; y++) {
            const float* row = &xc[(i * 8 + y) * 32 + j * 8];
#pragma unroll
            for (int xx = 0; xx < 8; xx++) s += row[xx];
        }
        g_sp4[(b * Cc + c) * 16 + cell] = s * (1.f / 64.f);
    }
}

// ---------------- K2: rce + q/k feats + bilinear upsample ----------------------
__global__ void k_prep(const float* __restrict__ rce_w, const float* __restrict__ rce_b,
                       const float* __restrict__ qw, const float* __restrict__ qb,
                       const float* __restrict__ kw, const float* __restrict__ kb) {
    __shared__ float sp4[Cc * 16];
    __shared__ float f4[C4 * 16];
    __shared__ float f2[C4 * 4];
    __shared__ float qf4[QKC * 16], kf4[QKC * 16];
    __shared__ float qf2[QKC * 4],  kf2[QKC * 4];
    const int b = blockIdx.x, t = threadIdx.x;

    for (int idx = t; idx < Cc * 16 / 4; idx += 256)
        *(float4*)&sp4[idx * 4] = *(const float4*)&g_sp4[b * Cc * 16 + idx * 4];
    __syncthreads();

    if (t < C4) {
        float a4[16] = {}, a2[4] = {};
        for (int c = 0; c < Cc; c++) {
            const float w4 = rce_w[(2 * C4 + t) * Cc + c];
            const float w2 = rce_w[(1 * C4 + t) * Cc + c];
            const float* p = &sp4[c * 16];
#pragma unroll
            for (int cell = 0; cell < 16; cell++) a4[cell] += w4 * p[cell];
#pragma unroll
            for (int i = 0; i < 2; i++)
#pragma unroll
                for (int j = 0; j < 2; j++)
                    a2[i * 2 + j] += w2 * 0.25f *
                        (p[(2 * i) * 4 + 2 * j] + p[(2 * i) * 4 + 2 * j + 1] +
                         p[(2 * i + 1) * 4 + 2 * j] + p[(2 * i + 1) * 4 + 2 * j + 1]);
        }
        const float b4 = rce_b[2 * C4 + t], b2v = rce_b[1 * C4 + t];
#pragma unroll
        for (int cell = 0; cell < 16; cell++) f4[t * 16 + cell] = a4[cell] + b4;
#pragma unroll
        for (int cc = 0; cc < 4; cc++) f2[t * 4 + cc] = a2[cc] + b2v;
    }
    __syncthreads();

    {
        const int qc = t >> 4, cell = t & 15;
        float aq = 0.f, ak = 0.f;
        for (int o = 0; o < C4; o++) {
            const float fv = f4[o * 16 + cell];
            aq += qw[qc * C4 + o] * fv;
            ak += kw[qc * C4 + o] * fv;
        }
        qf4[t] = aq + qb[qc]; kf4[t] = ak + kb[qc];
    }
    if (t < 64) {
        const int qc = t >> 2, cc = t & 3;
        float aq = 0.f, ak = 0.f;
        for (int o = 0; o < C4; o++) {
            const float fv = f2[o * 4 + cc];
            aq += qw[qc * C4 + o] * fv;
            ak += kw[qc * C4 + o] * fv;
        }
        qf2[t] = aq + qb[qc]; kf2[t] = ak + kb[qc];
    }
    __syncthreads();

    const float st4 = 3.0f / 31.0f, st2 = 1.0f / 31.0f;
    for (int idx = t; idx < QKC * LLEN; idx += 256) {
        const int qc = idx >> 10, p = idx & 1023, r = p >> 5, cc = p & 31;
        float pr = r * st4;  int lr = (int)pr; lr = lr > 2 ? 2 : lr; float fr = pr - lr;
        float pc = cc * st4; int lc = (int)pc; lc = lc > 2 ? 2 : lc; float fc = pc - lc;
        const float w00 = (1.f - fr) * (1.f - fc), w01 = (1.f - fr) * fc;
        const float w10 = fr * (1.f - fc),         w11 = fr * fc;
        const float* q4 = &qf4[qc * 16]; const float* k4 = &kf4[qc * 16];
        g_qk[qk_idx(0, 1, b, qc, p)] =
            w00 * q4[lr * 4 + lc] + w01 * q4[lr * 4 + lc + 1] +
            w10 * q4[(lr + 1) * 4 + lc] + w11 * q4[(lr + 1) * 4 + lc + 1];
        g_qk[qk_idx(1, 1, b, qc, p)] =
            w00 * k4[lr * 4 + lc] + w01 * k4[lr * 4 + lc + 1] +
            w10 * k4[(lr + 1) * 4 + lc] + w11 * k4[(lr + 1) * 4 + lc + 1];
        const float fr2 = r * st2, fc2 = cc * st2;
        const float u00 = (1.f - fr2) * (1.f - fc2), u01 = (1.f - fr2) * fc2;
        const float u10 = fr2 * (1.f - fc2),          u11 = fr2 * fc2;
        const float* q2 = &qf2[qc * 4]; const float* k2 = &kf2[qc * 4];
        g_qk[qk_idx(0, 0, b, qc, p)] = u00 * q2[0] + u01 * q2[1] + u10 * q2[2] + u11 * q2[3];
        g_qk[qk_idx(1, 0, b, qc, p)] = u00 * k2[0] + u01 * k2[1] + u10 * k2[2] + u11 * k2[3];
    }
}

// ---------------- K3: sz=1 pyramid mean (reads fp16 V) -------------------------
__global__ void k_mean() {
    const int c = blockIdx.x, b = blockIdx.y, t = threadIdx.x;
    const __half* v = &g_vh[(b * C4 + c) * LLEN];
    float s = 0.f;
    for (int i = t; i < LLEN; i += 256) s += __half2float(v[i]);
    __shared__ float red[256];
    red[t] = s; __syncthreads();
    for (int o = 128; o > 0; o >>= 1) { if (t < o) red[t] += red[t + o]; __syncthreads(); }
    if (t == 0) g_mean[b * C4 + c] = red[0] * (1.f / LLEN);
}

// ---------------- K3b: border-pattern weight sums ----------------
__global__ void k_wsum(const float* __restrict__ fw) {
    const int co = blockIdx.x, ci = threadIdx.x;
    float w[9];
#pragma unroll
    for (int k = 0; k < 9; k++) w[k] = fw[co * 3456 + ci * 9 + k];
#pragma unroll
    for (int rt = 0; rt < 3; rt++) {
        const int kylo = (rt == 0) ? 1 : 0, kyhi = (rt == 2) ? 1 : 2;
#pragma unroll
        for (int ct = 0; ct < 3; ct++) {
            const int kxlo = (ct == 0) ? 1 : 0, kxhi = (ct == 2) ? 1 : 2;
            float s = 0.f;
            for (int ky = kylo; ky <= kyhi; ky++)
                for (int kx = kxlo; kx <= kxhi; kx++)
                    s += w[ky * 3 + kx];
            g_wsum[((rt * 3 + ct) * Cc + co) * C4 + ci] = s;
        }
    }
}

// ---------------- K3c: constant-channel conv contribution ----------------
__global__ void k_const() {
    __shared__ float sm[C4];
    const int b = blockIdx.x, co = threadIdx.x;
    if (co < C4) sm[co] = g_mean[b * C4 + co];
    __syncthreads();
#pragma unroll
    for (int pat = 0; pat < 9; pat++) {
        const float* ws = &g_wsum[(pat * Cc + co) * C4];
        float s = 0.f;
        for (int ci = 0; ci < C4; ci++) s += sm[ci] * ws[ci];
        g_contrib[(b * 9 + pat) * Cc + co] = s;
    }
}

// ---------------- K3d: fusion weight fp16, reordered [co][tap*256+cc] ----------
__global__ void k_wsplit(const float* __restrict__ fw) {
    const int idx = blockIdx.x * 256 + threadIdx.x;   // 512*2304
    const int co = idx / CONVK, k = idx % CONVK;
    const int tap = k >> 8, cc = k & 255;
    g_wh[idx] = __float2half(fw[co * 3456 + 1152 + cc * 9 + tap]);
}

// ---------------- K4: energy + softmax -> attn probabilities -------------------
// k tile fp16, 16 halfs/row XOR-8 swizzled (32KB). HFMA2 dot. 4 CTAs/SM.
__global__ void __launch_bounds__(256, 4) k_attn() {
    extern __shared__ __half ksh[];   // 1024 * 16 halfs = 32KB
    const int b = blockIdx.z, pyr = blockIdx.y;
    const int mbase = blockIdx.x * 128;
    const int t = threadIdx.x, w = t >> 5, lane = t & 31;
    const float* gq = &g_qk[qk_idx(0, pyr, b, 0, 0)];
    const float* gk = &g_qk[qk_idx(1, pyr, b, 0, 0)];
    for (int idx = t; idx < QKC * LLEN; idx += 256) {
        const int qc = idx >> 10, l = idx & 1023;
        const int addr = (l * 16 + qc) ^ ((l & 4) ? 8 : 0);
        ksh[addr] = __float2half(gk[qc * LLEN + l]);
    }
    __syncthreads();
    __half* pb = &g_attnh[(size_t)(pyr * Nn + b) * LLEN * LLEN];

    for (int pr = 0; pr < 16; pr++) {
        const int m = mbase + pr * 8 + w;
        __half2 q2[8];
#pragma unroll
        for (int j = 0; j < 8; j++)
            q2[j] = __floats2half2_rn(gq[(2 * j) * LLEN + m], gq[(2 * j + 1) * LLEN + m]);
        uint32_t e2[16];
        float mx = -1e30f;
        float sprev = 0.f;
#pragma unroll
        for (int i = 0; i < 32; i++) {
            const int l = i * 32 + lane;
            const int hi = (l * 16) ^ ((l & 4) ? 8 : 0);
            const uint4 kA = *(const uint4*)&ksh[hi];
            const uint4 kB = *(const uint4*)&ksh[hi ^ 8];
            const __half2* hA = (const __half2*)&kA;
            const __half2* hB = (const __half2*)&kB;
            __half2 s2 = __float2half2_rn(0.f);
#pragma unroll
            for (int j = 0; j < 4; j++) s2 = __hfma2(q2[j], hA[j], s2);
#pragma unroll
            for (int j = 0; j < 4; j++) s2 = __hfma2(q2[4 + j], hB[j], s2);
            const float2 fs = __half22float2(s2);
            const float s = fs.x + fs.y;
            mx = fmaxf(mx, s);
            if (i & 1) {
                const __half2 pk = __floats2half2_rn(sprev, s);
                e2[i >> 1] = *(const uint32_t*)&pk;
            } else {
                sprev = s;
            }
        }
#pragma unroll
        for (int o = 16; o > 0; o >>= 1)
            mx = fmaxf(mx, __shfl_xor_sync(0xffffffffu, mx, o));
        float sm = 0.f;
#pragma unroll
        for (int i2 = 0; i2 < 16; i2++) {
            const float2 f = __half22float2(*(const __half2*)&e2[i2]);
            const float a = fexp(f.x - mx);
            const float bb = fexp(f.y - mx);
            sm += a + bb;
            const __half2 pk = __floats2half2_rn(a, bb);
            e2[i2] = *(const uint32_t*)&pk;
        }
#pragma unroll
        for (int o = 16; o > 0; o >>= 1)
            sm += __shfl_xor_sync(0xffffffffu, sm, o);
        const float inv = 1.f / sm;
        __half* pa = &pb[(size_t)m * LLEN];
#pragma unroll
        for (int i2 = 0; i2 < 16; i2++) {
            const float2 f = __half22float2(*(const __half2*)&e2[i2]);
            pa[(2 * i2) * 32 + lane]     = __float2half(f.x * inv);
            pa[(2 * i2 + 1) * 32 + lane] = __float2half(f.y * inv);
        }
    }
}

// ---------------- K5: HMMA out-GEMM: catT[pix][c] = sum_l V[c][l]*P[pix][l] ----
#define BUFO 32768
__global__ void __launch_bounds__(512) k_outgemm_mma() {
    extern __shared__ char dsm[];
    const uint32_t sbase = smem_u32(dsm);
    const uint32_t offA = 0, offB = 16384;

    const int z = blockIdx.z; const int b = z >> 1; const int pyr = z & 1;
    const int pix0 = blockIdx.x * 128;
    const int t = threadIdx.x;
    const int wid = t >> 5, lane = t & 31;
    const int wm = wid >> 2, wn = wid & 3;

    const __half* __restrict__ vh = g_vh + (size_t)b * C4 * LLEN;
    const __half* __restrict__ P  = g_attnh + (size_t)(pyr * Nn + b) * LLEN * LLEN;

    float acc[2][4][4] = {};

    const int aRow = wm * 32 + (lane & 15);
    const int aColHalf = (lane & 16) ? 16 : 0;
    const int bRow = wn * 32 + (lane & 7);
    const int bColHalf = (lane & 8) ? 16 : 0;

    auto stage_load = [&](int s, uint32_t bufOff) {
        const int l0 = s * 64;
        for (int idx = t; idx < 1024; idx += 512) {
            const int r = idx >> 3, ch = idx & 7;
            const uint32_t sw = swz((uint32_t)(r * 128 + ch * 16));
            const int goff = ch * 8;
            cp16(sbase + bufOff + offA + sw, vh + (size_t)r * LLEN + l0 + goff, true);
            cp16(sbase + bufOff + offB + sw, P + (size_t)(pix0 + r) * LLEN + l0 + goff, true);
        }
        cp_commit();
    };

    stage_load(0, 0);

    for (int s = 0; s < 16; s++) {
        const uint32_t bufOff = (uint32_t)(s & 1) * BUFO;
        if (s < 15) {
            stage_load(s + 1, (uint32_t)((s + 1) & 1) * BUFO);
            asm volatile("cp.async.wait_group 1;" ::: "memory");
        } else {
            asm volatile("cp.async.wait_group 0;" ::: "memory");
        }
        __syncthreads();

#pragma unroll
        for (int kk = 0; kk < 4; kk++) {
            uint32_t Af[2][4], Bf[4][2];
#pragma unroll
            for (int mt = 0; mt < 2; mt++) {
                const uint32_t boff = swz((uint32_t)((aRow + mt * 16) * 128 + kk * 32 + aColHalf));
                ldsm_x4(Af[mt][0], Af[mt][1], Af[mt][2], Af[mt][3], sbase + bufOff + offA + boff);
            }
#pragma unroll
            for (int nt = 0; nt < 4; nt++) {
                const uint32_t boff = swz((uint32_t)((bRow + nt * 8) * 128 + kk * 32 + bColHalf));
                ldsm_x2(Bf[nt][0], Bf[nt][1], sbase + bufOff + offB + boff);
            }
#pragma unroll
            for (int mt = 0; mt < 2; mt++)
#pragma unroll
                for (int nt = 0; nt < 4; nt++)
                    mma_f16(acc[mt][nt], Af[mt], Bf[nt]);
        }
        __syncthreads();
    }

    // epilogue: smem transpose [pixLocal][c] (pitch 136), then coalesced fp16 store
    __half* eb = (__half*)dsm;
    const int cBase = wm * 32 + (lane >> 2);
    const int pBase = wn * 32 + (lane & 3) * 2;
#pragma unroll
    for (int mt = 0; mt < 2; mt++)
#pragma unroll
        for (int half = 0; half < 2; half++) {
            const int c = cBase + mt * 16 + half * 8;
#pragma unroll
            for (int nt = 0; nt < 4; nt++)
#pragma unroll
                for (int e = 0; e < 2; e++) {
                    const int p = pBase + nt * 8 + e;
                    eb[p * 136 + c] = __float2half(acc[mt][nt][half * 2 + e]);
                }
        }
    __syncthreads();
    for (int idx = t; idx < 128 * 16; idx += 512) {
        const int row = idx >> 4, ch = idx & 15;
        const uint4 v = *(const uint4*)&eb[row * 136 + ch * 8];
        *(uint4*)&g_cth[((size_t)(b * LLEN + pix0 + row)) * 256 + pyr * C4 + ch * 8] = v;
    }
}

// ---------------- K6: fusion conv as fp16 HMMA GEMM (cp.async 2-buf) -----------
#define BUFB 32768
__global__ void __launch_bounds__(512) k_conv_mma() {
    extern __shared__ char dsm[];
    const uint32_t sbase = smem_u32(dsm);
    const uint32_t offA = 0, offB = 16384;

    const int b = blockIdx.z;
    const int co0 = blockIdx.y * 128;
    const int pix0 = blockIdx.x * 128;
    const int t = threadIdx.x;
    const int wid = t >> 5, lane = t & 31;
    const int wm = wid >> 2, wn = wid & 3;

    const __half* __restrict__ wh = g_wh;
    const __half* __restrict__ cth = g_cth + (size_t)b * LLEN * 256;

    float acc[2][4][4] = {};

    const int aRow = wm * 32 + (lane & 15);
    const int aColHalf = (lane & 16) ? 16 : 0;
    const int bRow = wn * 32 + (lane & 7);
    const int bColHalf = (lane & 8) ? 16 : 0;

    auto stage_load = [&](int s, uint32_t bufOff) {
        const int tap = s >> 2;
        const int ky = tap / 3, kx = tap - ky * 3;
        const int ci0 = (s & 3) * 64;
        const int kA = s * 64;
        for (int idx = t; idx < 1024; idx += 512) {
            const int r = idx >> 3, ch = idx & 7;
            const uint32_t sw = swz((uint32_t)(r * 128 + ch * 16));
            const int goff = ch * 8;
            cp16(sbase + bufOff + offA + sw, wh + (size_t)(co0 + r) * CONVK + kA + goff, true);
            const int gp = pix0 + r;
            const int sy = (gp >> 5) + ky - 1, sx = (gp & 31) + kx - 1;
            const bool ok = (sy >= 0 && sy < 32 && sx >= 0 && sx < 32);
            const __half* src = ok ? (cth + ((size_t)(sy * 32 + sx)) * 256 + ci0 + goff) : cth;
            cp16(sbase + bufOff + offB + sw, src, ok);
        }
        cp_commit();
    };

    stage_load(0, 0);

    for (int s = 0; s < 36; s++) {
        const uint32_t bufOff = (uint32_t)(s & 1) * BUFB;
        if (s < 35) {
            stage_load(s + 1, (uint32_t)((s + 1) & 1) * BUFB);
            asm volatile("cp.async.wait_group 1;" ::: "memory");
        } else {
            asm volatile("cp.async.wait_group 0;" ::: "memory");
        }
        __syncthreads();

#pragma unroll
        for (int kk = 0; kk < 4; kk++) {
            uint32_t Af[2][4], Bf[4][2];
#pragma unroll
            for (int mt = 0; mt < 2; mt++) {
                const uint32_t boff = swz((uint32_t)((aRow + mt * 16) * 128 + kk * 32 + aColHalf));
                ldsm_x4(Af[mt][0], Af[mt][1], Af[mt][2], Af[mt][3], sbase + bufOff + offA + boff);
            }
#pragma unroll
            for (int nt = 0; nt < 4; nt++) {
                const uint32_t boff = swz((uint32_t)((bRow + nt * 8) * 128 + kk * 32 + bColHalf));
                ldsm_x2(Bf[nt][0], Bf[nt][1], sbase + bufOff + offB + boff);
            }
#pragma unroll
            for (int mt = 0; mt < 2; mt++)
#pragma unroll
                for (int nt = 0; nt < 4; nt++)
                    mma_f16(acc[mt][nt], Af[mt], Bf[nt]);
        }
        __syncthreads();
    }

    const float* cbp = &g_contrib[(size_t)b * 9 * Cc];
    const int mBase = co0 + wm * 32 + (lane >> 2);
    const int nBase = pix0 + wn * 32 + (lane & 3) * 2;
#pragma unroll
    for (int mt = 0; mt < 2; mt++) {
#pragma unroll
        for (int half = 0; half < 2; half++) {
            const int co = mBase + mt * 16 + half * 8;
            float* yrow = &g_y[((size_t)b * Cc + co) * LLEN];
#pragma unroll
            for (int nt = 0; nt < 4; nt++) {
#pragma unroll
                for (int e = 0; e < 2; e++) {
                    const int gp = nBase + nt * 8 + e;
                    const int y = gp >> 5, xg = gp & 31;
                    const int rt = (y == 0) ? 0 : ((y == 31) ? 2 : 1);
                    const int ct = (xg == 0) ? 0 : ((xg == 31) ? 2 : 1);
                    const float cc = cbp[(rt * 3 + ct) * Cc + co];
                    yrow[gp] = acc[mt][nt][half * 2 + e] + cc;
                }
            }
        }
    }
}

// ---------------- K7: BN batch statistics -------------------------------------
__global__ void k_stats(const float* __restrict__ bn_scale) {
    const int c = blockIdx.x, t = threadIdx.x;
    double s = 0.0, ss = 0.0;
    for (int idx = t; idx < Nn * LLEN; idx += 256) {
        const int bb = idx >> 10, l = idx & 1023;
        const float v = g_y[((size_t)bb * Cc + c) * LLEN + l];
        s += v; ss += (double)v * v;
    }
    __shared__ double rs[256], rq[256];
    rs[t] = s; rq[t] = ss; __syncthreads();
    for (int o = 128; o > 0; o >>= 1) {
        if (t < o) { rs[t] += rs[t + o]; rq[t] += rq[t + o]; }
        __syncthreads();
    }
    if (t == 0) {
        const double mean = rs[0] / (double)(Nn * LLEN);
        const double var  = rq[0] / (double)(Nn * LLEN) - mean * mean;
        g_stats[c * 2]     = (float)mean;
        g_stats[c * 2 + 1] = bn_scale[c] * rsqrtf((float)var + EPSf);
    }
}

// ---------------- K8: BN apply + ReLU + gamma*y + x ----------------------------
__global__ void k_final(const float* __restrict__ x, const float* __restrict__ bn_bias,
                        const float* __restrict__ gamma, float* __restrict__ out) {
    const int idx = blockIdx.x * 256 + threadIdx.x;
    const float g = gamma[0];
    const int c = (idx >> 10) & (Cc - 1);
    const float v = g_y[idx];
    float tt = (v - g_stats[c * 2]) * g_stats[c * 2 + 1] + bn_bias[c];
    tt = fmaxf(tt, 0.f);
    out[idx] = g * tt + x[idx];
}

// ---------------- launch ------------------------------------------------------
extern "C" void kernel_launch(void* const* d_in, const int* in_sizes, int n_in,
                              void* d_out, int out_size) {
    (void)in_sizes; (void)n_in; (void)out_size;
    const float* x        = (const float*)d_in[0];
    const float* rce_w    = (const float*)d_in[1];
    const float* rce_b    = (const float*)d_in[2];
    const float* q_w      = (const float*)d_in[3];
    const float* q_b      = (const float*)d_in[4];
    const float* k_w      = (const float*)d_in[5];
    const float* k_b      = (const float*)d_in[6];
    const float* value_w  = (const float*)d_in[7];
    const float* value_b  = (const float*)d_in[8];
    const float* fusion_w = (const float*)d_in[9];
    const float* bn_scale = (const float*)d_in[10];
    const float* bn_bias  = (const float*)d_in[11];
    const float* gamma    = (const float*)d_in[12];
    float* out = (float*)d_out;

    cudaFuncSetAttribute(k_attn, cudaFuncAttributeMaxDynamicSharedMemorySize, 32768);
    cudaFuncSetAttribute(k_conv_mma, cudaFuncAttributeMaxDynamicSharedMemorySize, 65536);
    cudaFuncSetAttribute(k_outgemm_mma, cudaFuncAttributeMaxDynamicSharedMemorySize, 65536);
    cudaFuncSetAttribute(k_vproj_mma, cudaFuncAttributeMaxDynamicSharedMemorySize, 65536);

    k_pool<<<dim3(16, 8), 256>>>(x);
    k_xh<<<dim3(32, 16, 16), 256>>>(x);
    k_wv<<<256, 256>>>(value_w);
    k_prep<<<16, 256>>>(rce_w, rce_b, q_w, q_b, k_w, k_b);
    k_vproj_mma<<<dim3(8, 1, 16), 512, 65536>>>(value_b);
    k_attn<<<dim3(8, 2, 16), 256, 32768>>>();
    k_outgemm_mma<<<dim3(8, 1, 32), 512, 65536>>>();
    k_mean<<<dim3(128, 16), 256>>>();
    k_wsum<<<512, 128>>>(fusion_w);
    k_const<<<16, 512>>>();
    k_wsplit<<<4608, 256>>>(fusion_w);
    k_conv_mma<<<dim3(8, 4, 16), 512, 65536>>>();
    k_stats<<<512, 256>>>(bn_scale);
    k_final<<<32768, 256>>>(x, bn_bias, gamma, out);
}

// round 14
// speedup vs baseline: 2.8793x; 1.0523x over previous
#include <cuda_runtime.h>
#include <cuda_bf16.h>
#include <cuda_fp16.h>
#include <cstdint>
#include <stdint.h>
#include <math.h>

#define Nn 16
#define Cc 512
#define C4 128
#define QKC 16
#define LLEN 1024
#define EPSf 1e-5f
#define CONVK 2304          // 9 taps * 256 attn channels

// ---------------- scratch (device globals; no allocation allowed) ----------------
__device__ float g_qk[2 * 2 * Nn * QKC * LLEN];           // [q/k][pyr][b][qc][l]
__device__ __half g_attnh[(size_t)2 * Nn * LLEN * LLEN];  // [pyr][b][m][l] probs fp16
__device__ float g_y[Nn * Cc * LLEN];                     // conv output pre-BN
__device__ float g_stats[Cc * 2];
__device__ float g_mean[Nn * C4];
__device__ float g_wsum[9 * Cc * C4];
__device__ float g_contrib[Nn * 9 * Cc];
__device__ float g_sp4[Nn * Cc * 16];                     // pooled 4x4 per (b,c)
__device__ float g_rwT[2 * Cc * C4];                      // rce weights T [layer][c][out]
__device__ __half g_wh[Cc * CONVK];                       // fusion weight fp16 [co][tap*256+cc]
__device__ __half g_wv[C4 * Cc];                          // value weight fp16 [c][k]
__device__ __half g_xh[(size_t)Nn * LLEN * Cc];           // x transposed fp16 [b][l][c]
__device__ __half g_vh[Nn * C4 * LLEN];                   // V fp16 [b][c][l]
__device__ __half g_cth[(size_t)Nn * LLEN * 256];         // feat fp16 [b][pix][cc]

__device__ __forceinline__ int qk_idx(int g, int py, int b, int qc, int l) {
    return (((g * 2 + py) * Nn + b) * QKC + qc) * LLEN + l;
}

// ---------------- PTX helpers (legacy tensor path, sm_80+) ----------------
__device__ __forceinline__ uint32_t smem_u32(const void* p) {
    uint32_t a;
    asm("{ .reg .u64 t; cvta.to.shared.u64 t, %1; cvt.u32.u64 %0, t; }" : "=r"(a) : "l"(p));
    return a;
}
__device__ __forceinline__ void ldsm_x4(uint32_t& r0, uint32_t& r1, uint32_t& r2, uint32_t& r3,
                                        uint32_t addr) {
    asm volatile("ldmatrix.sync.aligned.m8n8.x4.shared.b16 {%0,%1,%2,%3}, [%4];"
                 : "=r"(r0), "=r"(r1), "=r"(r2), "=r"(r3) : "r"(addr));
}
__device__ __forceinline__ void ldsm_x2(uint32_t& r0, uint32_t& r1, uint32_t addr) {
    asm volatile("ldmatrix.sync.aligned.m8n8.x2.shared.b16 {%0,%1}, [%2];"
                 : "=r"(r0), "=r"(r1) : "r"(addr));
}
__device__ __forceinline__ void mma_f16(float* c, const uint32_t* a, const uint32_t* b) {
    asm volatile(
        "mma.sync.aligned.m16n8k16.row.col.f32.f16.f16.f32 "
        "{%0,%1,%2,%3}, {%4,%5,%6,%7}, {%8,%9}, {%0,%1,%2,%3};"
        : "+f"(c[0]), "+f"(c[1]), "+f"(c[2]), "+f"(c[3])
        : "r"(a[0]), "r"(a[1]), "r"(a[2]), "r"(a[3]), "r"(b[0]), "r"(b[1]));
}
__device__ __forceinline__ uint32_t swz(uint32_t boff) {
    return boff ^ ((boff >> 3) & 0x70);
}
__device__ __forceinline__ void cp16(uint32_t dst, const void* src, bool pred) {
    const int sz = pred ? 16 : 0;
    asm volatile("cp.async.cg.shared.global [%0], [%1], 16, %2;"
                 :: "r"(dst), "l"(src), "r"(sz) : "memory");
}
__device__ __forceinline__ void cp_commit() {
    asm volatile("cp.async.commit_group;" ::: "memory");
}
// FMA-pipe exp (x<=0): degree-5 Taylor of 2^f + exponent add. rel err ~2e-6.
__device__ __forceinline__ float fexp(float x) {
    float y = fmaxf(x * 1.44269504f, -80.f);
    float r = rintf(y);
    float f = y - r;
    float p = 1.3333558e-3f;
    p = fmaf(p, f, 9.6181291e-3f);
    p = fmaf(p, f, 5.5504109e-2f);
    p = fmaf(p, f, 2.4022651e-1f);
    p = fmaf(p, f, 6.9314718e-1f);
    p = fmaf(p, f, 1.0f);
    return __int_as_float(__float_as_int(p) + (((int)r) << 23));
}

// ---------------- K0a: transpose-convert x -> xh fp16 [b][l][c] -----------------
__global__ void k_xh(const float* __restrict__ x) {
    __shared__ float tile[32][33];
    const int b = blockIdx.z, c0 = blockIdx.y * 32, l0 = blockIdx.x * 32;
    const int t = threadIdx.x;
    const int col = t & 31, row = t >> 5;
    for (int r = row; r < 32; r += 8)
        tile[r][col] = x[((size_t)b * Cc + c0 + r) * LLEN + l0 + col];
    __syncthreads();
    for (int r = row; r < 32; r += 8)
        g_xh[((size_t)b * LLEN + l0 + r) * Cc + c0 + col] = __float2half(tile[col][r]);
}

// ---------------- K0b: value weight fp16 ----------------------------------------
__global__ void k_wv(const float* __restrict__ w) {
    const int idx = blockIdx.x * 256 + threadIdx.x;
    g_wv[idx] = __float2half(w[idx]);
}

// ---------------- K0c: rce weight transpose [layer][c][out] ---------------------
__global__ void k_rwt(const float* __restrict__ rce_w) {
    const int idx = blockIdx.x * 256 + threadIdx.x;   // 2*512*128 = 131072
    const int layer = idx >> 16;                       // 0 -> sz2 (rce layer 1), 1 -> sz4 (layer 2)
    const int rest = idx & 65535;
    const int c = rest >> 7, out = rest & 127;
    g_rwT[idx] = rce_w[((layer + 1) * C4 + out) * Cc + c];
}

// ---------------- K1: value projection as HMMA GEMM -----------------------------
#define BUFV 32768
__global__ void __launch_bounds__(512) k_vproj_mma(const float* __restrict__ bias) {
    extern __shared__ char dsm[];
    const uint32_t sbase = smem_u32(dsm);
    const uint32_t offA = 0, offB = 16384;

    const int b = blockIdx.z;
    const int pix0 = blockIdx.x * 128;
    const int t = threadIdx.x;
    const int wid = t >> 5, lane = t & 31;
    const int wm = wid >> 2, wn = wid & 3;

    const __half* __restrict__ wv = g_wv;
    const __half* __restrict__ xh = g_xh + (size_t)b * LLEN * Cc;

    float acc[2][4][4] = {};

    const int aRow = wm * 32 + (lane & 15);
    const int aColHalf = (lane & 16) ? 16 : 0;
    const int bRow = wn * 32 + (lane & 7);
    const int bColHalf = (lane & 8) ? 16 : 0;

    auto stage_load = [&](int s, uint32_t bufOff) {
        const int k0 = s * 64;
        for (int idx = t; idx < 1024; idx += 512) {
            const int r = idx >> 3, ch = idx & 7;
            const uint32_t sw = swz((uint32_t)(r * 128 + ch * 16));
            const int goff = ch * 8;
            cp16(sbase + bufOff + offA + sw, wv + (size_t)r * Cc + k0 + goff, true);
            cp16(sbase + bufOff + offB + sw, xh + (size_t)(pix0 + r) * Cc + k0 + goff, true);
        }
        cp_commit();
    };

    stage_load(0, 0);

    for (int s = 0; s < 8; s++) {
        const uint32_t bufOff = (uint32_t)(s & 1) * BUFV;
        if (s < 7) {
            stage_load(s + 1, (uint32_t)((s + 1) & 1) * BUFV);
            asm volatile("cp.async.wait_group 1;" ::: "memory");
        } else {
            asm volatile("cp.async.wait_group 0;" ::: "memory");
        }
        __syncthreads();

#pragma unroll
        for (int kk = 0; kk < 4; kk++) {
            uint32_t Af[2][4], Bf[4][2];
#pragma unroll
            for (int mt = 0; mt < 2; mt++) {
                const uint32_t boff = swz((uint32_t)((aRow + mt * 16) * 128 + kk * 32 + aColHalf));
                ldsm_x4(Af[mt][0], Af[mt][1], Af[mt][2], Af[mt][3], sbase + bufOff + offA + boff);
            }
#pragma unroll
            for (int nt = 0; nt < 4; nt++) {
                const uint32_t boff = swz((uint32_t)((bRow + nt * 8) * 128 + kk * 32 + bColHalf));
                ldsm_x2(Bf[nt][0], Bf[nt][1], sbase + bufOff + offB + boff);
            }
#pragma unroll
            for (int mt = 0; mt < 2; mt++)
#pragma unroll
                for (int nt = 0; nt < 4; nt++)
                    mma_f16(acc[mt][nt], Af[mt], Bf[nt]);
        }
        __syncthreads();
    }

    const int mBase = wm * 32 + (lane >> 2);
    const int nBase = pix0 + wn * 32 + (lane & 3) * 2;
#pragma unroll
    for (int mt = 0; mt < 2; mt++) {
#pragma unroll
        for (int half = 0; half < 2; half++) {
            const int co = mBase + mt * 16 + half * 8;
            const float bs = bias[co];
#pragma unroll
            for (int nt = 0; nt < 4; nt++) {
                const int l = nBase + nt * 8;
                const __half2 hv = __floats2half2_rn(acc[mt][nt][half * 2] + bs,
                                                     acc[mt][nt][half * 2 + 1] + bs);
                *(__half2*)&g_vh[((size_t)b * C4 + co) * LLEN + l] = hv;
            }
        }
    }
}

// ---------------- K1c: adaptive avg pool to 4x4 (parallel over 128 CTAs) --------
__global__ void k_pool(const float* __restrict__ x) {
    const int b = blockIdx.x, cg = blockIdx.y;
    const int t = threadIdx.x;
    const int c = cg * 64 + (t >> 2);
    const int cellq = (t & 3) * 4;
    const float* xc = x + ((size_t)b * Cc + c) * LLEN;
#pragma unroll
    for (int cq = 0; cq < 4; cq++) {
        const int cell = cellq + cq;
        const int i = cell >> 2, j = cell & 3;
        float s = 0.f;
        for (int y = 0; y < 8; y++) {
            const float* row = &xc[(i * 8 + y) * 32 + j * 8];
#pragma unroll
            for (int xx = 0; xx < 8; xx++) s += row[xx];
        }
        g_sp4[(b * Cc + c) * 16 + cell] = s * (1.f / 64.f);
    }
}

// ---------------- K2: rce + q/k feats + bilinear upsample ----------------------
// rce: 2-way K-split over 256 threads, coalesced transposed weights
__global__ void k_prep(const float* __restrict__ rce_b,
                       const float* __restrict__ qw, const float* __restrict__ qb,
                       const float* __restrict__ kw, const float* __restrict__ kb) {
    __shared__ float sp4[Cc * 16];
    __shared__ float f4[C4 * 16];
    __shared__ float f2[C4 * 4];
    __shared__ float pf4[C4 * 16];   // partials from half 1
    __shared__ float pf2[C4 * 4];
    __shared__ float qf4[QKC * 16], kf4[QKC * 16];
    __shared__ float qf2[QKC * 4],  kf2[QKC * 4];
    const int b = blockIdx.x, t = threadIdx.x;

    for (int idx = t; idx < Cc * 16 / 4; idx += 256)
        *(float4*)&sp4[idx * 4] = *(const float4*)&g_sp4[b * Cc * 16 + idx * 4];
    __syncthreads();

    {
        const int out = t & 127, half = t >> 7;
        const int c0 = half * 256;
        float a4[16] = {}, a2[4] = {};
        for (int c = c0; c < c0 + 256; c++) {
            const float w4 = g_rwT[(Cc + c) * C4 + out];       // layer 1 (sz4)
            const float w2 = g_rwT[c * C4 + out];              // layer 0 (sz2)
            const float* p = &sp4[c * 16];
#pragma unroll
            for (int cell = 0; cell < 16; cell++) a4[cell] = fmaf(w4, p[cell], a4[cell]);
#pragma unroll
            for (int i = 0; i < 2; i++)
#pragma unroll
                for (int j = 0; j < 2; j++)
                    a2[i * 2 + j] = fmaf(w2 * 0.25f,
                        p[(2 * i) * 4 + 2 * j] + p[(2 * i) * 4 + 2 * j + 1] +
                        p[(2 * i + 1) * 4 + 2 * j] + p[(2 * i + 1) * 4 + 2 * j + 1],
                        a2[i * 2 + j]);
        }
        if (half == 1) {
#pragma unroll
            for (int cell = 0; cell < 16; cell++) pf4[out * 16 + cell] = a4[cell];
#pragma unroll
            for (int cc = 0; cc < 4; cc++) pf2[out * 4 + cc] = a2[cc];
        }
        __syncthreads();
        if (half == 0) {
            const float b4 = rce_b[2 * C4 + out], b2v = rce_b[1 * C4 + out];
#pragma unroll
            for (int cell = 0; cell < 16; cell++)
                f4[out * 16 + cell] = a4[cell] + pf4[out * 16 + cell] + b4;
#pragma unroll
            for (int cc = 0; cc < 4; cc++)
                f2[out * 4 + cc] = a2[cc] + pf2[out * 4 + cc] + b2v;
        }
    }
    __syncthreads();

    {
        const int qc = t >> 4, cell = t & 15;
        float aq = 0.f, ak = 0.f;
        for (int o = 0; o < C4; o++) {
            const float fv = f4[o * 16 + cell];
            aq += qw[qc * C4 + o] * fv;
            ak += kw[qc * C4 + o] * fv;
        }
        qf4[t] = aq + qb[qc]; kf4[t] = ak + kb[qc];
    }
    if (t < 64) {
        const int qc = t >> 2, cc = t & 3;
        float aq = 0.f, ak = 0.f;
        for (int o = 0; o < C4; o++) {
            const float fv = f2[o * 4 + cc];
            aq += qw[qc * C4 + o] * fv;
            ak += kw[qc * C4 + o] * fv;
        }
        qf2[t] = aq + qb[qc]; kf2[t] = ak + kb[qc];
    }
    __syncthreads();

    const float st4 = 3.0f / 31.0f, st2 = 1.0f / 31.0f;
    for (int idx = t; idx < QKC * LLEN; idx += 256) {
        const int qc = idx >> 10, p = idx & 1023, r = p >> 5, cc = p & 31;
        float pr = r * st4;  int lr = (int)pr; lr = lr > 2 ? 2 : lr; float fr = pr - lr;
        float pc = cc * st4; int lc = (int)pc; lc = lc > 2 ? 2 : lc; float fc = pc - lc;
        const float w00 = (1.f - fr) * (1.f - fc), w01 = (1.f - fr) * fc;
        const float w10 = fr * (1.f - fc),         w11 = fr * fc;
        const float* q4 = &qf4[qc * 16]; const float* k4 = &kf4[qc * 16];
        g_qk[qk_idx(0, 1, b, qc, p)] =
            w00 * q4[lr * 4 + lc] + w01 * q4[lr * 4 + lc + 1] +
            w10 * q4[(lr + 1) * 4 + lc] + w11 * q4[(lr + 1) * 4 + lc + 1];
        g_qk[qk_idx(1, 1, b, qc, p)] =
            w00 * k4[lr * 4 + lc] + w01 * k4[lr * 4 + lc + 1] +
            w10 * k4[(lr + 1) * 4 + lc] + w11 * k4[(lr + 1) * 4 + lc + 1];
        const float fr2 = r * st2, fc2 = cc * st2;
        const float u00 = (1.f - fr2) * (1.f - fc2), u01 = (1.f - fr2) * fc2;
        const float u10 = fr2 * (1.f - fc2),          u11 = fr2 * fc2;
        const float* q2 = &qf2[qc * 4]; const float* k2 = &kf2[qc * 4];
        g_qk[qk_idx(0, 0, b, qc, p)] = u00 * q2[0] + u01 * q2[1] + u10 * q2[2] + u11 * q2[3];
        g_qk[qk_idx(1, 0, b, qc, p)] = u00 * k2[0] + u01 * k2[1] + u10 * k2[2] + u11 * k2[3];
    }
}

// ---------------- K3: sz=1 pyramid mean (reads fp16 V) -------------------------
__global__ void k_mean() {
    const int c = blockIdx.x, b = blockIdx.y, t = threadIdx.x;
    const __half* v = &g_vh[(b * C4 + c) * LLEN];
    float s = 0.f;
    for (int i = t; i < LLEN; i += 256) s += __half2float(v[i]);
    __shared__ float red[256];
    red[t] = s; __syncthreads();
    for (int o = 128; o > 0; o >>= 1) { if (t < o) red[t] += red[t + o]; __syncthreads(); }
    if (t == 0) g_mean[b * C4 + c] = red[0] * (1.f / LLEN);
}

// ---------------- K3b: border-pattern weight sums ----------------
__global__ void k_wsum(const float* __restrict__ fw) {
    const int co = blockIdx.x, ci = threadIdx.x;
    float w[9];
#pragma unroll
    for (int k = 0; k < 9; k++) w[k] = fw[co * 3456 + ci * 9 + k];
#pragma unroll
    for (int rt = 0; rt < 3; rt++) {
        const int kylo = (rt == 0) ? 1 : 0, kyhi = (rt == 2) ? 1 : 2;
#pragma unroll
        for (int ct = 0; ct < 3; ct++) {
            const int kxlo = (ct == 0) ? 1 : 0, kxhi = (ct == 2) ? 1 : 2;
            float s = 0.f;
            for (int ky = kylo; ky <= kyhi; ky++)
                for (int kx = kxlo; kx <= kxhi; kx++)
                    s += w[ky * 3 + kx];
            g_wsum[((rt * 3 + ct) * Cc + co) * C4 + ci] = s;
        }
    }
}

// ---------------- K3c: constant-channel conv contribution ----------------
__global__ void k_const() {
    __shared__ float sm[C4];
    const int b = blockIdx.x, co = threadIdx.x;
    if (co < C4) sm[co] = g_mean[b * C4 + co];
    __syncthreads();
#pragma unroll
    for (int pat = 0; pat < 9; pat++) {
        const float* ws = &g_wsum[(pat * Cc + co) * C4];
        float s = 0.f;
        for (int ci = 0; ci < C4; ci++) s += sm[ci] * ws[ci];
        g_contrib[(b * 9 + pat) * Cc + co] = s;
    }
}

// ---------------- K3d: fusion weight fp16, reordered [co][tap*256+cc] ----------
__global__ void k_wsplit(const float* __restrict__ fw) {
    const int idx = blockIdx.x * 256 + threadIdx.x;
    const int co = idx / CONVK, k = idx % CONVK;
    const int tap = k >> 8, cc = k & 255;
    g_wh[idx] = __float2half(fw[co * 3456 + 1152 + cc * 9 + tap]);
}

// ---------------- K4: energy + softmax -> attn probabilities -------------------
__global__ void __launch_bounds__(256, 4) k_attn() {
    extern __shared__ __half ksh[];   // 1024 * 16 halfs = 32KB
    const int b = blockIdx.z, pyr = blockIdx.y;
    const int mbase = blockIdx.x * 128;
    const int t = threadIdx.x, w = t >> 5, lane = t & 31;
    const float* gq = &g_qk[qk_idx(0, pyr, b, 0, 0)];
    const float* gk = &g_qk[qk_idx(1, pyr, b, 0, 0)];
    for (int idx = t; idx < QKC * LLEN; idx += 256) {
        const int qc = idx >> 10, l = idx & 1023;
        const int addr = (l * 16 + qc) ^ ((l & 4) ? 8 : 0);
        ksh[addr] = __float2half(gk[qc * LLEN + l]);
    }
    __syncthreads();
    __half* pb = &g_attnh[(size_t)(pyr * Nn + b) * LLEN * LLEN];

    for (int pr = 0; pr < 16; pr++) {
        const int m = mbase + pr * 8 + w;
        __half2 q2[8];
#pragma unroll
        for (int j = 0; j < 8; j++)
            q2[j] = __floats2half2_rn(gq[(2 * j) * LLEN + m], gq[(2 * j + 1) * LLEN + m]);
        uint32_t e2[16];
        float mx = -1e30f;
        float sprev = 0.f;
#pragma unroll
        for (int i = 0; i < 32; i++) {
            const int l = i * 32 + lane;
            const int hi = (l * 16) ^ ((l & 4) ? 8 : 0);
            const uint4 kA = *(const uint4*)&ksh[hi];
            const uint4 kB = *(const uint4*)&ksh[hi ^ 8];
            const __half2* hA = (const __half2*)&kA;
            const __half2* hB = (const __half2*)&kB;
            __half2 s2 = __float2half2_rn(0.f);
#pragma unroll
            for (int j = 0; j < 4; j++) s2 = __hfma2(q2[j], hA[j], s2);
#pragma unroll
            for (int j = 0; j < 4; j++) s2 = __hfma2(q2[4 + j], hB[j], s2);
            const float2 fs = __half22float2(s2);
            const float s = fs.x + fs.y;
            mx = fmaxf(mx, s);
            if (i & 1) {
                const __half2 pk = __floats2half2_rn(sprev, s);
                e2[i >> 1] = *(const uint32_t*)&pk;
            } else {
                sprev = s;
            }
        }
#pragma unroll
        for (int o = 16; o > 0; o >>= 1)
            mx = fmaxf(mx, __shfl_xor_sync(0xffffffffu, mx, o));
        float sm = 0.f;
#pragma unroll
        for (int i2 = 0; i2 < 16; i2++) {
            const float2 f = __half22float2(*(const __half2*)&e2[i2]);
            const float a = fexp(f.x - mx);
            const float bb = fexp(f.y - mx);
            sm += a + bb;
            const __half2 pk = __floats2half2_rn(a, bb);
            e2[i2] = *(const uint32_t*)&pk;
        }
#pragma unroll
        for (int o = 16; o > 0; o >>= 1)
            sm += __shfl_xor_sync(0xffffffffu, sm, o);
        const float inv = 1.f / sm;
        __half* pa = &pb[(size_t)m * LLEN];
#pragma unroll
        for (int i2 = 0; i2 < 16; i2++) {
            const float2 f = __half22float2(*(const __half2*)&e2[i2]);
            pa[(2 * i2) * 32 + lane]     = __float2half(f.x * inv);
            pa[(2 * i2 + 1) * 32 + lane] = __float2half(f.y * inv);
        }
    }
}

// ---------------- K5: HMMA out-GEMM: catT[pix][c] = sum_l V[c][l]*P[pix][l] ----
#define BUFO 32768
__global__ void __launch_bounds__(512) k_outgemm_mma() {
    extern __shared__ char dsm[];
    const uint32_t sbase = smem_u32(dsm);
    const uint32_t offA = 0, offB = 16384;

    const int z = blockIdx.z; const int b = z >> 1; const int pyr = z & 1;
    const int pix0 = blockIdx.x * 128;
    const int t = threadIdx.x;
    const int wid = t >> 5, lane = t & 31;
    const int wm = wid >> 2, wn = wid & 3;

    const __half* __restrict__ vh = g_vh + (size_t)b * C4 * LLEN;
    const __half* __restrict__ P  = g_attnh + (size_t)(pyr * Nn + b) * LLEN * LLEN;

    float acc[2][4][4] = {};

    const int aRow = wm * 32 + (lane & 15);
    const int aColHalf = (lane & 16) ? 16 : 0;
    const int bRow = wn * 32 + (lane & 7);
    const int bColHalf = (lane & 8) ? 16 : 0;

    auto stage_load = [&](int s, uint32_t bufOff) {
        const int l0 = s * 64;
        for (int idx = t; idx < 1024; idx += 512) {
            const int r = idx >> 3, ch = idx & 7;
            const uint32_t sw = swz((uint32_t)(r * 128 + ch * 16));
            const int goff = ch * 8;
            cp16(sbase + bufOff + offA + sw, vh + (size_t)r * LLEN + l0 + goff, true);
            cp16(sbase + bufOff + offB + sw, P + (size_t)(pix0 + r) * LLEN + l0 + goff, true);
        }
        cp_commit();
    };

    stage_load(0, 0);

    for (int s = 0; s < 16; s++) {
        const uint32_t bufOff = (uint32_t)(s & 1) * BUFO;
        if (s < 15) {
            stage_load(s + 1, (uint32_t)((s + 1) & 1) * BUFO);
            asm volatile("cp.async.wait_group 1;" ::: "memory");
        } else {
            asm volatile("cp.async.wait_group 0;" ::: "memory");
        }
        __syncthreads();

#pragma unroll
        for (int kk = 0; kk < 4; kk++) {
            uint32_t Af[2][4], Bf[4][2];
#pragma unroll
            for (int mt = 0; mt < 2; mt++) {
                const uint32_t boff = swz((uint32_t)((aRow + mt * 16) * 128 + kk * 32 + aColHalf));
                ldsm_x4(Af[mt][0], Af[mt][1], Af[mt][2], Af[mt][3], sbase + bufOff + offA + boff);
            }
#pragma unroll
            for (int nt = 0; nt < 4; nt++) {
                const uint32_t boff = swz((uint32_t)((bRow + nt * 8) * 128 + kk * 32 + bColHalf));
                ldsm_x2(Bf[nt][0], Bf[nt][1], sbase + bufOff + offB + boff);
            }
#pragma unroll
            for (int mt = 0; mt < 2; mt++)
#pragma unroll
                for (int nt = 0; nt < 4; nt++)
                    mma_f16(acc[mt][nt], Af[mt], Bf[nt]);
        }
        __syncthreads();
    }

    // epilogue: smem transpose [pixLocal][c] (pitch 136), then coalesced fp16 store
    __half* eb = (__half*)dsm;
    const int cBase = wm * 32 + (lane >> 2);
    const int pBase = wn * 32 + (lane & 3) * 2;
#pragma unroll
    for (int mt = 0; mt < 2; mt++)
#pragma unroll
        for (int half = 0; half < 2; half++) {
            const int c = cBase + mt * 16 + half * 8;
#pragma unroll
            for (int nt = 0; nt < 4; nt++)
#pragma unroll
                for (int e = 0; e < 2; e++) {
                    const int p = pBase + nt * 8 + e;
                    eb[p * 136 + c] = __float2half(acc[mt][nt][half * 2 + e]);
                }
        }
    __syncthreads();
    for (int idx = t; idx < 128 * 16; idx += 512) {
        const int row = idx >> 4, ch = idx & 15;
        const uint4 v = *(const uint4*)&eb[row * 136 + ch * 8];
        *(uint4*)&g_cth[((size_t)(b * LLEN + pix0 + row)) * 256 + pyr * C4 + ch * 8] = v;
    }
}

// ---------------- K6: fusion conv as fp16 HMMA GEMM (cp.async 2-buf) -----------
#define BUFB 32768
__global__ void __launch_bounds__(512) k_conv_mma() {
    extern __shared__ char dsm[];
    const uint32_t sbase = smem_u32(dsm);
    const uint32_t offA = 0, offB = 16384;

    const int b = blockIdx.z;
    const int co0 = blockIdx.y * 128;
    const int pix0 = blockIdx.x * 128;
    const int t = threadIdx.x;
    const int wid = t >> 5, lane = t & 31;
    const int wm = wid >> 2, wn = wid & 3;

    const __half* __restrict__ wh = g_wh;
    const __half* __restrict__ cth = g_cth + (size_t)b * LLEN * 256;

    float acc[2][4][4] = {};

    const int aRow = wm * 32 + (lane & 15);
    const int aColHalf = (lane & 16) ? 16 : 0;
    const int bRow = wn * 32 + (lane & 7);
    const int bColHalf = (lane & 8) ? 16 : 0;

    auto stage_load = [&](int s, uint32_t bufOff) {
        const int tap = s >> 2;
        const int ky = tap / 3, kx = tap - ky * 3;
        const int ci0 = (s & 3) * 64;
        const int kA = s * 64;
        for (int idx = t; idx < 1024; idx += 512) {
            const int r = idx >> 3, ch = idx & 7;
            const uint32_t sw = swz((uint32_t)(r * 128 + ch * 16));
            const int goff = ch * 8;
            cp16(sbase + bufOff + offA + sw, wh + (size_t)(co0 + r) * CONVK + kA + goff, true);
            const int gp = pix0 + r;
            const int sy = (gp >> 5) + ky - 1, sx = (gp & 31) + kx - 1;
            const bool ok = (sy >= 0 && sy < 32 && sx >= 0 && sx < 32);
            const __half* src = ok ? (cth + ((size_t)(sy * 32 + sx)) * 256 + ci0 + goff) : cth;
            cp16(sbase + bufOff + offB + sw, src, ok);
        }
        cp_commit();
    };

    stage_load(0, 0);

    for (int s = 0; s < 36; s++) {
        const uint32_t bufOff = (uint32_t)(s & 1) * BUFB;
        if (s < 35) {
            stage_load(s + 1, (uint32_t)((s + 1) & 1) * BUFB);
            asm volatile("cp.async.wait_group 1;" ::: "memory");
        } else {
            asm volatile("cp.async.wait_group 0;" ::: "memory");
        }
        __syncthreads();

#pragma unroll
        for (int kk = 0; kk < 4; kk++) {
            uint32_t Af[2][4], Bf[4][2];
#pragma unroll
            for (int mt = 0; mt < 2; mt++) {
                const uint32_t boff = swz((uint32_t)((aRow + mt * 16) * 128 + kk * 32 + aColHalf));
                ldsm_x4(Af[mt][0], Af[mt][1], Af[mt][2], Af[mt][3], sbase + bufOff + offA + boff);
            }
#pragma unroll
            for (int nt = 0; nt < 4; nt++) {
                const uint32_t boff = swz((uint32_t)((bRow + nt * 8) * 128 + kk * 32 + bColHalf));
                ldsm_x2(Bf[nt][0], Bf[nt][1], sbase + bufOff + offB + boff);
            }
#pragma unroll
            for (int mt = 0; mt < 2; mt++)
#pragma unroll
                for (int nt = 0; nt < 4; nt++)
                    mma_f16(acc[mt][nt], Af[mt], Bf[nt]);
        }
        __syncthreads();
    }

    const float* cbp = &g_contrib[(size_t)b * 9 * Cc];
    const int mBase = co0 + wm * 32 + (lane >> 2);
    const int nBase = pix0 + wn * 32 + (lane & 3) * 2;
#pragma unroll
    for (int mt = 0; mt < 2; mt++) {
#pragma unroll
        for (int half = 0; half < 2; half++) {
            const int co = mBase + mt * 16 + half * 8;
            float* yrow = &g_y[((size_t)b * Cc + co) * LLEN];
#pragma unroll
            for (int nt = 0; nt < 4; nt++) {
#pragma unroll
                for (int e = 0; e < 2; e++) {
                    const int gp = nBase + nt * 8 + e;
                    const int y = gp >> 5, xg = gp & 31;
                    const int rt = (y == 0) ? 0 : ((y == 31) ? 2 : 1);
                    const int ct = (xg == 0) ? 0 : ((xg == 31) ? 2 : 1);
                    const float cc = cbp[(rt * 3 + ct) * Cc + co];
                    yrow[gp] = acc[mt][nt][half * 2 + e] + cc;
                }
            }
        }
    }
}

// ---------------- K7: BN batch statistics (fp32 partials) ----------------------
__global__ void k_stats(const float* __restrict__ bn_scale) {
    const int c = blockIdx.x, t = threadIdx.x;
    float s = 0.f, ss = 0.f;
    for (int idx = t; idx < Nn * LLEN; idx += 256) {
        const int bb = idx >> 10, l = idx & 1023;
        const float v = g_y[((size_t)bb * Cc + c) * LLEN + l];
        s += v; ss = fmaf(v, v, ss);
    }
    __shared__ float rs[256], rq[256];
    rs[t] = s; rq[t] = ss; __syncthreads();
    for (int o = 128; o > 0; o >>= 1) {
        if (t < o) { rs[t] += rs[t + o]; rq[t] += rq[t + o]; }
        __syncthreads();
    }
    if (t == 0) {
        const float mean = rs[0] * (1.f / (Nn * LLEN));
        float var = rq[0] * (1.f / (Nn * LLEN)) - mean * mean;
        var = fmaxf(var, 0.f);
        g_stats[c * 2]     = mean;
        g_stats[c * 2 + 1] = bn_scale[c] * rsqrtf(var + EPSf);
    }
}

// ---------------- K8: BN apply + ReLU + gamma*y + x ----------------------------
__global__ void k_final(const float* __restrict__ x, const float* __restrict__ bn_bias,
                        const float* __restrict__ gamma, float* __restrict__ out) {
    const int idx = blockIdx.x * 256 + threadIdx.x;
    const float g = gamma[0];
    const int c = (idx >> 10) & (Cc - 1);
    const float v = g_y[idx];
    float tt = (v - g_stats[c * 2]) * g_stats[c * 2 + 1] + bn_bias[c];
    tt = fmaxf(tt, 0.f);
    out[idx] = g * tt + x[idx];
}

// ---------------- launch ------------------------------------------------------
extern "C" void kernel_launch(void* const* d_in, const int* in_sizes, int n_in,
                              void* d_out, int out_size) {
    (void)in_sizes; (void)n_in; (void)out_size;
    const float* x        = (const float*)d_in[0];
    const float* rce_w    = (const float*)d_in[1];
    const float* rce_b    = (const float*)d_in[2];
    const float* q_w      = (const float*)d_in[3];
    const float* q_b      = (const float*)d_in[4];
    const float* k_w      = (const float*)d_in[5];
    const float* k_b      = (const float*)d_in[6];
    const float* value_w  = (const float*)d_in[7];
    const float* value_b  = (const float*)d_in[8];
    const float* fusion_w = (const float*)d_in[9];
    const float* bn_scale = (const float*)d_in[10];
    const float* bn_bias  = (const float*)d_in[11];
    const float* gamma    = (const float*)d_in[12];
    float* out = (float*)d_out;

    cudaFuncSetAttribute(k_attn, cudaFuncAttributeMaxDynamicSharedMemorySize, 32768);
    cudaFuncSetAttribute(k_conv_mma, cudaFuncAttributeMaxDynamicSharedMemorySize, 65536);
    cudaFuncSetAttribute(k_outgemm_mma, cudaFuncAttributeMaxDynamicSharedMemorySize, 65536);
    cudaFuncSetAttribute(k_vproj_mma, cudaFuncAttributeMaxDynamicSharedMemorySize, 65536);

    // Launch #4 (ncu capture slot) = k_vproj_mma — first direct HMMA profile.
    k_pool<<<dim3(16, 8), 256>>>(x);
    k_xh<<<dim3(32, 16, 16), 256>>>(x);
    k_wv<<<256, 256>>>(value_w);
    k_vproj_mma<<<dim3(8, 1, 16), 512, 65536>>>(value_b);
    k_rwt<<<512, 256>>>(rce_w);
    k_prep<<<16, 256>>>(rce_b, q_w, q_b, k_w, k_b);
    k_attn<<<dim3(8, 2, 16), 256, 32768>>>();
    k_outgemm_mma<<<dim3(8, 1, 32), 512, 65536>>>();
    k_mean<<<dim3(128, 16), 256>>>();
    k_wsum<<<512, 128>>>(fusion_w);
    k_const<<<16, 512>>>();
    k_wsplit<<<4608, 256>>>(fusion_w);
    k_conv_mma<<<dim3(8, 4, 16), 512, 65536>>>();
    k_stats<<<512, 256>>>(bn_scale);
    k_final<<<32768, 256>>>(x, bn_bias, gamma, out);
}